// round 10
// baseline (speedup 1.0000x reference)
#include <cuda_runtime.h>
#include <cuda_bf16.h>
#include <math.h>
#include <stdint.h>

// ---------------- problem constants ----------------
#define C_N   1024
#define C_K   16
#define C_D   512
#define C_H   8
#define C_FF  2048
#define C_MA  64
#define C_ES  64
#define C_E   (C_N * C_K)      // 16384
#define C_EPS 1e-6f

typedef __nv_bfloat16 bf16;

// ---------------- fp32 scratch ----------------
__device__ float g_TV  [3][C_N][C_D];
__device__ float g_MSG [3][C_E][C_D];
__device__ float g_w   [C_E][3*C_D];
__device__ float g_PV  [3][C_E][C_D];
__device__ float g_araw[C_E][C_MA];
__device__ float g_attr[C_E][C_H];
__device__ float g_att [C_E][C_H];
__device__ float g_XP  [3][C_N][C_D];
__device__ float g_X1  [3][C_N][C_D];
__device__ float g_Y   [3][C_N][C_FF];
__device__ float g_DV  [3][C_N][C_FF];
__device__ float g_Y3  [3][C_N][C_D];

// ---------------- bf16 hi/lo pairs (GEMM operands) ----------------
__device__ __align__(128) bf16 g_Tb_h [3][C_N][C_D],        g_Tb_l [3][C_N][C_D];
__device__ __align__(128) bf16 g_Mb_h [3][C_E][C_D],        g_Mb_l [3][C_E][C_D];
__device__ __align__(128) bf16 g_pscb_h[C_E][C_D],          g_pscb_l[C_E][C_D];
__device__ __align__(128) bf16 g_Zb_h [3][C_N][C_H][C_D],   g_Zb_l [3][C_N][C_H][C_D];
__device__ __align__(128) bf16 g_OUTb_h[3][C_N][C_D],       g_OUTb_l[3][C_N][C_D];
__device__ __align__(128) bf16 g_X1b_h[3][C_N][C_D],        g_X1b_l[3][C_N][C_D];
__device__ __align__(128) bf16 g_Yb_h [3][C_N][C_FF],       g_Yb_l [3][C_N][C_FF];
__device__ __align__(128) bf16 g_Y2b_h[3][C_N][C_FF],       g_Y2b_l[3][C_N][C_FF];
// weights
__device__ __align__(128) bf16 g_Wsrc_h[C_D*C_D],  g_Wsrc_l[C_D*C_D];
__device__ __align__(128) bf16 g_Wdst_h[C_D*C_D],  g_Wdst_l[C_D*C_D];
__device__ __align__(128) bf16 g_Wa_h  [C_MA*C_D], g_Wa_l  [C_MA*C_D];
__device__ __align__(128) bf16 g_Wv_h  [C_D*C_D],  g_Wv_l  [C_D*C_D];
__device__ __align__(128) bf16 g_Wp_h  [C_D*C_D],  g_Wp_l  [C_D*C_D];
__device__ __align__(128) bf16 g_Wf1_h [C_FF*C_D], g_Wf1_l [C_FF*C_D];
__device__ __align__(128) bf16 g_Wfd_h [C_FF*C_FF],g_Wfd_l [C_FF*C_FF];
__device__ __align__(128) bf16 g_Wf2_h [C_D*C_FF], g_Wf2_l [C_D*C_FF];

// ---------------- helpers ----------------
__device__ __forceinline__ void bsplit(float v, bf16* H, bf16* L, long i) {
    bf16 h = __float2bfloat16_rn(v);
    H[i] = h;
    L[i] = __float2bfloat16_rn(v - __bfloat162float(h));
}
__device__ __forceinline__ void bsplit2(float v0, float v1, bf16* H, bf16* L, long i) {
    bf16 h0 = __float2bfloat16_rn(v0), h1 = __float2bfloat16_rn(v1);
    *(__nv_bfloat162*)(H + i) = __nv_bfloat162(h0, h1);
    *(__nv_bfloat162*)(L + i) = __nv_bfloat162(
        __float2bfloat16_rn(v0 - __bfloat162float(h0)),
        __float2bfloat16_rn(v1 - __bfloat162float(h1)));
}
__device__ __forceinline__ uint32_t s2u(const void* p) {
    uint32_t a;
    asm("{ .reg .u64 t; cvta.to.shared.u64 t, %1; cvt.u32.u64 %0, t; }" : "=r"(a) : "l"(p));
    return a;
}
__device__ __forceinline__ void mma_bf16(float* c, const uint32_t* a, const uint32_t* b) {
    asm volatile("mma.sync.aligned.m16n8k16.row.col.f32.bf16.bf16.f32 "
                 "{%0,%1,%2,%3},{%4,%5,%6,%7},{%8,%9},{%0,%1,%2,%3};"
                 : "+f"(c[0]), "+f"(c[1]), "+f"(c[2]), "+f"(c[3])
                 : "r"(a[0]), "r"(a[1]), "r"(a[2]), "r"(a[3]), "r"(b[0]), "r"(b[1]));
}
__device__ __forceinline__ void ldsm4(uint32_t* r, uint32_t addr) {
    asm volatile("ldmatrix.sync.aligned.m8n8.x4.shared.b16 {%0,%1,%2,%3}, [%4];"
        : "=r"(r[0]), "=r"(r[1]), "=r"(r[2]), "=r"(r[3]) : "r"(addr));
}
#define CPA(d, s) asm volatile("cp.async.cg.shared.global [%0], [%1], 16;" :: "r"(d), "l"(s) : "memory")
#define CPC()     asm volatile("cp.async.commit_group;" ::: "memory")
#define CPW(n)    asm volatile("cp.async.wait_group %0;" :: "n"(n) : "memory")

// ============ bf16-pair NT GEMM: C[m,n] = sum_k A[m,k]*B[n,k] (+Add) ============
// 128xBN CTA tile, 128 threads (4 warps, 64x(BN/2) warp tiles), 3-stage cp.async
// ring with 2-ahead issue, ldmatrix fragments, 3 HMMA passes (hh+hl+lh).
// M%128==0, N%BN==0, K%64==0.
template<int BN>
__global__ void __launch_bounds__(128, 2) gemm_bf(
    const bf16* __restrict__ Ah, const bf16* __restrict__ Al,
    const bf16* __restrict__ Bh, const bf16* __restrict__ Bl,
    float* __restrict__ C, const float* __restrict__ Add,
    bf16* __restrict__ CbH, bf16* __restrict__ CbL,
    int lda, int ldb, int ldc, int Kc,
    long sA1, long sA2, long sB1, long sB2, long sC1, long sC2, int nz2,
    int addDiv, int ldadd, long sAdd1)
{
    constexpr int WN   = BN / 2;         // warp n-tile
    constexpr int NSUB = WN / 8;
    constexpr int ABY  = 10240;          // 128 rows x 80B
    constexpr int BBY  = BN * 80;
    constexpr int STG  = 2 * ABY + 2 * BBY;

    extern __shared__ __align__(16) char sm[];
    const int t = threadIdx.x, wid = t >> 5, lane = t & 31;
    const int g = lane >> 2, tq = lane & 3;
    const int wm = wid & 1, wn = wid >> 1;

    const int z = blockIdx.z, z1 = z / nz2, z2 = z - z1 * nz2;
    const long m0 = (long)blockIdx.y * 128, n0 = (long)blockIdx.x * BN;
    const bf16* Agh = Ah + z1 * sA1 + z2 * sA2 + m0 * lda;
    const bf16* Agl = Al + z1 * sA1 + z2 * sA2 + m0 * lda;
    const bf16* Bgh = Bh + z1 * sB1 + z2 * sB2 + n0 * ldb;
    const bf16* Bgl = Bl + z1 * sB1 + z2 * sB2 + n0 * ldb;

    const uint32_t smb = s2u(sm);
    const int crow = t >> 2, cseg = t & 3;

    const int lm = lane >> 3, lr = lane & 7;
    const int a_off0 = (wm * 64 + (lm & 1) * 8 + lr) * 80 + (lm >> 1) * 16;
    const int b_off0 = (wn * WN + (lm >> 1) * 8 + lr) * 80 + (lm & 1) * 16;

    float acc[4][NSUB][4];
#pragma unroll
    for (int mi = 0; mi < 4; mi++)
#pragma unroll
        for (int ni = 0; ni < NSUB; ni++)
#pragma unroll
            for (int j = 0; j < 4; j++) acc[mi][ni][j] = 0.f;

    const int nch = Kc >> 5;

    // issue one chunk's loads into stage st
    auto issue = [&](int ch, int st) {
        const uint32_t sb = smb + st * STG;
        const bf16* ah = Agh + ch * 32;
        const bf16* al = Agl + ch * 32;
        const bf16* bh = Bgh + ch * 32;
        const bf16* bl = Bgl + ch * 32;
#pragma unroll
        for (int i = 0; i < 4; i++) {
            int row = crow + i * 32;
            uint32_t d = sb + row * 80 + cseg * 16;
            CPA(d,       ah + (long)row * lda + cseg * 8);
            CPA(d + ABY, al + (long)row * lda + cseg * 8);
        }
#pragma unroll
        for (int i = 0; i < BN / 32; i++) {
            int row = crow + i * 32;
            uint32_t d = sb + 2 * ABY + row * 80 + cseg * 16;
            CPA(d,       bh + (long)row * ldb + cseg * 8);
            CPA(d + BBY, bl + (long)row * ldb + cseg * 8);
        }
        CPC();
    };

    // prologue: chunks 0 and 1 in flight
    issue(0, 0);
    if (nch > 1) issue(1, 1);

    int stage = 0;
    for (int ch = 0; ch < nch; ch++) {
        if (ch + 2 <= nch - 1 || ch + 1 <= nch - 1) { CPW(1); } else { CPW(0); }
        __syncthreads();
        if (ch + 2 < nch) {
            int s2 = stage + 2; if (s2 >= 3) s2 -= 3;
            issue(ch + 2, s2);
        }
        const uint32_t sbase = smb + stage * STG;
#pragma unroll
        for (int ks = 0; ks < 2; ks++) {
            const int ko = ks * 32;
            uint32_t fa[16], fbh[2 * NSUB], fbl[2 * NSUB];
            const uint32_t abase = sbase + a_off0 + ko;
            const uint32_t bbase = sbase + 2 * ABY + b_off0 + ko;
#pragma unroll
            for (int mi = 0; mi < 4; mi++) ldsm4(&fa[mi * 4], abase + mi * 1280);
#pragma unroll
            for (int np = 0; np < NSUB / 2; np++) ldsm4(&fbh[np * 4], bbase + np * 1280);
#pragma unroll
            for (int mi = 0; mi < 4; mi++)
#pragma unroll
                for (int ni = 0; ni < NSUB; ni++)
                    mma_bf16(acc[mi][ni], &fa[mi * 4], &fbh[ni * 2]);   // hi*hi
#pragma unroll
            for (int np = 0; np < NSUB / 2; np++) ldsm4(&fbl[np * 4], bbase + BBY + np * 1280);
#pragma unroll
            for (int mi = 0; mi < 4; mi++)
#pragma unroll
                for (int ni = 0; ni < NSUB; ni++)
                    mma_bf16(acc[mi][ni], &fa[mi * 4], &fbl[ni * 2]);   // hi*lo
#pragma unroll
            for (int mi = 0; mi < 4; mi++) ldsm4(&fa[mi * 4], abase + ABY + mi * 1280);
#pragma unroll
            for (int mi = 0; mi < 4; mi++)
#pragma unroll
                for (int ni = 0; ni < NSUB; ni++)
                    mma_bf16(acc[mi][ni], &fa[mi * 4], &fbh[ni * 2]);   // lo*hi
        }
        stage++; if (stage == 3) stage = 0;
    }

    // ---- epilogue ----
    float* Cp = C ? (C + z1 * sC1 + z2 * sC2) : (float*)0;
    bf16* Ch = CbH ? (CbH + z1 * sC1 + z2 * sC2) : (bf16*)0;
    bf16* Cl = CbL ? (CbL + z1 * sC1 + z2 * sC2) : (bf16*)0;
    const float* Ad = Add ? (Add + z1 * sAdd1) : (const float*)0;
#pragma unroll
    for (int mi = 0; mi < 4; mi++) {
        long r0 = m0 + wm * 64 + mi * 16 + g;
#pragma unroll
        for (int ni = 0; ni < NSUB; ni++) {
            long col = n0 + wn * WN + ni * 8 + tq * 2;
            float2 v0 = make_float2(acc[mi][ni][0], acc[mi][ni][1]);
            float2 v1 = make_float2(acc[mi][ni][2], acc[mi][ni][3]);
            if (Ad) {
                float2 a0 = *(const float2*)(Ad + (r0 / addDiv) * (long)ldadd + col);
                float2 a1 = *(const float2*)(Ad + ((r0 + 8) / addDiv) * (long)ldadd + col);
                v0.x += a0.x; v0.y += a0.y; v1.x += a1.x; v1.y += a1.y;
            }
            if (Cp) {
                *(float2*)(Cp + r0 * ldc + col) = v0;
                *(float2*)(Cp + (r0 + 8) * ldc + col) = v1;
            }
            if (Ch) {
                long i0 = r0 * ldc + col, i1 = (r0 + 8) * ldc + col;
                bsplit2(v0.x, v0.y, Ch, Cl, i0);
                bsplit2(v1.x, v1.y, Ch, Cl, i1);
            }
        }
    }
}

// ---------------- input transpose + bf16 split (vectorized) ----------------
__global__ void k_split_in(const float* __restrict__ tgt, const float* __restrict__ mem)
{
    long stride = (long)gridDim.x * blockDim.x;
    long base   = (long)blockIdx.x * blockDim.x + threadIdx.x;
    for (long p = base; p < (long)C_N * C_D / 2; p += stride) {
        const float* s = tgt + 6 * p;
        float2 a = *(const float2*)s, b = *(const float2*)(s + 2), c = *(const float2*)(s + 4);
        bsplit2(a.x, b.y, &g_Tb_h[0][0][0], &g_Tb_l[0][0][0], 2 * p);
        bsplit2(a.y, c.x, &g_Tb_h[1][0][0], &g_Tb_l[1][0][0], 2 * p);
        bsplit2(b.x, c.y, &g_Tb_h[2][0][0], &g_Tb_l[2][0][0], 2 * p);
    }
    for (long p = base; p < (long)C_E * C_D / 2; p += stride) {
        const float* s = mem + 6 * p;
        float2 a = *(const float2*)s, b = *(const float2*)(s + 2), c = *(const float2*)(s + 4);
        bsplit2(a.x, b.y, &g_Mb_h[0][0][0], &g_Mb_l[0][0][0], 2 * p);
        bsplit2(a.y, c.x, &g_Mb_h[1][0][0], &g_Mb_l[1][0][0], 2 * p);
        bsplit2(b.x, c.y, &g_Mb_h[2][0][0], &g_Mb_l[2][0][0], 2 * p);
    }
}

// ---------------- all weight splits in one kernel ----------------
__global__ void k_split_all(
    const float* __restrict__ Wsrc, const float* __restrict__ Wdst,
    const float* __restrict__ Wv,   const float* __restrict__ Wp,
    const float* __restrict__ Wf1,  const float* __restrict__ Wfd,
    const float* __restrict__ Wf2,  const float* __restrict__ Wa)
{
    const long SQ = (long)C_D * C_D;
    const long O4 = 4 * SQ;
    const long O5 = O4 + (long)C_FF * C_D;
    const long O6 = O5 + (long)C_FF * C_FF;
    const long O7 = O6 + (long)C_D * C_FF;
    const long O8 = O7 + (long)C_MA * C_D;
    long stride = (long)gridDim.x * blockDim.x;
    for (long i = (long)blockIdx.x * blockDim.x + threadIdx.x; i < O8; i += stride) {
        if (i < SQ)            bsplit(Wsrc[i],      g_Wsrc_h, g_Wsrc_l, i);
        else if (i < 2 * SQ)   bsplit(Wdst[i - SQ], g_Wdst_h, g_Wdst_l, i - SQ);
        else if (i < 3 * SQ)   bsplit(Wv[i - 2*SQ], g_Wv_h,   g_Wv_l,   i - 2*SQ);
        else if (i < 4 * SQ)   bsplit(Wp[i - 3*SQ], g_Wp_h,   g_Wp_l,   i - 3*SQ);
        else if (i < O5)       bsplit(Wf1[i - O4],  g_Wf1_h,  g_Wf1_l,  i - O4);
        else if (i < O6)       bsplit(Wfd[i - O5],  g_Wfd_h,  g_Wfd_l,  i - O5);
        else if (i < O7)       bsplit(Wf2[i - O6],  g_Wf2_h,  g_Wf2_l,  i - O6);
        else {
            long k = i - O7;
            long r = k >> 6, c = k & 63;
            bsplit(Wa[k], g_Wa_h, g_Wa_l, c * C_D + r);
        }
    }
}

// ---------------- fused edge MLP ----------------
__global__ void __launch_bounds__(256) k_mlp(
    const float* __restrict__ es, const float* __restrict__ w1, const float* __restrict__ b1,
    const float* __restrict__ w2, const float* __restrict__ b2,
    const float* __restrict__ w3, const float* __restrict__ b3)
{
    __shared__ float s_es[64][65];
    __shared__ float s_w1[64][32];
    __shared__ float s_w2[32][32];
    __shared__ float s_h1[64][33];
    __shared__ float s_h2[64][33];
    const int t = threadIdx.x;
    const long e0 = (long)blockIdx.x * 64;

    for (int i = t; i < 64 * 32; i += 256) s_w1[i >> 5][i & 31] = w1[i];
    for (int i = t; i < 32 * 32; i += 256) s_w2[i >> 5][i & 31] = w2[i];
    for (int i = t; i < 64 * 64; i += 256) s_es[i >> 6][i & 63] = es[e0 * 64 + i];
    __syncthreads();

    for (int i = t; i < 64 * 32; i += 256) {
        int e = i >> 5, j = i & 31;
        float acc = b1[j];
#pragma unroll 8
        for (int c = 0; c < 64; c++) acc = fmaf(s_es[e][c], s_w1[c][j], acc);
        s_h1[e][j] = acc / (1.f + expf(-acc));
    }
    __syncthreads();
    for (int i = t; i < 64 * 32; i += 256) {
        int e = i >> 5, j = i & 31;
        float acc = b2[j];
#pragma unroll 8
        for (int c = 0; c < 32; c++) acc = fmaf(s_h1[e][c], s_w2[c][j], acc);
        s_h2[e][j] = acc / (1.f + expf(-acc));
    }
    __syncthreads();
    for (int i = t; i < 64 * 1536; i += 256) {
        int e = i / 1536, o = i - e * 1536;
        float acc = b3[o];
#pragma unroll 8
        for (int c = 0; c < 32; c++) acc = fmaf(s_h2[e][c], w3[c * 1536 + o], acc);
        g_w[e0 + e][o] = acc;
    }
}

// ---------------- pointwise equivariant products (vectorized) ----------------
__global__ void k_pointwise(const float* __restrict__ esh)
{
    long stride = (long)gridDim.x * blockDim.x;
    for (long p = (long)blockIdx.x * blockDim.x + threadIdx.x; p < (long)C_E * C_D / 2; p += stride) {
        int  c = (int)(p & 255) * 2;
        long e = p >> 8;
        float s  = esh[e * 4 + 0];
        float v0 = esh[e * 4 + 1], v1 = esh[e * 4 + 2], v2 = esh[e * 4 + 3];
        float2 m0 = *(const float2*)&g_MSG[0][e][c];
        float2 m1 = *(const float2*)&g_MSG[1][e][c];
        float2 m2 = *(const float2*)&g_MSG[2][e][c];
        float2 w0 = *(const float2*)&g_w[e][c];
        float2 w1 = *(const float2*)&g_w[e][512 + c];
        float2 w2 = *(const float2*)&g_w[e][1024 + c];
        float p0 = w0.x * (m0.x * v0 + m1.x * v1 + m2.x * v2) * 0.5773502691896258f;
        float p1 = w0.y * (m0.y * v0 + m1.y * v1 + m2.y * v2) * 0.5773502691896258f;
        bsplit2(p0, p1, &g_pscb_h[0][0], &g_pscb_l[0][0], e * C_D + c);
        float k2x = w2.x * 0.7071067811865475f, k2y = w2.y * 0.7071067811865475f;
        float wsx = w1.x * s, wsy = w1.y * s;
        *(float2*)&g_PV[0][e][c] = make_float2(wsx * m0.x + k2x * (m1.x * v2 - m2.x * v1),
                                               wsy * m0.y + k2y * (m1.y * v2 - m2.y * v1));
        *(float2*)&g_PV[1][e][c] = make_float2(wsx * m1.x + k2x * (m2.x * v0 - m0.x * v2),
                                               wsy * m1.y + k2y * (m2.y * v0 - m0.y * v2));
        *(float2*)&g_PV[2][e][c] = make_float2(wsx * m2.x + k2x * (m0.x * v1 - m1.x * v0),
                                               wsy * m2.y + k2y * (m0.y * v1 - m1.y * v0));
    }
}

// ---------------- alpha post: LN + smooth_lrelu + head dot ----------------
__global__ void k_alpha_post(const float* __restrict__ gg, const float* __restrict__ bb,
                             const float* __restrict__ adot)
{
    int gt = blockIdx.x * blockDim.x + threadIdx.x;
    int e = gt >> 5, lane = gt & 31;
    if (e >= C_E) return;
    float v0 = g_araw[e][lane * 2], v1 = g_araw[e][lane * 2 + 1];
    float s = v0 + v1, s2 = v0 * v0 + v1 * v1;
#pragma unroll
    for (int o = 16; o > 0; o >>= 1) {
        s  += __shfl_xor_sync(0xffffffffu, s, o);
        s2 += __shfl_xor_sync(0xffffffffu, s2, o);
    }
    float mu  = s * (1.f / 64.f);
    float var = s2 * (1.f / 64.f) - mu * mu;
    float inv = rsqrtf(var + C_EPS);
    float a0 = (v0 - mu) * inv * gg[lane * 2]     + bb[lane * 2];
    float a1 = (v1 - mu) * inv * gg[lane * 2 + 1] + bb[lane * 2 + 1];
    a0 = 0.6f * a0 + 0.4f * a0 * tanhf(0.5f * a0);
    a1 = 0.6f * a1 + 0.4f * a1 * tanhf(0.5f * a1);
    int h = lane >> 2;
    int m = (lane & 3) * 2;
    float p = a0 * adot[h * 8 + m] + a1 * adot[h * 8 + m + 1];
    p += __shfl_xor_sync(0xffffffffu, p, 1);
    p += __shfl_xor_sync(0xffffffffu, p, 2);
    if ((lane & 3) == 0) g_attr[e][h] = p;
}

// ---------------- softmax over K per (n,h) ----------------
__global__ void k_softmax()
{
    int i = blockIdx.x * blockDim.x + threadIdx.x;
    if (i >= C_N * C_H) return;
    int n = i >> 3, h = i & 7;
    float v[16]; float mx = -1e30f;
#pragma unroll
    for (int k = 0; k < 16; k++) { v[k] = g_attr[n * 16 + k][h]; mx = fmaxf(mx, v[k]); }
    float sum = 0.f;
#pragma unroll
    for (int k = 0; k < 16; k++) { v[k] = expf(v[k] - mx); sum += v[k]; }
    float is = 1.f / sum;
#pragma unroll
    for (int k = 0; k < 16; k++) g_att[n * 16 + k][h] = v[k] * is;
}

// ---------------- z = sum_k att * pv (vectorized bf16-pair output) ----------------
__global__ void __launch_bounds__(256) k_z()
{
    int n = blockIdx.x, x = blockIdx.y;
    __shared__ float s_a[16][8];
    if (threadIdx.x < 128)
        s_a[threadIdx.x >> 3][threadIdx.x & 7] = g_att[n * 16 + (threadIdx.x >> 3)][threadIdx.x & 7];
    __syncthreads();
    int c = threadIdx.x * 2;
    float2 acc[8];
#pragma unroll
    for (int h = 0; h < 8; h++) acc[h] = make_float2(0.f, 0.f);
#pragma unroll
    for (int k = 0; k < 16; k++) {
        float2 pv = *(const float2*)&g_PV[x][n * 16 + k][c];
#pragma unroll
        for (int h = 0; h < 8; h++) {
            acc[h].x = fmaf(s_a[k][h], pv.x, acc[h].x);
            acc[h].y = fmaf(s_a[k][h], pv.y, acc[h].y);
        }
    }
#pragma unroll
    for (int h = 0; h < 8; h++) {
        long idx = (((long)x * C_N + n) * C_H + h) * C_D + c;
        bsplit2(acc[h].x, acc[h].y, &g_Zb_h[0][0][0][0], &g_Zb_l[0][0][0][0], idx);
    }
}

// ---------------- vector-norm LayerNorm (vn_ln) ----------------
__global__ void __launch_bounds__(256) k_vnln(const float* __restrict__ Xin, float* __restrict__ Xout,
                                              bf16* __restrict__ bH, bf16* __restrict__ bL,
                                              const float* __restrict__ gg, const float* __restrict__ bb,
                                              int inter)
{
    int n = blockIdx.x, t = threadIdx.x;
    const long P = (long)C_N * C_D;
    __shared__ float rs[8], rs2[8];
    __shared__ float smu, sinv;
    float xv[2][3], nc[2];
    float s = 0.f, s2 = 0.f;
#pragma unroll
    for (int i = 0; i < 2; i++) {
        int c = t * 2 + i;
#pragma unroll
        for (int xx = 0; xx < 3; xx++) xv[i][xx] = Xin[xx * P + (long)n * C_D + c];
        float v = sqrtf(xv[i][0] * xv[i][0] + xv[i][1] * xv[i][1] + xv[i][2] * xv[i][2] + C_EPS);
        nc[i] = v; s += v; s2 = fmaf(v, v, s2);
    }
#pragma unroll
    for (int o = 16; o > 0; o >>= 1) {
        s  += __shfl_xor_sync(0xffffffffu, s, o);
        s2 += __shfl_xor_sync(0xffffffffu, s2, o);
    }
    if ((t & 31) == 0) { rs[t >> 5] = s; rs2[t >> 5] = s2; }
    __syncthreads();
    if (t == 0) {
        float S = 0.f, S2 = 0.f;
        for (int i = 0; i < 8; i++) { S += rs[i]; S2 += rs2[i]; }
        float mu  = S * (1.f / 512.f);
        float var = S2 * (1.f / 512.f) - mu * mu;
        smu = mu; sinv = rsqrtf(var + C_EPS);
    }
    __syncthreads();
    float sc[2];
#pragma unroll
    for (int i = 0; i < 2; i++) {
        int c = t * 2 + i;
        float ln = (nc[i] - smu) * sinv * gg[c] + bb[c];
        sc[i] = ln / nc[i];
    }
    if (inter) {
#pragma unroll
        for (int i = 0; i < 2; i++) {
            int c = t * 2 + i;
#pragma unroll
            for (int xx = 0; xx < 3; xx++) Xout[(long)n * 1536 + c * 3 + xx] = xv[i][xx] * sc[i];
        }
    } else {
#pragma unroll
        for (int xx = 0; xx < 3; xx++) {
            long idx = xx * P + (long)n * C_D + t * 2;
            float o0 = xv[0][xx] * sc[0], o1 = xv[1][xx] * sc[1];
            *(float2*)(Xout + idx) = make_float2(o0, o1);
            if (bH) bsplit2(o0, o1, bH, bL, idx);
        }
    }
}

// ---------------- FF gating (projection rejection, vectorized) ----------------
__global__ void k_gate()
{
    const long P = (long)C_N * C_FF;
    const float* Y  = &g_Y[0][0][0];
    const float* Dv = &g_DV[0][0][0];
    long stride = (long)gridDim.x * blockDim.x;
    for (long p = (long)blockIdx.x * blockDim.x + threadIdx.x; p < P / 2; p += stride) {
        long i = 2 * p;
        float2 y0 = *(const float2*)(Y + i), y1 = *(const float2*)(Y + P + i), y2 = *(const float2*)(Y + 2 * P + i);
        float2 d0 = *(const float2*)(Dv + i), d1 = *(const float2*)(Dv + P + i), d2 = *(const float2*)(Dv + 2 * P + i);
        float dotx = y0.x * d0.x + y1.x * d1.x + y2.x * d2.x;
        float doty = y0.y * d0.y + y1.y * d1.y + y2.y * d2.y;
        float fx = (dotx >= 0.f) ? 0.f : 0.8f * dotx / (d0.x * d0.x + d1.x * d1.x + d2.x * d2.x + C_EPS);
        float fy = (doty >= 0.f) ? 0.f : 0.8f * doty / (d0.y * d0.y + d1.y * d1.y + d2.y * d2.y + C_EPS);
        bsplit2(y0.x - fx * d0.x, y0.y - fy * d0.y, &g_Y2b_h[0][0][0], &g_Y2b_l[0][0][0], i);
        bsplit2(y1.x - fx * d1.x, y1.y - fy * d1.y, &g_Y2b_h[0][0][0], &g_Y2b_l[0][0][0], P + i);
        bsplit2(y2.x - fx * d2.x, y2.y - fy * d2.y, &g_Y2b_h[0][0][0], &g_Y2b_l[0][0][0], 2 * P + i);
    }
}

// ---------------- host launch ----------------
extern "C" void kernel_launch(void* const* d_in, const int* in_sizes, int n_in,
                              void* d_out, int out_size)
{
    const float* tgt    = (const float*)d_in[0];
    const float* mem    = (const float*)d_in[1];
    const float* esh    = (const float*)d_in[2];
    const float* escal  = (const float*)d_in[3];
    const float* W_src  = (const float*)d_in[4];
    const float* W_dst  = (const float*)d_in[5];
    const float* fc_w1  = (const float*)d_in[6];
    const float* fc_b1  = (const float*)d_in[7];
    const float* fc_w2  = (const float*)d_in[8];
    const float* fc_b2  = (const float*)d_in[9];
    const float* fc_w3  = (const float*)d_in[10];
    const float* fc_b3  = (const float*)d_in[11];
    const float* W_alpha= (const float*)d_in[12];
    const float* ln_a_g = (const float*)d_in[13];
    const float* ln_a_b = (const float*)d_in[14];
    const float* adot   = (const float*)d_in[15];
    const float* W_value= (const float*)d_in[16];
    const float* W_proj = (const float*)d_in[17];
    const float* n1_g   = (const float*)d_in[18];
    const float* n1_b   = (const float*)d_in[19];
    const float* n2_g   = (const float*)d_in[20];
    const float* n2_b   = (const float*)d_in[21];
    const float* W_ff1  = (const float*)d_in[22];
    const float* W_ffd  = (const float*)d_in[23];
    const float* W_ff2  = (const float*)d_in[24];

#define SYM(p, s) cudaGetSymbolAddress((void**)&p, s)
    float *pTV, *pMSG, *paraw, *pXP, *pX1, *pY, *pDV, *pY3;
    SYM(pTV, g_TV); SYM(pMSG, g_MSG); SYM(paraw, g_araw);
    SYM(pXP, g_XP); SYM(pX1, g_X1); SYM(pY, g_Y); SYM(pDV, g_DV); SYM(pY3, g_Y3);
    bf16 *pTbh, *pTbl, *pMbh, *pMbl, *ppsh, *ppsl, *pZh, *pZl, *pOh, *pOl;
    bf16 *pX1h, *pX1l, *pYh, *pYl, *pY2h, *pY2l;
    SYM(pTbh, g_Tb_h); SYM(pTbl, g_Tb_l); SYM(pMbh, g_Mb_h); SYM(pMbl, g_Mb_l);
    SYM(ppsh, g_pscb_h); SYM(ppsl, g_pscb_l); SYM(pZh, g_Zb_h); SYM(pZl, g_Zb_l);
    SYM(pOh, g_OUTb_h); SYM(pOl, g_OUTb_l); SYM(pX1h, g_X1b_h); SYM(pX1l, g_X1b_l);
    SYM(pYh, g_Yb_h); SYM(pYl, g_Yb_l); SYM(pY2h, g_Y2b_h); SYM(pY2l, g_Y2b_l);
    bf16 *pWsh, *pWsl, *pWdh, *pWdl, *pWah, *pWal, *pWvh, *pWvl, *pWph, *pWpl;
    bf16 *pW1h, *pW1l, *pWfh, *pWfl, *pW2h, *pW2l;
    SYM(pWsh, g_Wsrc_h); SYM(pWsl, g_Wsrc_l); SYM(pWdh, g_Wdst_h); SYM(pWdl, g_Wdst_l);
    SYM(pWah, g_Wa_h); SYM(pWal, g_Wa_l); SYM(pWvh, g_Wv_h); SYM(pWvl, g_Wv_l);
    SYM(pWph, g_Wp_h); SYM(pWpl, g_Wp_l); SYM(pW1h, g_Wf1_h); SYM(pW1l, g_Wf1_l);
    SYM(pWfh, g_Wfd_h); SYM(pWfl, g_Wfd_l); SYM(pW2h, g_Wf2_h); SYM(pW2l, g_Wf2_l);
#undef SYM

    const long NP_D  = (long)C_N * C_D;
    const long EP_D  = (long)C_E * C_D;
    const long NP_FF = (long)C_N * C_FF;
    const long NHD   = (long)C_N * C_H * C_D;

    const int SM128 = 3 * (2 * 10240 + 2 * 128 * 80);   // 92160
    const int SM64  = 3 * (2 * 10240 + 2 * 64 * 80);    // 61440
    cudaFuncSetAttribute(gemm_bf<128>, cudaFuncAttributeMaxDynamicSharedMemorySize, SM128);
    cudaFuncSetAttribute(gemm_bf<64>,  cudaFuncAttributeMaxDynamicSharedMemorySize, SM64);

    // 1) input + weight splits
    k_split_in<<<4096, 256>>>(tgt, mem);
    k_split_all<<<8192, 256>>>(W_src, W_dst, W_value, W_proj, W_ff1, W_ffd, W_ff2, W_alpha);

    // 2) tv = W_dst @ tgt
    gemm_bf<128><<<dim3(4, 8, 3), 128, SM128>>>(pTbh, pTbl, pWdh, pWdl, pTV, nullptr, nullptr, nullptr,
        C_D, C_D, C_D, C_D, NP_D, 0, 0, 0, NP_D, 0, 1, 1, 0, 0);

    // 3) msg = W_src @ memory + tv[e/K]
    gemm_bf<128><<<dim3(4, 128, 3), 128, SM128>>>(pMbh, pMbl, pWsh, pWsl, pMSG, pTV, nullptr, nullptr,
        C_D, C_D, C_D, C_D, EP_D, 0, 0, 0, EP_D, 0, 1, C_K, C_D, NP_D);

    // 4) edge MLP -> g_w
    k_mlp<<<C_E / 64, 256>>>(escal, fc_w1, fc_b1, fc_w2, fc_b2, fc_w3, fc_b3);

    // 5) p_sc / pv
    k_pointwise<<<2048, 256>>>(esh);

    // 6) a_raw = p_sc @ W_alpha
    gemm_bf<64><<<dim3(1, 128, 1), 128, SM64>>>(ppsh, ppsl, pWah, pWal, paraw, nullptr, nullptr, nullptr,
        C_D, C_D, C_MA, C_D, 0, 0, 0, 0, 0, 0, 1, 1, 0, 0);

    // 7) LN + lrelu + head dot, then softmax over K
    k_alpha_post<<<2048, 256>>>(ln_a_g, ln_a_b, adot);
    k_softmax<<<32, 256>>>();

    // 8) z = sum_k att * pv
    k_z<<<dim3(C_N, 3), 256>>>();

    // 9) out = W_value @ z (per head, bf16 out), then proj + tv
    gemm_bf<64><<<dim3(1, 8, 24), 128, SM64>>>(pZh, pZl, pWvh, pWvl, nullptr, nullptr, pOh, pOl,
        C_H * C_D, C_D, C_D, C_D, NHD, C_D, 0, 64 * C_D, NP_D, 64, C_H, 1, 0, 0);
    gemm_bf<128><<<dim3(4, 8, 3), 128, SM128>>>(pOh, pOl, pWph, pWpl, pXP, pTV, nullptr, nullptr,
        C_D, C_D, C_D, C_D, NP_D, 0, 0, 0, NP_D, 0, 1, 1, C_D, NP_D);

    // 10) vn_ln #1 (fp32 + bf16 pair)
    k_vnln<<<C_N, 256>>>(pXP, pX1, pX1h, pX1l, n1_g, n1_b, 0);

    // 11) FF block
    gemm_bf<128><<<dim3(16, 8, 3), 128, SM128>>>(pX1h, pX1l, pW1h, pW1l, pY, nullptr, pYh, pYl,
        C_D, C_D, C_FF, C_D, NP_D, 0, 0, 0, NP_FF, 0, 1, 1, 0, 0);
    gemm_bf<128><<<dim3(16, 8, 3), 128, SM128>>>(pYh, pYl, pWfh, pWfl, pDV, nullptr, nullptr, nullptr,
        C_FF, C_FF, C_FF, C_FF, NP_FF, 0, 0, 0, NP_FF, 0, 1, 1, 0, 0);
    k_gate<<<2048, 256>>>();
    gemm_bf<128><<<dim3(4, 8, 3), 128, SM128>>>(pY2h, pY2l, pW2h, pW2l, pY3, pX1, nullptr, nullptr,
        C_FF, C_FF, C_D, C_FF, NP_FF, 0, 0, 0, NP_D, 0, 1, 1, C_D, NP_D);

    // 12) vn_ln #2 -> interleaved (n, c*3+x) output
    k_vnln<<<C_N, 256>>>(pY3, (float*)d_out, nullptr, nullptr, n2_g, n2_b, 1);
}

// round 12
// speedup vs baseline: 1.0753x; 1.0753x over previous
#include <cuda_runtime.h>
#include <cuda_bf16.h>
#include <math.h>
#include <stdint.h>

// ---------------- problem constants ----------------
#define C_N   1024
#define C_K   16
#define C_D   512
#define C_H   8
#define C_FF  2048
#define C_MA  64
#define C_ES  64
#define C_E   (C_N * C_K)      // 16384
#define C_EPS 1e-6f

typedef __nv_bfloat16 bf16;

// ---------------- fp32 scratch ----------------
__device__ float g_TV  [3][C_N][C_D];
__device__ float g_w   [C_E][3*C_D];
__device__ float g_araw[C_E][C_MA];
__device__ float g_att [C_E][C_H];
__device__ float g_XP  [3][C_N][C_D];
__device__ float g_X1  [3][C_N][C_D];
__device__ float g_Y   [3][C_N][C_FF];
__device__ float g_DV  [3][C_N][C_FF];
__device__ float g_Y3  [3][C_N][C_D];

// ---------------- bf16 hi/lo pairs ----------------
__device__ __align__(128) bf16 g_Tb_h [3][C_N][C_D],        g_Tb_l [3][C_N][C_D];
__device__ __align__(128) bf16 g_Mb_h [3][C_E][C_D],        g_Mb_l [3][C_E][C_D];
__device__ __align__(128) bf16 g_MSGb_h[3][C_E][C_D],       g_MSGb_l[3][C_E][C_D];
__device__ __align__(128) bf16 g_PVb_h[3][C_E][C_D],        g_PVb_l[3][C_E][C_D];
__device__ __align__(128) bf16 g_pscb_h[C_E][C_D],          g_pscb_l[C_E][C_D];
__device__ __align__(128) bf16 g_Zb_h [3][C_N][C_H][C_D],   g_Zb_l [3][C_N][C_H][C_D];
__device__ __align__(128) bf16 g_OUTb_h[3][C_N][C_D],       g_OUTb_l[3][C_N][C_D];
__device__ __align__(128) bf16 g_X1b_h[3][C_N][C_D],        g_X1b_l[3][C_N][C_D];
__device__ __align__(128) bf16 g_Yb_h [3][C_N][C_FF],       g_Yb_l [3][C_N][C_FF];
__device__ __align__(128) bf16 g_Y2b_h[3][C_N][C_FF],       g_Y2b_l[3][C_N][C_FF];
// weights
__device__ __align__(128) bf16 g_Wsrc_h[C_D*C_D],  g_Wsrc_l[C_D*C_D];
__device__ __align__(128) bf16 g_Wdst_h[C_D*C_D],  g_Wdst_l[C_D*C_D];
__device__ __align__(128) bf16 g_Wa_h  [C_MA*C_D], g_Wa_l  [C_MA*C_D];
__device__ __align__(128) bf16 g_Wv_h  [C_D*C_D],  g_Wv_l  [C_D*C_D];
__device__ __align__(128) bf16 g_Wp_h  [C_D*C_D],  g_Wp_l  [C_D*C_D];
__device__ __align__(128) bf16 g_Wf1_h [C_FF*C_D], g_Wf1_l [C_FF*C_D];
__device__ __align__(128) bf16 g_Wfd_h [C_FF*C_FF],g_Wfd_l [C_FF*C_FF];
__device__ __align__(128) bf16 g_Wf2_h [C_D*C_FF], g_Wf2_l [C_D*C_FF];

// ---------------- helpers ----------------
__device__ __forceinline__ void bsplit(float v, bf16* H, bf16* L, long i) {
    bf16 h = __float2bfloat16_rn(v);
    H[i] = h;
    L[i] = __float2bfloat16_rn(v - __bfloat162float(h));
}
__device__ __forceinline__ void bsplit2(float v0, float v1, bf16* H, bf16* L, long i) {
    bf16 h0 = __float2bfloat16_rn(v0), h1 = __float2bfloat16_rn(v1);
    *(__nv_bfloat162*)(H + i) = __nv_bfloat162(h0, h1);
    *(__nv_bfloat162*)(L + i) = __nv_bfloat162(
        __float2bfloat16_rn(v0 - __bfloat162float(h0)),
        __float2bfloat16_rn(v1 - __bfloat162float(h1)));
}
// reconstruct 2 adjacent values from a hi/lo pair
__device__ __forceinline__ float2 brecon2(const bf16* H, const bf16* L, long i) {
    __nv_bfloat162 h = *(const __nv_bfloat162*)(H + i);
    __nv_bfloat162 l = *(const __nv_bfloat162*)(L + i);
    return make_float2(__bfloat162float(h.x) + __bfloat162float(l.x),
                       __bfloat162float(h.y) + __bfloat162float(l.y));
}
__device__ __forceinline__ uint32_t s2u(const void* p) {
    uint32_t a;
    asm("{ .reg .u64 t; cvta.to.shared.u64 t, %1; cvt.u32.u64 %0, t; }" : "=r"(a) : "l"(p));
    return a;
}
__device__ __forceinline__ void mma_bf16(float* c, const uint32_t* a, const uint32_t* b) {
    asm volatile("mma.sync.aligned.m16n8k16.row.col.f32.bf16.bf16.f32 "
                 "{%0,%1,%2,%3},{%4,%5,%6,%7},{%8,%9},{%0,%1,%2,%3};"
                 : "+f"(c[0]), "+f"(c[1]), "+f"(c[2]), "+f"(c[3])
                 : "r"(a[0]), "r"(a[1]), "r"(a[2]), "r"(a[3]), "r"(b[0]), "r"(b[1]));
}
__device__ __forceinline__ void ldsm4(uint32_t* r, uint32_t addr) {
    asm volatile("ldmatrix.sync.aligned.m8n8.x4.shared.b16 {%0,%1,%2,%3}, [%4];"
        : "=r"(r[0]), "=r"(r[1]), "=r"(r[2]), "=r"(r[3]) : "r"(addr));
}
#define CPA(d, s) asm volatile("cp.async.cg.shared.global [%0], [%1], 16;" :: "r"(d), "l"(s) : "memory")
#define CPC()     asm volatile("cp.async.commit_group;" ::: "memory")
#define CPW(n)    asm volatile("cp.async.wait_group %0;" :: "n"(n) : "memory")

// ============ bf16-pair NT GEMM: C[m,n] = sum_k A[m,k]*B[n,k] (+Add) ============
// 128xBN CTA tile, 128 threads (4 warps, 64x(BN/2) warp tiles), 2-stage cp.async,
// ldmatrix fragments, 3 HMMA passes (hh+hl+lh). M%128==0, N%BN==0, K%64==0.
template<int BN>
__global__ void __launch_bounds__(128, 2) gemm_bf(
    const bf16* __restrict__ Ah, const bf16* __restrict__ Al,
    const bf16* __restrict__ Bh, const bf16* __restrict__ Bl,
    float* __restrict__ C, const float* __restrict__ Add,
    bf16* __restrict__ CbH, bf16* __restrict__ CbL,
    int lda, int ldb, int ldc, int Kc,
    long sA1, long sA2, long sB1, long sB2, long sC1, long sC2, int nz2,
    int addDiv, int ldadd, long sAdd1)
{
    constexpr int WN   = BN / 2;
    constexpr int NSUB = WN / 8;
    constexpr int ABY  = 10240;          // 128 rows x 80B
    constexpr int BBY  = BN * 80;
    constexpr int STG  = 2 * ABY + 2 * BBY;

    extern __shared__ __align__(16) char sm[];
    const int t = threadIdx.x, wid = t >> 5, lane = t & 31;
    const int g = lane >> 2, tq = lane & 3;
    const int wm = wid & 1, wn = wid >> 1;

    const int z = blockIdx.z, z1 = z / nz2, z2 = z - z1 * nz2;
    const long m0 = (long)blockIdx.y * 128, n0 = (long)blockIdx.x * BN;
    const bf16* Agh = Ah + z1 * sA1 + z2 * sA2 + m0 * lda;
    const bf16* Agl = Al + z1 * sA1 + z2 * sA2 + m0 * lda;
    const bf16* Bgh = Bh + z1 * sB1 + z2 * sB2 + n0 * ldb;
    const bf16* Bgl = Bl + z1 * sB1 + z2 * sB2 + n0 * ldb;

    const uint32_t smb = s2u(sm);
    const int crow = t >> 2, cseg = t & 3;

    const int lm = lane >> 3, lr = lane & 7;
    const int a_off0 = (wm * 64 + (lm & 1) * 8 + lr) * 80 + (lm >> 1) * 16;
    const int b_off0 = (wn * WN + (lm >> 1) * 8 + lr) * 80 + (lm & 1) * 16;

    float acc[4][NSUB][4];
#pragma unroll
    for (int mi = 0; mi < 4; mi++)
#pragma unroll
        for (int ni = 0; ni < NSUB; ni++)
#pragma unroll
            for (int j = 0; j < 4; j++) acc[mi][ni][j] = 0.f;

    const int nch = Kc >> 5;

    // prologue: issue chunk 0
    {
        const uint32_t st = smb;
#pragma unroll
        for (int i = 0; i < 4; i++) {
            int row = crow + i * 32;
            uint32_t d = st + row * 80 + cseg * 16;
            CPA(d,       Agh + (long)row * lda + cseg * 8);
            CPA(d + ABY, Agl + (long)row * lda + cseg * 8);
        }
#pragma unroll
        for (int i = 0; i < BN / 32; i++) {
            int row = crow + i * 32;
            uint32_t d = st + 2 * ABY + row * 80 + cseg * 16;
            CPA(d,       Bgh + (long)row * ldb + cseg * 8);
            CPA(d + BBY, Bgl + (long)row * ldb + cseg * 8);
        }
        CPC();
    }

    for (int ch = 0; ch < nch; ch++) {
        if (ch + 1 < nch) {
            const uint32_t st = smb + ((ch + 1) & 1) * STG;
            const bf16* ah = Agh + (ch + 1) * 32;
            const bf16* al = Agl + (ch + 1) * 32;
            const bf16* bh = Bgh + (ch + 1) * 32;
            const bf16* bl = Bgl + (ch + 1) * 32;
#pragma unroll
            for (int i = 0; i < 4; i++) {
                int row = crow + i * 32;
                uint32_t d = st + row * 80 + cseg * 16;
                CPA(d,       ah + (long)row * lda + cseg * 8);
                CPA(d + ABY, al + (long)row * lda + cseg * 8);
            }
#pragma unroll
            for (int i = 0; i < BN / 32; i++) {
                int row = crow + i * 32;
                uint32_t d = st + 2 * ABY + row * 80 + cseg * 16;
                CPA(d,       bh + (long)row * ldb + cseg * 8);
                CPA(d + BBY, bl + (long)row * ldb + cseg * 8);
            }
            CPC();
            CPW(1);
        } else {
            CPW(0);
        }
        __syncthreads();

        const uint32_t sbase = smb + (ch & 1) * STG;
#pragma unroll
        for (int ks = 0; ks < 2; ks++) {
            const int ko = ks * 32;
            uint32_t fa[16], fbh[2 * NSUB], fbl[2 * NSUB];
            const uint32_t abase = sbase + a_off0 + ko;
            const uint32_t bbase = sbase + 2 * ABY + b_off0 + ko;
#pragma unroll
            for (int mi = 0; mi < 4; mi++) ldsm4(&fa[mi * 4], abase + mi * 1280);
#pragma unroll
            for (int np = 0; np < NSUB / 2; np++) ldsm4(&fbh[np * 4], bbase + np * 1280);
#pragma unroll
            for (int mi = 0; mi < 4; mi++)
#pragma unroll
                for (int ni = 0; ni < NSUB; ni++)
                    mma_bf16(acc[mi][ni], &fa[mi * 4], &fbh[ni * 2]);   // hi*hi
#pragma unroll
            for (int np = 0; np < NSUB / 2; np++) ldsm4(&fbl[np * 4], bbase + BBY + np * 1280);
#pragma unroll
            for (int mi = 0; mi < 4; mi++)
#pragma unroll
                for (int ni = 0; ni < NSUB; ni++)
                    mma_bf16(acc[mi][ni], &fa[mi * 4], &fbl[ni * 2]);   // hi*lo
#pragma unroll
            for (int mi = 0; mi < 4; mi++) ldsm4(&fa[mi * 4], abase + ABY + mi * 1280);
#pragma unroll
            for (int mi = 0; mi < 4; mi++)
#pragma unroll
                for (int ni = 0; ni < NSUB; ni++)
                    mma_bf16(acc[mi][ni], &fa[mi * 4], &fbh[ni * 2]);   // lo*hi
        }
        __syncthreads();
    }

    // ---- epilogue ----
    float* Cp = C ? (C + z1 * sC1 + z2 * sC2) : (float*)0;
    bf16* Ch = CbH ? (CbH + z1 * sC1 + z2 * sC2) : (bf16*)0;
    bf16* Cl = CbL ? (CbL + z1 * sC1 + z2 * sC2) : (bf16*)0;
    const float* Ad = Add ? (Add + z1 * sAdd1) : (const float*)0;
#pragma unroll
    for (int mi = 0; mi < 4; mi++) {
        long r0 = m0 + wm * 64 + mi * 16 + g;
#pragma unroll
        for (int ni = 0; ni < NSUB; ni++) {
            long col = n0 + wn * WN + ni * 8 + tq * 2;
            float2 v0 = make_float2(acc[mi][ni][0], acc[mi][ni][1]);
            float2 v1 = make_float2(acc[mi][ni][2], acc[mi][ni][3]);
            if (Ad) {
                float2 a0 = *(const float2*)(Ad + (r0 / addDiv) * (long)ldadd + col);
                float2 a1 = *(const float2*)(Ad + ((r0 + 8) / addDiv) * (long)ldadd + col);
                v0.x += a0.x; v0.y += a0.y; v1.x += a1.x; v1.y += a1.y;
            }
            if (Cp) {
                *(float2*)(Cp + r0 * ldc + col) = v0;
                *(float2*)(Cp + (r0 + 8) * ldc + col) = v1;
            }
            if (Ch) {
                long i0 = r0 * ldc + col, i1 = (r0 + 8) * ldc + col;
                bsplit2(v0.x, v0.y, Ch, Cl, i0);
                bsplit2(v1.x, v1.y, Ch, Cl, i1);
            }
        }
    }
}

// ---------------- input transpose + bf16 split (vectorized) ----------------
__global__ void k_split_in(const float* __restrict__ tgt, const float* __restrict__ mem)
{
    long stride = (long)gridDim.x * blockDim.x;
    long base   = (long)blockIdx.x * blockDim.x + threadIdx.x;
    for (long p = base; p < (long)C_N * C_D / 2; p += stride) {
        const float* s = tgt + 6 * p;
        float2 a = *(const float2*)s, b = *(const float2*)(s + 2), c = *(const float2*)(s + 4);
        bsplit2(a.x, b.y, &g_Tb_h[0][0][0], &g_Tb_l[0][0][0], 2 * p);
        bsplit2(a.y, c.x, &g_Tb_h[1][0][0], &g_Tb_l[1][0][0], 2 * p);
        bsplit2(b.x, c.y, &g_Tb_h[2][0][0], &g_Tb_l[2][0][0], 2 * p);
    }
    for (long p = base; p < (long)C_E * C_D / 2; p += stride) {
        const float* s = mem + 6 * p;
        float2 a = *(const float2*)s, b = *(const float2*)(s + 2), c = *(const float2*)(s + 4);
        bsplit2(a.x, b.y, &g_Mb_h[0][0][0], &g_Mb_l[0][0][0], 2 * p);
        bsplit2(a.y, c.x, &g_Mb_h[1][0][0], &g_Mb_l[1][0][0], 2 * p);
        bsplit2(b.x, c.y, &g_Mb_h[2][0][0], &g_Mb_l[2][0][0], 2 * p);
    }
}

// ---------------- all weight splits in one kernel ----------------
__global__ void k_split_all(
    const float* __restrict__ Wsrc, const float* __restrict__ Wdst,
    const float* __restrict__ Wv,   const float* __restrict__ Wp,
    const float* __restrict__ Wf1,  const float* __restrict__ Wfd,
    const float* __restrict__ Wf2,  const float* __restrict__ Wa)
{
    const long SQ = (long)C_D * C_D;
    const long O4 = 4 * SQ;
    const long O5 = O4 + (long)C_FF * C_D;
    const long O6 = O5 + (long)C_FF * C_FF;
    const long O7 = O6 + (long)C_D * C_FF;
    const long O8 = O7 + (long)C_MA * C_D;
    long stride = (long)gridDim.x * blockDim.x;
    for (long i = (long)blockIdx.x * blockDim.x + threadIdx.x; i < O8; i += stride) {
        if (i < SQ)            bsplit(Wsrc[i],      g_Wsrc_h, g_Wsrc_l, i);
        else if (i < 2 * SQ)   bsplit(Wdst[i - SQ], g_Wdst_h, g_Wdst_l, i - SQ);
        else if (i < 3 * SQ)   bsplit(Wv[i - 2*SQ], g_Wv_h,   g_Wv_l,   i - 2*SQ);
        else if (i < 4 * SQ)   bsplit(Wp[i - 3*SQ], g_Wp_h,   g_Wp_l,   i - 3*SQ);
        else if (i < O5)       bsplit(Wf1[i - O4],  g_Wf1_h,  g_Wf1_l,  i - O4);
        else if (i < O6)       bsplit(Wfd[i - O5],  g_Wfd_h,  g_Wfd_l,  i - O5);
        else if (i < O7)       bsplit(Wf2[i - O6],  g_Wf2_h,  g_Wf2_l,  i - O6);
        else {
            long k = i - O7;                          // W_alpha (D x MA) -> transposed
            long r = k >> 6, c = k & 63;
            bsplit(Wa[k], g_Wa_h, g_Wa_l, c * C_D + r);
        }
    }
}

// ---------------- fused edge MLP ----------------
__global__ void __launch_bounds__(256) k_mlp(
    const float* __restrict__ es, const float* __restrict__ w1, const float* __restrict__ b1,
    const float* __restrict__ w2, const float* __restrict__ b2,
    const float* __restrict__ w3, const float* __restrict__ b3)
{
    __shared__ float s_es[64][65];
    __shared__ float s_w1[64][32];
    __shared__ float s_w2[32][32];
    __shared__ float s_h1[64][33];
    __shared__ float s_h2[64][33];
    const int t = threadIdx.x;
    const long e0 = (long)blockIdx.x * 64;

    for (int i = t; i < 64 * 32; i += 256) s_w1[i >> 5][i & 31] = w1[i];
    for (int i = t; i < 32 * 32; i += 256) s_w2[i >> 5][i & 31] = w2[i];
    for (int i = t; i < 64 * 64; i += 256) s_es[i >> 6][i & 63] = es[e0 * 64 + i];
    __syncthreads();

    for (int i = t; i < 64 * 32; i += 256) {
        int e = i >> 5, j = i & 31;
        float acc = b1[j];
#pragma unroll 8
        for (int c = 0; c < 64; c++) acc = fmaf(s_es[e][c], s_w1[c][j], acc);
        s_h1[e][j] = acc / (1.f + expf(-acc));
    }
    __syncthreads();
    for (int i = t; i < 64 * 32; i += 256) {
        int e = i >> 5, j = i & 31;
        float acc = b2[j];
#pragma unroll 8
        for (int c = 0; c < 32; c++) acc = fmaf(s_h1[e][c], s_w2[c][j], acc);
        s_h2[e][j] = acc / (1.f + expf(-acc));
    }
    __syncthreads();
    for (int i = t; i < 64 * 1536; i += 256) {
        int e = i / 1536, o = i - e * 1536;
        float acc = b3[o];
#pragma unroll 8
        for (int c = 0; c < 32; c++) acc = fmaf(s_h2[e][c], w3[c * 1536 + o], acc);
        g_w[e0 + e][o] = acc;
    }
}

// ---------------- pointwise equivariant products (bf16-pair MSG in / PV out) ----------------
__global__ void k_pointwise(const float* __restrict__ esh)
{
    long stride = (long)gridDim.x * blockDim.x;
    for (long p = (long)blockIdx.x * blockDim.x + threadIdx.x; p < (long)C_E * C_D / 2; p += stride) {
        int  c = (int)(p & 255) * 2;
        long e = p >> 8;
        long idx = e * C_D + c;
        float s  = esh[e * 4 + 0];
        float v0 = esh[e * 4 + 1], v1 = esh[e * 4 + 2], v2 = esh[e * 4 + 3];
        const long P = (long)C_E * C_D;
        float2 m0 = brecon2(&g_MSGb_h[0][0][0], &g_MSGb_l[0][0][0], idx);
        float2 m1 = brecon2(&g_MSGb_h[0][0][0], &g_MSGb_l[0][0][0], P + idx);
        float2 m2 = brecon2(&g_MSGb_h[0][0][0], &g_MSGb_l[0][0][0], 2 * P + idx);
        float2 w0 = *(const float2*)&g_w[e][c];
        float2 w1 = *(const float2*)&g_w[e][512 + c];
        float2 w2 = *(const float2*)&g_w[e][1024 + c];
        float p0 = w0.x * (m0.x * v0 + m1.x * v1 + m2.x * v2) * 0.5773502691896258f;
        float p1 = w0.y * (m0.y * v0 + m1.y * v1 + m2.y * v2) * 0.5773502691896258f;
        bsplit2(p0, p1, &g_pscb_h[0][0], &g_pscb_l[0][0], idx);
        float k2x = w2.x * 0.7071067811865475f, k2y = w2.y * 0.7071067811865475f;
        float wsx = w1.x * s, wsy = w1.y * s;
        bsplit2(wsx * m0.x + k2x * (m1.x * v2 - m2.x * v1),
                wsy * m0.y + k2y * (m1.y * v2 - m2.y * v1),
                &g_PVb_h[0][0][0], &g_PVb_l[0][0][0], idx);
        bsplit2(wsx * m1.x + k2x * (m2.x * v0 - m0.x * v2),
                wsy * m1.y + k2y * (m2.y * v0 - m0.y * v2),
                &g_PVb_h[0][0][0], &g_PVb_l[0][0][0], P + idx);
        bsplit2(wsx * m2.x + k2x * (m0.x * v1 - m1.x * v0),
                wsy * m2.y + k2y * (m0.y * v1 - m1.y * v0),
                &g_PVb_h[0][0][0], &g_PVb_l[0][0][0], 2 * P + idx);
    }
}

// ---------------- fused alpha post (LN + lrelu + head dot) + softmax over K ----------------
__global__ void __launch_bounds__(512) k_alpha(const float* __restrict__ gg, const float* __restrict__ bb,
                                               const float* __restrict__ adot)
{
    int n = blockIdx.x;
    int t = threadIdx.x, wid = t >> 5, lane = t & 31;
    __shared__ float s_l[16][8];
    int e = n * 16 + wid;
    float v0 = g_araw[e][lane * 2], v1 = g_araw[e][lane * 2 + 1];
    float s = v0 + v1, s2 = v0 * v0 + v1 * v1;
#pragma unroll
    for (int o = 16; o > 0; o >>= 1) {
        s  += __shfl_xor_sync(0xffffffffu, s, o);
        s2 += __shfl_xor_sync(0xffffffffu, s2, o);
    }
    float mu  = s * (1.f / 64.f);
    float var = s2 * (1.f / 64.f) - mu * mu;
    float inv = rsqrtf(var + C_EPS);
    float a0 = (v0 - mu) * inv * gg[lane * 2]     + bb[lane * 2];
    float a1 = (v1 - mu) * inv * gg[lane * 2 + 1] + bb[lane * 2 + 1];
    a0 = 0.6f * a0 + 0.4f * a0 * tanhf(0.5f * a0);
    a1 = 0.6f * a1 + 0.4f * a1 * tanhf(0.5f * a1);
    int h = lane >> 2;
    int m = (lane & 3) * 2;
    float p = a0 * adot[h * 8 + m] + a1 * adot[h * 8 + m + 1];
    p += __shfl_xor_sync(0xffffffffu, p, 1);
    p += __shfl_xor_sync(0xffffffffu, p, 2);
    if ((lane & 3) == 0) s_l[wid][h] = p;
    __syncthreads();
    if (t < 8) {
        float mx = -1e30f;
#pragma unroll
        for (int k = 0; k < 16; k++) mx = fmaxf(mx, s_l[k][t]);
        float sum = 0.f; float ex[16];
#pragma unroll
        for (int k = 0; k < 16; k++) { ex[k] = expf(s_l[k][t] - mx); sum += ex[k]; }
        float is = 1.f / sum;
#pragma unroll
        for (int k = 0; k < 16; k++) g_att[n * 16 + k][t] = ex[k] * is;
    }
}

// ---------------- z = sum_k att * pv (bf16-pair PV in / pair out) ----------------
__global__ void __launch_bounds__(256) k_z()
{
    int n = blockIdx.x, x = blockIdx.y;
    __shared__ float s_a[16][8];
    if (threadIdx.x < 128)
        s_a[threadIdx.x >> 3][threadIdx.x & 7] = g_att[n * 16 + (threadIdx.x >> 3)][threadIdx.x & 7];
    __syncthreads();
    int c = threadIdx.x * 2;
    const long P = (long)C_E * C_D;
    float2 acc[8];
#pragma unroll
    for (int h = 0; h < 8; h++) acc[h] = make_float2(0.f, 0.f);
#pragma unroll
    for (int k = 0; k < 16; k++) {
        float2 pv = brecon2(&g_PVb_h[0][0][0], &g_PVb_l[0][0][0],
                            (long)x * P + (long)(n * 16 + k) * C_D + c);
#pragma unroll
        for (int h = 0; h < 8; h++) {
            acc[h].x = fmaf(s_a[k][h], pv.x, acc[h].x);
            acc[h].y = fmaf(s_a[k][h], pv.y, acc[h].y);
        }
    }
#pragma unroll
    for (int h = 0; h < 8; h++) {
        long idx = (((long)x * C_N + n) * C_H + h) * C_D + c;
        bsplit2(acc[h].x, acc[h].y, &g_Zb_h[0][0][0][0], &g_Zb_l[0][0][0][0], idx);
    }
}

// ---------------- vector-norm LayerNorm (vn_ln) ----------------
__global__ void __launch_bounds__(256) k_vnln(const float* __restrict__ Xin, float* __restrict__ Xout,
                                              bf16* __restrict__ bH, bf16* __restrict__ bL,
                                              const float* __restrict__ gg, const float* __restrict__ bb,
                                              int inter)
{
    int n = blockIdx.x, t = threadIdx.x;
    const long P = (long)C_N * C_D;
    __shared__ float rs[8], rs2[8];
    __shared__ float smu, sinv;
    float xv[2][3], nc[2];
    float s = 0.f, s2 = 0.f;
#pragma unroll
    for (int i = 0; i < 2; i++) {
        int c = t * 2 + i;
#pragma unroll
        for (int xx = 0; xx < 3; xx++) xv[i][xx] = Xin[xx * P + (long)n * C_D + c];
        float v = sqrtf(xv[i][0] * xv[i][0] + xv[i][1] * xv[i][1] + xv[i][2] * xv[i][2] + C_EPS);
        nc[i] = v; s += v; s2 = fmaf(v, v, s2);
    }
#pragma unroll
    for (int o = 16; o > 0; o >>= 1) {
        s  += __shfl_xor_sync(0xffffffffu, s, o);
        s2 += __shfl_xor_sync(0xffffffffu, s2, o);
    }
    if ((t & 31) == 0) { rs[t >> 5] = s; rs2[t >> 5] = s2; }
    __syncthreads();
    if (t == 0) {
        float S = 0.f, S2 = 0.f;
        for (int i = 0; i < 8; i++) { S += rs[i]; S2 += rs2[i]; }
        float mu  = S * (1.f / 512.f);
        float var = S2 * (1.f / 512.f) - mu * mu;
        smu = mu; sinv = rsqrtf(var + C_EPS);
    }
    __syncthreads();
    float sc[2];
#pragma unroll
    for (int i = 0; i < 2; i++) {
        int c = t * 2 + i;
        float ln = (nc[i] - smu) * sinv * gg[c] + bb[c];
        sc[i] = ln / nc[i];
    }
    if (inter) {
#pragma unroll
        for (int i = 0; i < 2; i++) {
            int c = t * 2 + i;
#pragma unroll
            for (int xx = 0; xx < 3; xx++) Xout[(long)n * 1536 + c * 3 + xx] = xv[i][xx] * sc[i];
        }
    } else {
#pragma unroll
        for (int xx = 0; xx < 3; xx++) {
            long idx = xx * P + (long)n * C_D + t * 2;
            float o0 = xv[0][xx] * sc[0], o1 = xv[1][xx] * sc[1];
            *(float2*)(Xout + idx) = make_float2(o0, o1);
            if (bH) bsplit2(o0, o1, bH, bL, idx);
        }
    }
}

// ---------------- FF gating (projection rejection, vectorized) ----------------
__global__ void k_gate()
{
    const long P = (long)C_N * C_FF;
    const float* Y  = &g_Y[0][0][0];
    const float* Dv = &g_DV[0][0][0];
    long stride = (long)gridDim.x * blockDim.x;
    for (long p = (long)blockIdx.x * blockDim.x + threadIdx.x; p < P / 2; p += stride) {
        long i = 2 * p;
        float2 y0 = *(const float2*)(Y + i), y1 = *(const float2*)(Y + P + i), y2 = *(const float2*)(Y + 2 * P + i);
        float2 d0 = *(const float2*)(Dv + i), d1 = *(const float2*)(Dv + P + i), d2 = *(const float2*)(Dv + 2 * P + i);
        float dotx = y0.x * d0.x + y1.x * d1.x + y2.x * d2.x;
        float doty = y0.y * d0.y + y1.y * d1.y + y2.y * d2.y;
        float fx = (dotx >= 0.f) ? 0.f : 0.8f * dotx / (d0.x * d0.x + d1.x * d1.x + d2.x * d2.x + C_EPS);
        float fy = (doty >= 0.f) ? 0.f : 0.8f * doty / (d0.y * d0.y + d1.y * d1.y + d2.y * d2.y + C_EPS);
        bsplit2(y0.x - fx * d0.x, y0.y - fy * d0.y, &g_Y2b_h[0][0][0], &g_Y2b_l[0][0][0], i);
        bsplit2(y1.x - fx * d1.x, y1.y - fy * d1.y, &g_Y2b_h[0][0][0], &g_Y2b_l[0][0][0], P + i);
        bsplit2(y2.x - fx * d2.x, y2.y - fy * d2.y, &g_Y2b_h[0][0][0], &g_Y2b_l[0][0][0], 2 * P + i);
    }
}

// ---------------- host launch ----------------
extern "C" void kernel_launch(void* const* d_in, const int* in_sizes, int n_in,
                              void* d_out, int out_size)
{
    const float* tgt    = (const float*)d_in[0];
    const float* mem    = (const float*)d_in[1];
    const float* esh    = (const float*)d_in[2];
    const float* escal  = (const float*)d_in[3];
    const float* W_src  = (const float*)d_in[4];
    const float* W_dst  = (const float*)d_in[5];
    const float* fc_w1  = (const float*)d_in[6];
    const float* fc_b1  = (const float*)d_in[7];
    const float* fc_w2  = (const float*)d_in[8];
    const float* fc_b2  = (const float*)d_in[9];
    const float* fc_w3  = (const float*)d_in[10];
    const float* fc_b3  = (const float*)d_in[11];
    const float* W_alpha= (const float*)d_in[12];
    const float* ln_a_g = (const float*)d_in[13];
    const float* ln_a_b = (const float*)d_in[14];
    const float* adot   = (const float*)d_in[15];
    const float* W_value= (const float*)d_in[16];
    const float* W_proj = (const float*)d_in[17];
    const float* n1_g   = (const float*)d_in[18];
    const float* n1_b   = (const float*)d_in[19];
    const float* n2_g   = (const float*)d_in[20];
    const float* n2_b   = (const float*)d_in[21];
    const float* W_ff1  = (const float*)d_in[22];
    const float* W_ffd  = (const float*)d_in[23];
    const float* W_ff2  = (const float*)d_in[24];

#define SYM(p, s) cudaGetSymbolAddress((void**)&p, s)
    float *pTV, *paraw, *pXP, *pX1, *pY, *pDV, *pY3;
    SYM(pTV, g_TV); SYM(paraw, g_araw);
    SYM(pXP, g_XP); SYM(pX1, g_X1); SYM(pY, g_Y); SYM(pDV, g_DV); SYM(pY3, g_Y3);
    bf16 *pTbh, *pTbl, *pMbh, *pMbl, *pMSGh, *pMSGl, *ppsh, *ppsl, *pZh, *pZl, *pOh, *pOl;
    bf16 *pX1h, *pX1l, *pYh, *pYl, *pY2h, *pY2l;
    SYM(pTbh, g_Tb_h); SYM(pTbl, g_Tb_l); SYM(pMbh, g_Mb_h); SYM(pMbl, g_Mb_l);
    SYM(pMSGh, g_MSGb_h); SYM(pMSGl, g_MSGb_l);
    SYM(ppsh, g_pscb_h); SYM(ppsl, g_pscb_l); SYM(pZh, g_Zb_h); SYM(pZl, g_Zb_l);
    SYM(pOh, g_OUTb_h); SYM(pOl, g_OUTb_l); SYM(pX1h, g_X1b_h); SYM(pX1l, g_X1b_l);
    SYM(pYh, g_Yb_h); SYM(pYl, g_Yb_l); SYM(pY2h, g_Y2b_h); SYM(pY2l, g_Y2b_l);
    bf16 *pWsh, *pWsl, *pWdh, *pWdl, *pWah, *pWal, *pWvh, *pWvl, *pWph, *pWpl;
    bf16 *pW1h, *pW1l, *pWfh, *pWfl, *pW2h, *pW2l;
    SYM(pWsh, g_Wsrc_h); SYM(pWsl, g_Wsrc_l); SYM(pWdh, g_Wdst_h); SYM(pWdl, g_Wdst_l);
    SYM(pWah, g_Wa_h); SYM(pWal, g_Wa_l); SYM(pWvh, g_Wv_h); SYM(pWvl, g_Wv_l);
    SYM(pWph, g_Wp_h); SYM(pWpl, g_Wp_l); SYM(pW1h, g_Wf1_h); SYM(pW1l, g_Wf1_l);
    SYM(pWfh, g_Wfd_h); SYM(pWfl, g_Wfd_l); SYM(pW2h, g_Wf2_h); SYM(pW2l, g_Wf2_l);
#undef SYM

    const long NP_D  = (long)C_N * C_D;
    const long EP_D  = (long)C_E * C_D;
    const long NP_FF = (long)C_N * C_FF;
    const long NHD   = (long)C_N * C_H * C_D;

    const int SM128 = 2 * (2 * 10240 + 2 * 128 * 80);   // 81920
    const int SM64  = 2 * (2 * 10240 + 2 * 64 * 80);    // 61440
    cudaFuncSetAttribute(gemm_bf<128>, cudaFuncAttributeMaxDynamicSharedMemorySize, SM128);
    cudaFuncSetAttribute(gemm_bf<64>,  cudaFuncAttributeMaxDynamicSharedMemorySize, SM64);

    // 1) input + weight splits
    k_split_in<<<4096, 256>>>(tgt, mem);
    k_split_all<<<8192, 256>>>(W_src, W_dst, W_value, W_proj, W_ff1, W_ffd, W_ff2, W_alpha);

    // 2) tv = W_dst @ tgt (fp32, reused by msg Add and proj Add)
    gemm_bf<128><<<dim3(4, 8, 3), 128, SM128>>>(pTbh, pTbl, pWdh, pWdl, pTV, nullptr, nullptr, nullptr,
        C_D, C_D, C_D, C_D, NP_D, 0, 0, 0, NP_D, 0, 1, 1, 0, 0);

    // 3) msg = W_src @ memory + tv[e/K]  -> bf16 pairs only
    gemm_bf<128><<<dim3(4, 128, 3), 128, SM128>>>(pMbh, pMbl, pWsh, pWsl, nullptr, pTV, pMSGh, pMSGl,
        C_D, C_D, C_D, C_D, EP_D, 0, 0, 0, EP_D, 0, 1, C_K, C_D, NP_D);

    // 4) edge MLP -> g_w
    k_mlp<<<C_E / 64, 256>>>(escal, fc_w1, fc_b1, fc_w2, fc_b2, fc_w3, fc_b3);

    // 5) p_sc / pv (pair in, pair out)
    k_pointwise<<<2048, 256>>>(esh);

    // 6) a_raw = p_sc @ W_alpha
    gemm_bf<64><<<dim3(1, 128, 1), 128, SM64>>>(ppsh, ppsl, pWah, pWal, paraw, nullptr, nullptr, nullptr,
        C_D, C_D, C_MA, C_D, 0, 0, 0, 0, 0, 0, 1, 1, 0, 0);

    // 7) fused LN + lrelu + head dot + softmax
    k_alpha<<<C_N, 512>>>(ln_a_g, ln_a_b, adot);

    // 8) z = sum_k att * pv
    k_z<<<dim3(C_N, 3), 256>>>();

    // 9) out = W_value @ z (per head, bf16 out), then proj + tv
    gemm_bf<64><<<dim3(1, 8, 24), 128, SM64>>>(pZh, pZl, pWvh, pWvl, nullptr, nullptr, pOh, pOl,
        C_H * C_D, C_D, C_D, C_D, NHD, C_D, 0, 64 * C_D, NP_D, 64, C_H, 1, 0, 0);
    gemm_bf<128><<<dim3(4, 8, 3), 128, SM128>>>(pOh, pOl, pWph, pWpl, pXP, pTV, nullptr, nullptr,
        C_D, C_D, C_D, C_D, NP_D, 0, 0, 0, NP_D, 0, 1, 1, C_D, NP_D);

    // 10) vn_ln #1 (fp32 + bf16 pair)
    k_vnln<<<C_N, 256>>>(pXP, pX1, pX1h, pX1l, n1_g, n1_b, 0);

    // 11) FF block
    gemm_bf<128><<<dim3(16, 8, 3), 128, SM128>>>(pX1h, pX1l, pW1h, pW1l, pY, nullptr, pYh, pYl,
        C_D, C_D, C_FF, C_D, NP_D, 0, 0, 0, NP_FF, 0, 1, 1, 0, 0);
    gemm_bf<128><<<dim3(16, 8, 3), 128, SM128>>>(pYh, pYl, pWfh, pWfl, pDV, nullptr, nullptr, nullptr,
        C_FF, C_FF, C_FF, C_FF, NP_FF, 0, 0, 0, NP_FF, 0, 1, 1, 0, 0);
    k_gate<<<2048, 256>>>();
    gemm_bf<128><<<dim3(4, 8, 3), 128, SM128>>>(pY2h, pY2l, pW2h, pW2l, pY3, pX1, nullptr, nullptr,
        C_FF, C_FF, C_D, C_FF, NP_FF, 0, 0, 0, NP_D, 0, 1, 1, C_D, NP_D);

    // 12) vn_ln #2 -> interleaved (n, c*3+x) output
    k_vnln<<<C_N, 256>>>(pY3, (float*)d_out, nullptr, nullptr, n2_g, n2_b, 1);
}

// round 13
// speedup vs baseline: 1.1088x; 1.0311x over previous
#include <cuda_runtime.h>
#include <cuda_bf16.h>
#include <math.h>
#include <stdint.h>

// ---------------- problem constants ----------------
#define C_N   1024
#define C_K   16
#define C_D   512
#define C_H   8
#define C_FF  2048
#define C_MA  64
#define C_ES  64
#define C_E   (C_N * C_K)      // 16384
#define C_EPS 1e-6f

typedef __nv_bfloat16 bf16;

// ---------------- fp32 scratch ----------------
__device__ float g_TV  [3][C_N][C_D];
__device__ float g_MSG [3][C_E][C_D];
__device__ float g_w   [C_E][3*C_D];
__device__ float g_PV  [3][C_E][C_D];
__device__ float g_araw[C_E][C_MA];
__device__ float g_att [C_E][C_H];
__device__ float g_X1  [3][C_N][C_D];
__device__ float g_Y   [3][C_N][C_FF];
// split-K partial buffers
__device__ float g_PRJP[2][3][C_N][C_D];
__device__ float g_FF2P[4][3][C_N][C_D];
__device__ float g_DVP [2][3][C_N][C_FF];

// ---------------- bf16 hi/lo pairs (GEMM operands) ----------------
__device__ __align__(128) bf16 g_Tb_h [3][C_N][C_D],        g_Tb_l [3][C_N][C_D];
__device__ __align__(128) bf16 g_Mb_h [3][C_E][C_D],        g_Mb_l [3][C_E][C_D];
__device__ __align__(128) bf16 g_pscb_h[C_E][C_D],          g_pscb_l[C_E][C_D];
__device__ __align__(128) bf16 g_Zb_h [3][C_N][C_H][C_D],   g_Zb_l [3][C_N][C_H][C_D];
__device__ __align__(128) bf16 g_OUTb_h[3][C_N][C_D],       g_OUTb_l[3][C_N][C_D];
__device__ __align__(128) bf16 g_X1b_h[3][C_N][C_D],        g_X1b_l[3][C_N][C_D];
__device__ __align__(128) bf16 g_Yb_h [3][C_N][C_FF],       g_Yb_l [3][C_N][C_FF];
__device__ __align__(128) bf16 g_Y2b_h[3][C_N][C_FF],       g_Y2b_l[3][C_N][C_FF];
// weights
__device__ __align__(128) bf16 g_Wsrc_h[C_D*C_D],  g_Wsrc_l[C_D*C_D];
__device__ __align__(128) bf16 g_Wdst_h[C_D*C_D],  g_Wdst_l[C_D*C_D];
__device__ __align__(128) bf16 g_Wa_h  [C_MA*C_D], g_Wa_l  [C_MA*C_D];
__device__ __align__(128) bf16 g_Wv_h  [C_D*C_D],  g_Wv_l  [C_D*C_D];
__device__ __align__(128) bf16 g_Wp_h  [C_D*C_D],  g_Wp_l  [C_D*C_D];
__device__ __align__(128) bf16 g_Wf1_h [C_FF*C_D], g_Wf1_l [C_FF*C_D];
__device__ __align__(128) bf16 g_Wfd_h [C_FF*C_FF],g_Wfd_l [C_FF*C_FF];
__device__ __align__(128) bf16 g_Wf2_h [C_D*C_FF], g_Wf2_l [C_D*C_FF];

// ---------------- helpers ----------------
__device__ __forceinline__ void bsplit(float v, bf16* H, bf16* L, long i) {
    bf16 h = __float2bfloat16_rn(v);
    H[i] = h;
    L[i] = __float2bfloat16_rn(v - __bfloat162float(h));
}
__device__ __forceinline__ void bsplit2(float v0, float v1, bf16* H, bf16* L, long i) {
    bf16 h0 = __float2bfloat16_rn(v0), h1 = __float2bfloat16_rn(v1);
    *(__nv_bfloat162*)(H + i) = __nv_bfloat162(h0, h1);
    *(__nv_bfloat162*)(L + i) = __nv_bfloat162(
        __float2bfloat16_rn(v0 - __bfloat162float(h0)),
        __float2bfloat16_rn(v1 - __bfloat162float(h1)));
}
__device__ __forceinline__ uint32_t s2u(const void* p) {
    uint32_t a;
    asm("{ .reg .u64 t; cvta.to.shared.u64 t, %1; cvt.u32.u64 %0, t; }" : "=r"(a) : "l"(p));
    return a;
}
__device__ __forceinline__ void mma_bf16(float* c, const uint32_t* a, const uint32_t* b) {
    asm volatile("mma.sync.aligned.m16n8k16.row.col.f32.bf16.bf16.f32 "
                 "{%0,%1,%2,%3},{%4,%5,%6,%7},{%8,%9},{%0,%1,%2,%3};"
                 : "+f"(c[0]), "+f"(c[1]), "+f"(c[2]), "+f"(c[3])
                 : "r"(a[0]), "r"(a[1]), "r"(a[2]), "r"(a[3]), "r"(b[0]), "r"(b[1]));
}
__device__ __forceinline__ void ldsm4(uint32_t* r, uint32_t addr) {
    asm volatile("ldmatrix.sync.aligned.m8n8.x4.shared.b16 {%0,%1,%2,%3}, [%4];"
        : "=r"(r[0]), "=r"(r[1]), "=r"(r[2]), "=r"(r[3]) : "r"(addr));
}
#define CPA(d, s) asm volatile("cp.async.cg.shared.global [%0], [%1], 16;" :: "r"(d), "l"(s) : "memory")
#define CPC()     asm volatile("cp.async.commit_group;" ::: "memory")
#define CPW(n)    asm volatile("cp.async.wait_group %0;" :: "n"(n) : "memory")

// ============ bf16-pair NT GEMM: C[m,n] = sum_k A[m,k]*B[n,k] (+Add) ============
// 128xBN CTA tile, 128 threads (4 warps, 64x(BN/2) warp tiles), 2-stage cp.async,
// ldmatrix fragments, 3 HMMA passes (hh+hl+lh). Optional split-K: grid.z =
// nzTot*nsplit; each split writes its own partial buffer at C + sk*sCk.
// M%128==0, N%BN==0, K%(32*nsplit)==0.
template<int BN>
__global__ void __launch_bounds__(128, 2) gemm_bf(
    const bf16* __restrict__ Ah, const bf16* __restrict__ Al,
    const bf16* __restrict__ Bh, const bf16* __restrict__ Bl,
    float* __restrict__ C, const float* __restrict__ Add,
    bf16* __restrict__ CbH, bf16* __restrict__ CbL,
    int lda, int ldb, int ldc, int Kc,
    long sA1, long sA2, long sB1, long sB2, long sC1, long sC2, int nz2,
    int addDiv, int ldadd, long sAdd1,
    int nsplit, int nzTot, long sCk)
{
    constexpr int WN   = BN / 2;
    constexpr int NSUB = WN / 8;
    constexpr int ABY  = 10240;          // 128 rows x 80B
    constexpr int BBY  = BN * 80;
    constexpr int STG  = 2 * ABY + 2 * BBY;

    extern __shared__ __align__(16) char sm[];
    const int t = threadIdx.x, wid = t >> 5, lane = t & 31;
    const int g = lane >> 2, tq = lane & 3;
    const int wm = wid & 1, wn = wid >> 1;

    const int bz = blockIdx.z;
    const int sk = bz / nzTot;
    const int z  = bz - sk * nzTot;
    const int z1 = z / nz2, z2 = z - z1 * nz2;
    const int nchAll = Kc >> 5;
    const int nch = nchAll / nsplit;
    const long kOff = (long)sk * nch * 32;

    const long m0 = (long)blockIdx.y * 128, n0 = (long)blockIdx.x * BN;
    const bf16* Agh = Ah + z1 * sA1 + z2 * sA2 + m0 * lda + kOff;
    const bf16* Agl = Al + z1 * sA1 + z2 * sA2 + m0 * lda + kOff;
    const bf16* Bgh = Bh + z1 * sB1 + z2 * sB2 + n0 * ldb + kOff;
    const bf16* Bgl = Bl + z1 * sB1 + z2 * sB2 + n0 * ldb + kOff;

    const uint32_t smb = s2u(sm);
    const int crow = t >> 2, cseg = t & 3;

    const int lm = lane >> 3, lr = lane & 7;
    const int a_off0 = (wm * 64 + (lm & 1) * 8 + lr) * 80 + (lm >> 1) * 16;
    const int b_off0 = (wn * WN + (lm >> 1) * 8 + lr) * 80 + (lm & 1) * 16;

    float acc[4][NSUB][4];
#pragma unroll
    for (int mi = 0; mi < 4; mi++)
#pragma unroll
        for (int ni = 0; ni < NSUB; ni++)
#pragma unroll
            for (int j = 0; j < 4; j++) acc[mi][ni][j] = 0.f;

    // prologue: issue chunk 0
    {
        const uint32_t st = smb;
#pragma unroll
        for (int i = 0; i < 4; i++) {
            int row = crow + i * 32;
            uint32_t d = st + row * 80 + cseg * 16;
            CPA(d,       Agh + (long)row * lda + cseg * 8);
            CPA(d + ABY, Agl + (long)row * lda + cseg * 8);
        }
#pragma unroll
        for (int i = 0; i < BN / 32; i++) {
            int row = crow + i * 32;
            uint32_t d = st + 2 * ABY + row * 80 + cseg * 16;
            CPA(d,       Bgh + (long)row * ldb + cseg * 8);
            CPA(d + BBY, Bgl + (long)row * ldb + cseg * 8);
        }
        CPC();
    }

    for (int ch = 0; ch < nch; ch++) {
        if (ch + 1 < nch) {
            const uint32_t st = smb + ((ch + 1) & 1) * STG;
            const bf16* ah = Agh + (ch + 1) * 32;
            const bf16* al = Agl + (ch + 1) * 32;
            const bf16* bh = Bgh + (ch + 1) * 32;
            const bf16* bl = Bgl + (ch + 1) * 32;
#pragma unroll
            for (int i = 0; i < 4; i++) {
                int row = crow + i * 32;
                uint32_t d = st + row * 80 + cseg * 16;
                CPA(d,       ah + (long)row * lda + cseg * 8);
                CPA(d + ABY, al + (long)row * lda + cseg * 8);
            }
#pragma unroll
            for (int i = 0; i < BN / 32; i++) {
                int row = crow + i * 32;
                uint32_t d = st + 2 * ABY + row * 80 + cseg * 16;
                CPA(d,       bh + (long)row * ldb + cseg * 8);
                CPA(d + BBY, bl + (long)row * ldb + cseg * 8);
            }
            CPC();
            CPW(1);
        } else {
            CPW(0);
        }
        __syncthreads();

        const uint32_t sbase = smb + (ch & 1) * STG;
#pragma unroll
        for (int ks = 0; ks < 2; ks++) {
            const int ko = ks * 32;
            uint32_t fa[16], fbh[2 * NSUB], fbl[2 * NSUB];
            const uint32_t abase = sbase + a_off0 + ko;
            const uint32_t bbase = sbase + 2 * ABY + b_off0 + ko;
#pragma unroll
            for (int mi = 0; mi < 4; mi++) ldsm4(&fa[mi * 4], abase + mi * 1280);
#pragma unroll
            for (int np = 0; np < NSUB / 2; np++) ldsm4(&fbh[np * 4], bbase + np * 1280);
#pragma unroll
            for (int mi = 0; mi < 4; mi++)
#pragma unroll
                for (int ni = 0; ni < NSUB; ni++)
                    mma_bf16(acc[mi][ni], &fa[mi * 4], &fbh[ni * 2]);   // hi*hi
#pragma unroll
            for (int np = 0; np < NSUB / 2; np++) ldsm4(&fbl[np * 4], bbase + BBY + np * 1280);
#pragma unroll
            for (int mi = 0; mi < 4; mi++)
#pragma unroll
                for (int ni = 0; ni < NSUB; ni++)
                    mma_bf16(acc[mi][ni], &fa[mi * 4], &fbl[ni * 2]);   // hi*lo
#pragma unroll
            for (int mi = 0; mi < 4; mi++) ldsm4(&fa[mi * 4], abase + ABY + mi * 1280);
#pragma unroll
            for (int mi = 0; mi < 4; mi++)
#pragma unroll
                for (int ni = 0; ni < NSUB; ni++)
                    mma_bf16(acc[mi][ni], &fa[mi * 4], &fbh[ni * 2]);   // lo*hi
        }
        __syncthreads();
    }

    // ---- epilogue ----
    float* Cp = C ? (C + sk * sCk + z1 * sC1 + z2 * sC2) : (float*)0;
    bf16* Ch = CbH ? (CbH + z1 * sC1 + z2 * sC2) : (bf16*)0;
    bf16* Cl = CbL ? (CbL + z1 * sC1 + z2 * sC2) : (bf16*)0;
    const float* Ad = Add ? (Add + z1 * sAdd1) : (const float*)0;
#pragma unroll
    for (int mi = 0; mi < 4; mi++) {
        long r0 = m0 + wm * 64 + mi * 16 + g;
#pragma unroll
        for (int ni = 0; ni < NSUB; ni++) {
            long col = n0 + wn * WN + ni * 8 + tq * 2;
            float2 v0 = make_float2(acc[mi][ni][0], acc[mi][ni][1]);
            float2 v1 = make_float2(acc[mi][ni][2], acc[mi][ni][3]);
            if (Ad) {
                float2 a0 = *(const float2*)(Ad + (r0 / addDiv) * (long)ldadd + col);
                float2 a1 = *(const float2*)(Ad + ((r0 + 8) / addDiv) * (long)ldadd + col);
                v0.x += a0.x; v0.y += a0.y; v1.x += a1.x; v1.y += a1.y;
            }
            if (Cp) {
                *(float2*)(Cp + r0 * ldc + col) = v0;
                *(float2*)(Cp + (r0 + 8) * ldc + col) = v1;
            }
            if (Ch) {
                long i0 = r0 * ldc + col, i1 = (r0 + 8) * ldc + col;
                bsplit2(v0.x, v0.y, Ch, Cl, i0);
                bsplit2(v1.x, v1.y, Ch, Cl, i1);
            }
        }
    }
}

// ---------------- input transpose + bf16 split (vectorized) ----------------
__global__ void k_split_in(const float* __restrict__ tgt, const float* __restrict__ mem)
{
    long stride = (long)gridDim.x * blockDim.x;
    long base   = (long)blockIdx.x * blockDim.x + threadIdx.x;
    for (long p = base; p < (long)C_N * C_D / 2; p += stride) {
        const float* s = tgt + 6 * p;
        float2 a = *(const float2*)s, b = *(const float2*)(s + 2), c = *(const float2*)(s + 4);
        bsplit2(a.x, b.y, &g_Tb_h[0][0][0], &g_Tb_l[0][0][0], 2 * p);
        bsplit2(a.y, c.x, &g_Tb_h[1][0][0], &g_Tb_l[1][0][0], 2 * p);
        bsplit2(b.x, c.y, &g_Tb_h[2][0][0], &g_Tb_l[2][0][0], 2 * p);
    }
    for (long p = base; p < (long)C_E * C_D / 2; p += stride) {
        const float* s = mem + 6 * p;
        float2 a = *(const float2*)s, b = *(const float2*)(s + 2), c = *(const float2*)(s + 4);
        bsplit2(a.x, b.y, &g_Mb_h[0][0][0], &g_Mb_l[0][0][0], 2 * p);
        bsplit2(a.y, c.x, &g_Mb_h[1][0][0], &g_Mb_l[1][0][0], 2 * p);
        bsplit2(b.x, c.y, &g_Mb_h[2][0][0], &g_Mb_l[2][0][0], 2 * p);
    }
}

// ---------------- all weight splits in one kernel ----------------
__global__ void k_split_all(
    const float* __restrict__ Wsrc, const float* __restrict__ Wdst,
    const float* __restrict__ Wv,   const float* __restrict__ Wp,
    const float* __restrict__ Wf1,  const float* __restrict__ Wfd,
    const float* __restrict__ Wf2,  const float* __restrict__ Wa)
{
    const long SQ = (long)C_D * C_D;
    const long O4 = 4 * SQ;
    const long O5 = O4 + (long)C_FF * C_D;
    const long O6 = O5 + (long)C_FF * C_FF;
    const long O7 = O6 + (long)C_D * C_FF;
    const long O8 = O7 + (long)C_MA * C_D;
    long stride = (long)gridDim.x * blockDim.x;
    for (long i = (long)blockIdx.x * blockDim.x + threadIdx.x; i < O8; i += stride) {
        if (i < SQ)            bsplit(Wsrc[i],      g_Wsrc_h, g_Wsrc_l, i);
        else if (i < 2 * SQ)   bsplit(Wdst[i - SQ], g_Wdst_h, g_Wdst_l, i - SQ);
        else if (i < 3 * SQ)   bsplit(Wv[i - 2*SQ], g_Wv_h,   g_Wv_l,   i - 2*SQ);
        else if (i < 4 * SQ)   bsplit(Wp[i - 3*SQ], g_Wp_h,   g_Wp_l,   i - 3*SQ);
        else if (i < O5)       bsplit(Wf1[i - O4],  g_Wf1_h,  g_Wf1_l,  i - O4);
        else if (i < O6)       bsplit(Wfd[i - O5],  g_Wfd_h,  g_Wfd_l,  i - O5);
        else if (i < O7)       bsplit(Wf2[i - O6],  g_Wf2_h,  g_Wf2_l,  i - O6);
        else {
            long k = i - O7;
            long r = k >> 6, c = k & 63;
            bsplit(Wa[k], g_Wa_h, g_Wa_l, c * C_D + r);
        }
    }
}

// ---------------- fused edge MLP ----------------
__global__ void __launch_bounds__(256) k_mlp(
    const float* __restrict__ es, const float* __restrict__ w1, const float* __restrict__ b1,
    const float* __restrict__ w2, const float* __restrict__ b2,
    const float* __restrict__ w3, const float* __restrict__ b3)
{
    __shared__ float s_es[64][65];
    __shared__ float s_w1[64][32];
    __shared__ float s_w2[32][32];
    __shared__ float s_h1[64][33];
    __shared__ float s_h2[64][33];
    const int t = threadIdx.x;
    const long e0 = (long)blockIdx.x * 64;

    for (int i = t; i < 64 * 32; i += 256) s_w1[i >> 5][i & 31] = w1[i];
    for (int i = t; i < 32 * 32; i += 256) s_w2[i >> 5][i & 31] = w2[i];
    for (int i = t; i < 64 * 64; i += 256) s_es[i >> 6][i & 63] = es[e0 * 64 + i];
    __syncthreads();

    for (int i = t; i < 64 * 32; i += 256) {
        int e = i >> 5, j = i & 31;
        float acc = b1[j];
#pragma unroll 8
        for (int c = 0; c < 64; c++) acc = fmaf(s_es[e][c], s_w1[c][j], acc);
        s_h1[e][j] = acc / (1.f + expf(-acc));
    }
    __syncthreads();
    for (int i = t; i < 64 * 32; i += 256) {
        int e = i >> 5, j = i & 31;
        float acc = b2[j];
#pragma unroll 8
        for (int c = 0; c < 32; c++) acc = fmaf(s_h1[e][c], s_w2[c][j], acc);
        s_h2[e][j] = acc / (1.f + expf(-acc));
    }
    __syncthreads();
    for (int i = t; i < 64 * 1536; i += 256) {
        int e = i / 1536, o = i - e * 1536;
        float acc = b3[o];
#pragma unroll 8
        for (int c = 0; c < 32; c++) acc = fmaf(s_h2[e][c], w3[c * 1536 + o], acc);
        g_w[e0 + e][o] = acc;
    }
}

// ---------------- pointwise equivariant products (vectorized) ----------------
__global__ void k_pointwise(const float* __restrict__ esh)
{
    long stride = (long)gridDim.x * blockDim.x;
    for (long p = (long)blockIdx.x * blockDim.x + threadIdx.x; p < (long)C_E * C_D / 2; p += stride) {
        int  c = (int)(p & 255) * 2;
        long e = p >> 8;
        float s  = esh[e * 4 + 0];
        float v0 = esh[e * 4 + 1], v1 = esh[e * 4 + 2], v2 = esh[e * 4 + 3];
        float2 m0 = *(const float2*)&g_MSG[0][e][c];
        float2 m1 = *(const float2*)&g_MSG[1][e][c];
        float2 m2 = *(const float2*)&g_MSG[2][e][c];
        float2 w0 = *(const float2*)&g_w[e][c];
        float2 w1 = *(const float2*)&g_w[e][512 + c];
        float2 w2 = *(const float2*)&g_w[e][1024 + c];
        float p0 = w0.x * (m0.x * v0 + m1.x * v1 + m2.x * v2) * 0.5773502691896258f;
        float p1 = w0.y * (m0.y * v0 + m1.y * v1 + m2.y * v2) * 0.5773502691896258f;
        bsplit2(p0, p1, &g_pscb_h[0][0], &g_pscb_l[0][0], e * C_D + c);
        float k2x = w2.x * 0.7071067811865475f, k2y = w2.y * 0.7071067811865475f;
        float wsx = w1.x * s, wsy = w1.y * s;
        *(float2*)&g_PV[0][e][c] = make_float2(wsx * m0.x + k2x * (m1.x * v2 - m2.x * v1),
                                               wsy * m0.y + k2y * (m1.y * v2 - m2.y * v1));
        *(float2*)&g_PV[1][e][c] = make_float2(wsx * m1.x + k2x * (m2.x * v0 - m0.x * v2),
                                               wsy * m1.y + k2y * (m2.y * v0 - m0.y * v2));
        *(float2*)&g_PV[2][e][c] = make_float2(wsx * m2.x + k2x * (m0.x * v1 - m1.x * v0),
                                               wsy * m2.y + k2y * (m0.y * v1 - m1.y * v0));
    }
}

// ---------------- fused alpha post (LN + lrelu + head dot) + softmax over K ----------------
__global__ void __launch_bounds__(512) k_alpha(const float* __restrict__ gg, const float* __restrict__ bb,
                                               const float* __restrict__ adot)
{
    int n = blockIdx.x;
    int t = threadIdx.x, wid = t >> 5, lane = t & 31;
    __shared__ float s_l[16][8];
    int e = n * 16 + wid;
    float v0 = g_araw[e][lane * 2], v1 = g_araw[e][lane * 2 + 1];
    float s = v0 + v1, s2 = v0 * v0 + v1 * v1;
#pragma unroll
    for (int o = 16; o > 0; o >>= 1) {
        s  += __shfl_xor_sync(0xffffffffu, s, o);
        s2 += __shfl_xor_sync(0xffffffffu, s2, o);
    }
    float mu  = s * (1.f / 64.f);
    float var = s2 * (1.f / 64.f) - mu * mu;
    float inv = rsqrtf(var + C_EPS);
    float a0 = (v0 - mu) * inv * gg[lane * 2]     + bb[lane * 2];
    float a1 = (v1 - mu) * inv * gg[lane * 2 + 1] + bb[lane * 2 + 1];
    a0 = 0.6f * a0 + 0.4f * a0 * tanhf(0.5f * a0);
    a1 = 0.6f * a1 + 0.4f * a1 * tanhf(0.5f * a1);
    int h = lane >> 2;
    int m = (lane & 3) * 2;
    float p = a0 * adot[h * 8 + m] + a1 * adot[h * 8 + m + 1];
    p += __shfl_xor_sync(0xffffffffu, p, 1);
    p += __shfl_xor_sync(0xffffffffu, p, 2);
    if ((lane & 3) == 0) s_l[wid][h] = p;
    __syncthreads();
    if (t < 8) {
        float mx = -1e30f;
#pragma unroll
        for (int k = 0; k < 16; k++) mx = fmaxf(mx, s_l[k][t]);
        float sum = 0.f; float ex[16];
#pragma unroll
        for (int k = 0; k < 16; k++) { ex[k] = expf(s_l[k][t] - mx); sum += ex[k]; }
        float is = 1.f / sum;
#pragma unroll
        for (int k = 0; k < 16; k++) g_att[n * 16 + k][t] = ex[k] * is;
    }
}

// ---------------- z = sum_k att * pv (vectorized bf16-pair output) ----------------
__global__ void __launch_bounds__(256) k_z()
{
    int n = blockIdx.x, x = blockIdx.y;
    __shared__ float s_a[16][8];
    if (threadIdx.x < 128)
        s_a[threadIdx.x >> 3][threadIdx.x & 7] = g_att[n * 16 + (threadIdx.x >> 3)][threadIdx.x & 7];
    __syncthreads();
    int c = threadIdx.x * 2;
    float2 acc[8];
#pragma unroll
    for (int h = 0; h < 8; h++) acc[h] = make_float2(0.f, 0.f);
#pragma unroll
    for (int k = 0; k < 16; k++) {
        float2 pv = *(const float2*)&g_PV[x][n * 16 + k][c];
#pragma unroll
        for (int h = 0; h < 8; h++) {
            acc[h].x = fmaf(s_a[k][h], pv.x, acc[h].x);
            acc[h].y = fmaf(s_a[k][h], pv.y, acc[h].y);
        }
    }
#pragma unroll
    for (int h = 0; h < 8; h++) {
        long idx = (((long)x * C_N + n) * C_H + h) * C_D + c;
        bsplit2(acc[h].x, acc[h].y, &g_Zb_h[0][0][0][0], &g_Zb_l[0][0][0][0], idx);
    }
}

// ---------------- vn_ln with fused split-K partial reduction ----------------
// Xin (base term) + sum of nparts partials (stride pstride), LN, output.
__global__ void __launch_bounds__(256) k_vnln(const float* __restrict__ Xin,
                                              const float* __restrict__ Parts, int nparts, long pstride,
                                              float* __restrict__ Xout,
                                              bf16* __restrict__ bH, bf16* __restrict__ bL,
                                              const float* __restrict__ gg, const float* __restrict__ bb,
                                              int inter)
{
    int n = blockIdx.x, t = threadIdx.x;
    const long P = (long)C_N * C_D;
    __shared__ float rs[8], rs2[8];
    __shared__ float smu, sinv;
    float xv[2][3], nc[2];
    float s = 0.f, s2 = 0.f;
#pragma unroll
    for (int i = 0; i < 2; i++) {
        int c = t * 2 + i;
#pragma unroll
        for (int xx = 0; xx < 3; xx++) {
            long idx = xx * P + (long)n * C_D + c;
            float v = Xin[idx];
            for (int pp = 0; pp < nparts; pp++) v += Parts[pp * pstride + idx];
            xv[i][xx] = v;
        }
        float v = sqrtf(xv[i][0] * xv[i][0] + xv[i][1] * xv[i][1] + xv[i][2] * xv[i][2] + C_EPS);
        nc[i] = v; s += v; s2 = fmaf(v, v, s2);
    }
#pragma unroll
    for (int o = 16; o > 0; o >>= 1) {
        s  += __shfl_xor_sync(0xffffffffu, s, o);
        s2 += __shfl_xor_sync(0xffffffffu, s2, o);
    }
    if ((t & 31) == 0) { rs[t >> 5] = s; rs2[t >> 5] = s2; }
    __syncthreads();
    if (t == 0) {
        float S = 0.f, S2 = 0.f;
        for (int i = 0; i < 8; i++) { S += rs[i]; S2 += rs2[i]; }
        float mu  = S * (1.f / 512.f);
        float var = S2 * (1.f / 512.f) - mu * mu;
        smu = mu; sinv = rsqrtf(var + C_EPS);
    }
    __syncthreads();
    float sc[2];
#pragma unroll
    for (int i = 0; i < 2; i++) {
        int c = t * 2 + i;
        float ln = (nc[i] - smu) * sinv * gg[c] + bb[c];
        sc[i] = ln / nc[i];
    }
    if (inter) {
#pragma unroll
        for (int i = 0; i < 2; i++) {
            int c = t * 2 + i;
#pragma unroll
            for (int xx = 0; xx < 3; xx++) Xout[(long)n * 1536 + c * 3 + xx] = xv[i][xx] * sc[i];
        }
    } else {
#pragma unroll
        for (int xx = 0; xx < 3; xx++) {
            long idx = xx * P + (long)n * C_D + t * 2;
            float o0 = xv[0][xx] * sc[0], o1 = xv[1][xx] * sc[1];
            *(float2*)(Xout + idx) = make_float2(o0, o1);
            if (bH) bsplit2(o0, o1, bH, bL, idx);
        }
    }
}

// ---------------- FF gating with fused DV partial reduction ----------------
__global__ void k_gate()
{
    const long P = (long)C_N * C_FF;
    const float* Y  = &g_Y[0][0][0];
    const float* D0 = &g_DVP[0][0][0][0];
    const float* D1 = &g_DVP[1][0][0][0];
    long stride = (long)gridDim.x * blockDim.x;
    for (long p = (long)blockIdx.x * blockDim.x + threadIdx.x; p < P / 2; p += stride) {
        long i = 2 * p;
        float2 y0 = *(const float2*)(Y + i), y1 = *(const float2*)(Y + P + i), y2 = *(const float2*)(Y + 2 * P + i);
        float2 a0 = *(const float2*)(D0 + i), a1 = *(const float2*)(D0 + P + i), a2 = *(const float2*)(D0 + 2 * P + i);
        float2 b0 = *(const float2*)(D1 + i), b1 = *(const float2*)(D1 + P + i), b2 = *(const float2*)(D1 + 2 * P + i);
        float2 d0 = make_float2(a0.x + b0.x, a0.y + b0.y);
        float2 d1 = make_float2(a1.x + b1.x, a1.y + b1.y);
        float2 d2 = make_float2(a2.x + b2.x, a2.y + b2.y);
        float dotx = y0.x * d0.x + y1.x * d1.x + y2.x * d2.x;
        float doty = y0.y * d0.y + y1.y * d1.y + y2.y * d2.y;
        float fx = (dotx >= 0.f) ? 0.f : 0.8f * dotx / (d0.x * d0.x + d1.x * d1.x + d2.x * d2.x + C_EPS);
        float fy = (doty >= 0.f) ? 0.f : 0.8f * doty / (d0.y * d0.y + d1.y * d1.y + d2.y * d2.y + C_EPS);
        bsplit2(y0.x - fx * d0.x, y0.y - fy * d0.y, &g_Y2b_h[0][0][0], &g_Y2b_l[0][0][0], i);
        bsplit2(y1.x - fx * d1.x, y1.y - fy * d1.y, &g_Y2b_h[0][0][0], &g_Y2b_l[0][0][0], P + i);
        bsplit2(y2.x - fx * d2.x, y2.y - fy * d2.y, &g_Y2b_h[0][0][0], &g_Y2b_l[0][0][0], 2 * P + i);
    }
}

// ---------------- host launch ----------------
extern "C" void kernel_launch(void* const* d_in, const int* in_sizes, int n_in,
                              void* d_out, int out_size)
{
    const float* tgt    = (const float*)d_in[0];
    const float* mem    = (const float*)d_in[1];
    const float* esh    = (const float*)d_in[2];
    const float* escal  = (const float*)d_in[3];
    const float* W_src  = (const float*)d_in[4];
    const float* W_dst  = (const float*)d_in[5];
    const float* fc_w1  = (const float*)d_in[6];
    const float* fc_b1  = (const float*)d_in[7];
    const float* fc_w2  = (const float*)d_in[8];
    const float* fc_b2  = (const float*)d_in[9];
    const float* fc_w3  = (const float*)d_in[10];
    const float* fc_b3  = (const float*)d_in[11];
    const float* W_alpha= (const float*)d_in[12];
    const float* ln_a_g = (const float*)d_in[13];
    const float* ln_a_b = (const float*)d_in[14];
    const float* adot   = (const float*)d_in[15];
    const float* W_value= (const float*)d_in[16];
    const float* W_proj = (const float*)d_in[17];
    const float* n1_g   = (const float*)d_in[18];
    const float* n1_b   = (const float*)d_in[19];
    const float* n2_g   = (const float*)d_in[20];
    const float* n2_b   = (const float*)d_in[21];
    const float* W_ff1  = (const float*)d_in[22];
    const float* W_ffd  = (const float*)d_in[23];
    const float* W_ff2  = (const float*)d_in[24];

#define SYM(p, s) cudaGetSymbolAddress((void**)&p, s)
    float *pTV, *pMSG, *paraw, *pX1, *pY, *pPRJ, *pFF2, *pDVP;
    SYM(pTV, g_TV); SYM(pMSG, g_MSG); SYM(paraw, g_araw);
    SYM(pX1, g_X1); SYM(pY, g_Y);
    SYM(pPRJ, g_PRJP); SYM(pFF2, g_FF2P); SYM(pDVP, g_DVP);
    bf16 *pTbh, *pTbl, *pMbh, *pMbl, *ppsh, *ppsl, *pZh, *pZl, *pOh, *pOl;
    bf16 *pX1h, *pX1l, *pYh, *pYl, *pY2h, *pY2l;
    SYM(pTbh, g_Tb_h); SYM(pTbl, g_Tb_l); SYM(pMbh, g_Mb_h); SYM(pMbl, g_Mb_l);
    SYM(ppsh, g_pscb_h); SYM(ppsl, g_pscb_l); SYM(pZh, g_Zb_h); SYM(pZl, g_Zb_l);
    SYM(pOh, g_OUTb_h); SYM(pOl, g_OUTb_l); SYM(pX1h, g_X1b_h); SYM(pX1l, g_X1b_l);
    SYM(pYh, g_Yb_h); SYM(pYl, g_Yb_l); SYM(pY2h, g_Y2b_h); SYM(pY2l, g_Y2b_l);
    bf16 *pWsh, *pWsl, *pWdh, *pWdl, *pWah, *pWal, *pWvh, *pWvl, *pWph, *pWpl;
    bf16 *pW1h, *pW1l, *pWfh, *pWfl, *pW2h, *pW2l;
    SYM(pWsh, g_Wsrc_h); SYM(pWsl, g_Wsrc_l); SYM(pWdh, g_Wdst_h); SYM(pWdl, g_Wdst_l);
    SYM(pWah, g_Wa_h); SYM(pWal, g_Wa_l); SYM(pWvh, g_Wv_h); SYM(pWvl, g_Wv_l);
    SYM(pWph, g_Wp_h); SYM(pWpl, g_Wp_l); SYM(pW1h, g_Wf1_h); SYM(pW1l, g_Wf1_l);
    SYM(pWfh, g_Wfd_h); SYM(pWfl, g_Wfd_l); SYM(pW2h, g_Wf2_h); SYM(pW2l, g_Wf2_l);
#undef SYM

    const long NP_D  = (long)C_N * C_D;
    const long EP_D  = (long)C_E * C_D;
    const long NP_FF = (long)C_N * C_FF;
    const long NHD   = (long)C_N * C_H * C_D;

    const int SM128 = 2 * (2 * 10240 + 2 * 128 * 80);   // 81920
    const int SM64  = 2 * (2 * 10240 + 2 * 64 * 80);    // 61440
    cudaFuncSetAttribute(gemm_bf<128>, cudaFuncAttributeMaxDynamicSharedMemorySize, SM128);
    cudaFuncSetAttribute(gemm_bf<64>,  cudaFuncAttributeMaxDynamicSharedMemorySize, SM64);

    // 1) input + weight splits
    k_split_in<<<4096, 256>>>(tgt, mem);
    k_split_all<<<8192, 256>>>(W_src, W_dst, W_value, W_proj, W_ff1, W_ffd, W_ff2, W_alpha);

    // 2) tv = W_dst @ tgt
    gemm_bf<128><<<dim3(4, 8, 3), 128, SM128>>>(pTbh, pTbl, pWdh, pWdl, pTV, nullptr, nullptr, nullptr,
        C_D, C_D, C_D, C_D, NP_D, 0, 0, 0, NP_D, 0, 1, 1, 0, 0, 1, 3, 0);

    // 3) msg = W_src @ memory + tv[e/K]
    gemm_bf<128><<<dim3(4, 128, 3), 128, SM128>>>(pMbh, pMbl, pWsh, pWsl, pMSG, pTV, nullptr, nullptr,
        C_D, C_D, C_D, C_D, EP_D, 0, 0, 0, EP_D, 0, 1, C_K, C_D, NP_D, 1, 3, 0);

    // 4) edge MLP -> g_w
    k_mlp<<<C_E / 64, 256>>>(escal, fc_w1, fc_b1, fc_w2, fc_b2, fc_w3, fc_b3);

    // 5) p_sc / pv
    k_pointwise<<<2048, 256>>>(esh);

    // 6) a_raw = p_sc @ W_alpha
    gemm_bf<64><<<dim3(1, 128, 1), 128, SM64>>>(ppsh, ppsl, pWah, pWal, paraw, nullptr, nullptr, nullptr,
        C_D, C_D, C_MA, C_D, 0, 0, 0, 0, 0, 0, 1, 1, 0, 0, 1, 1, 0);

    // 7) fused LN + lrelu + head dot + softmax
    k_alpha<<<C_N, 512>>>(ln_a_g, ln_a_b, adot);

    // 8) z = sum_k att * pv
    k_z<<<dim3(C_N, 3), 256>>>();

    // 9) out = W_value @ z (per head, bf16 out), then proj (split-K=2, partials)
    gemm_bf<64><<<dim3(1, 8, 24), 128, SM64>>>(pZh, pZl, pWvh, pWvl, nullptr, nullptr, pOh, pOl,
        C_H * C_D, C_D, C_D, C_D, NHD, C_D, 0, 64 * C_D, NP_D, 64, C_H, 1, 0, 0, 1, 24, 0);
    gemm_bf<128><<<dim3(4, 8, 6), 128, SM128>>>(pOh, pOl, pWph, pWpl, pPRJ, nullptr, nullptr, nullptr,
        C_D, C_D, C_D, C_D, NP_D, 0, 0, 0, NP_D, 0, 1, 1, 0, 0, 2, 3, 3 * NP_D);

    // 10) vn_ln #1: X1 = vn_ln(tv + proj partials)
    k_vnln<<<C_N, 256>>>(pTV, pPRJ, 2, 3 * NP_D, pX1, pX1h, pX1l, n1_g, n1_b, 0);

    // 11) FF block
    gemm_bf<128><<<dim3(16, 8, 3), 128, SM128>>>(pX1h, pX1l, pW1h, pW1l, pY, nullptr, pYh, pYl,
        C_D, C_D, C_FF, C_D, NP_D, 0, 0, 0, NP_FF, 0, 1, 1, 0, 0, 1, 3, 0);
    // ffd split-K=2 -> DV partials
    gemm_bf<128><<<dim3(16, 8, 6), 128, SM128>>>(pYh, pYl, pWfh, pWfl, pDVP, nullptr, nullptr, nullptr,
        C_FF, C_FF, C_FF, C_FF, NP_FF, 0, 0, 0, NP_FF, 0, 1, 1, 0, 0, 2, 3, 3 * NP_FF);
    k_gate<<<2048, 256>>>();
    // ff2 split-K=4 -> partials
    gemm_bf<128><<<dim3(4, 8, 12), 128, SM128>>>(pY2h, pY2l, pW2h, pW2l, pFF2, nullptr, nullptr, nullptr,
        C_FF, C_FF, C_D, C_FF, NP_FF, 0, 0, 0, NP_D, 0, 1, 1, 0, 0, 4, 3, 3 * NP_D);

    // 12) vn_ln #2: out = vn_ln(X1 + ff2 partials), interleaved layout
    k_vnln<<<C_N, 256>>>(pX1, pFF2, 4, 3 * NP_D, (float*)d_out, nullptr, nullptr, n2_g, n2_b, 1);
}

// round 14
// speedup vs baseline: 1.1672x; 1.0527x over previous
#include <cuda_runtime.h>
#include <cuda_bf16.h>
#include <cuda_fp16.h>
#include <math.h>
#include <stdint.h>

// ---------------- problem constants ----------------
#define C_N   1024
#define C_K   16
#define C_D   512
#define C_H   8
#define C_FF  2048
#define C_MA  64
#define C_ES  64
#define C_E   (C_N * C_K)      // 16384
#define C_EPS 1e-6f

typedef __nv_bfloat16 bf16;
typedef __half fp16;

// ---------------- fp32 scratch ----------------
__device__ float g_TV  [3][C_N][C_D];
__device__ float g_MSG [3][C_E][C_D];
__device__ float g_w   [C_E][3*C_D];
__device__ float g_PV  [3][C_E][C_D];
__device__ float g_araw[2][C_E][C_MA];
__device__ float g_att [C_E][C_H];
__device__ float g_X1  [3][C_N][C_D];
__device__ float g_Y   [3][C_N][C_FF];
// split-K partial buffers
__device__ float g_PRJP[2][3][C_N][C_D];
__device__ float g_FF2P[4][3][C_N][C_D];
__device__ float g_DVP [2][3][C_N][C_FF];

// ---------------- bf16 hi/lo pairs (GEMM operands) ----------------
__device__ __align__(128) bf16 g_Tb_h [3][C_N][C_D],        g_Tb_l [3][C_N][C_D];
__device__ __align__(128) bf16 g_Mb_h [3][C_E][C_D],        g_Mb_l [3][C_E][C_D];
__device__ __align__(128) bf16 g_pscb_h[C_E][C_D],          g_pscb_l[C_E][C_D];
__device__ __align__(128) bf16 g_Zb_h [3][C_N][C_H][C_D],   g_Zb_l [3][C_N][C_H][C_D];
__device__ __align__(128) bf16 g_OUTb_h[3][C_N][C_D],       g_OUTb_l[3][C_N][C_D];
__device__ __align__(128) bf16 g_X1b_h[3][C_N][C_D],        g_X1b_l[3][C_N][C_D];
__device__ __align__(128) bf16 g_Y2b_h[3][C_N][C_FF],       g_Y2b_l[3][C_N][C_FF];
// fp16 pairs for ffd path
__device__ __align__(128) fp16 g_Yf_h [3][C_N][C_FF],       g_Yf_l [3][C_N][C_FF];
// weights
__device__ __align__(128) bf16 g_Wsrc_h[C_D*C_D],  g_Wsrc_l[C_D*C_D];
__device__ __align__(128) bf16 g_Wdst_h[C_D*C_D],  g_Wdst_l[C_D*C_D];
__device__ __align__(128) bf16 g_Wa_h  [C_MA*C_D], g_Wa_l  [C_MA*C_D];
__device__ __align__(128) bf16 g_Wv_h  [C_D*C_D],  g_Wv_l  [C_D*C_D];
__device__ __align__(128) bf16 g_Wp_h  [C_D*C_D],  g_Wp_l  [C_D*C_D];
__device__ __align__(128) bf16 g_Wf1_h [C_FF*C_D], g_Wf1_l [C_FF*C_D];
__device__ __align__(128) fp16 g_Wfd_f [C_FF*C_FF];
__device__ __align__(128) bf16 g_Wf2_h [C_D*C_FF], g_Wf2_l [C_D*C_FF];

// ---------------- helpers ----------------
__device__ __forceinline__ void bsplit(float v, bf16* H, bf16* L, long i) {
    bf16 h = __float2bfloat16_rn(v);
    H[i] = h;
    L[i] = __float2bfloat16_rn(v - __bfloat162float(h));
}
__device__ __forceinline__ void bsplit2(float v0, float v1, bf16* H, bf16* L, long i) {
    bf16 h0 = __float2bfloat16_rn(v0), h1 = __float2bfloat16_rn(v1);
    *(__nv_bfloat162*)(H + i) = __nv_bfloat162(h0, h1);
    *(__nv_bfloat162*)(L + i) = __nv_bfloat162(
        __float2bfloat16_rn(v0 - __bfloat162float(h0)),
        __float2bfloat16_rn(v1 - __bfloat162float(h1)));
}
__device__ __forceinline__ void hsplit2(float v0, float v1, fp16* H, fp16* L, long i) {
    fp16 h0 = __float2half_rn(v0), h1 = __float2half_rn(v1);
    *(__half2*)(H + i) = __half2(h0, h1);
    *(__half2*)(L + i) = __half2(
        __float2half_rn(v0 - __half2float(h0)),
        __float2half_rn(v1 - __half2float(h1)));
}
__device__ __forceinline__ uint32_t s2u(const void* p) {
    uint32_t a;
    asm("{ .reg .u64 t; cvta.to.shared.u64 t, %1; cvt.u32.u64 %0, t; }" : "=r"(a) : "l"(p));
    return a;
}
__device__ __forceinline__ void mma_bf16(float* c, const uint32_t* a, const uint32_t* b) {
    asm volatile("mma.sync.aligned.m16n8k16.row.col.f32.bf16.bf16.f32 "
                 "{%0,%1,%2,%3},{%4,%5,%6,%7},{%8,%9},{%0,%1,%2,%3};"
                 : "+f"(c[0]), "+f"(c[1]), "+f"(c[2]), "+f"(c[3])
                 : "r"(a[0]), "r"(a[1]), "r"(a[2]), "r"(a[3]), "r"(b[0]), "r"(b[1]));
}
__device__ __forceinline__ void mma_f16(float* c, const uint32_t* a, const uint32_t* b) {
    asm volatile("mma.sync.aligned.m16n8k16.row.col.f32.f16.f16.f32 "
                 "{%0,%1,%2,%3},{%4,%5,%6,%7},{%8,%9},{%0,%1,%2,%3};"
                 : "+f"(c[0]), "+f"(c[1]), "+f"(c[2]), "+f"(c[3])
                 : "r"(a[0]), "r"(a[1]), "r"(a[2]), "r"(a[3]), "r"(b[0]), "r"(b[1]));
}
__device__ __forceinline__ void ldsm4(uint32_t* r, uint32_t addr) {
    asm volatile("ldmatrix.sync.aligned.m8n8.x4.shared.b16 {%0,%1,%2,%3}, [%4];"
        : "=r"(r[0]), "=r"(r[1]), "=r"(r[2]), "=r"(r[3]) : "r"(addr));
}
#define CPA(d, s) asm volatile("cp.async.cg.shared.global [%0], [%1], 16;" :: "r"(d), "l"(s) : "memory")
#define CPC()     asm volatile("cp.async.commit_group;" ::: "memory")
#define CPW(n)    asm volatile("cp.async.wait_group %0;" :: "n"(n) : "memory")

// ============ bf16-pair NT GEMM (3 HMMA passes), optional split-K ============
template<int BN>
__global__ void __launch_bounds__(128, 2) gemm_bf(
    const bf16* __restrict__ Ah, const bf16* __restrict__ Al,
    const bf16* __restrict__ Bh, const bf16* __restrict__ Bl,
    float* __restrict__ C, const float* __restrict__ Add,
    void* __restrict__ CbH, void* __restrict__ CbL, int pairHalf,
    int lda, int ldb, int ldc, int Kc,
    long sA1, long sA2, long sB1, long sB2, long sC1, long sC2, int nz2,
    int addDiv, int ldadd, long sAdd1,
    int nsplit, int nzTot, long sCk)
{
    constexpr int WN   = BN / 2;
    constexpr int NSUB = WN / 8;
    constexpr int ABY  = 10240;
    constexpr int BBY  = BN * 80;
    constexpr int STG  = 2 * ABY + 2 * BBY;

    extern __shared__ __align__(16) char sm[];
    const int t = threadIdx.x, wid = t >> 5, lane = t & 31;
    const int g = lane >> 2, tq = lane & 3;
    const int wm = wid & 1, wn = wid >> 1;

    const int bz = blockIdx.z;
    const int sk = bz / nzTot;
    const int z  = bz - sk * nzTot;
    const int z1 = z / nz2, z2 = z - z1 * nz2;
    const int nch = (Kc >> 5) / nsplit;
    const long kOff = (long)sk * nch * 32;

    const long m0 = (long)blockIdx.y * 128, n0 = (long)blockIdx.x * BN;
    const bf16* Agh = Ah + z1 * sA1 + z2 * sA2 + m0 * lda + kOff;
    const bf16* Agl = Al + z1 * sA1 + z2 * sA2 + m0 * lda + kOff;
    const bf16* Bgh = Bh + z1 * sB1 + z2 * sB2 + n0 * ldb + kOff;
    const bf16* Bgl = Bl + z1 * sB1 + z2 * sB2 + n0 * ldb + kOff;

    const uint32_t smb = s2u(sm);
    const int crow = t >> 2, cseg = t & 3;

    const int lm = lane >> 3, lr = lane & 7;
    const int a_off0 = (wm * 64 + (lm & 1) * 8 + lr) * 80 + (lm >> 1) * 16;
    const int b_off0 = (wn * WN + (lm >> 1) * 8 + lr) * 80 + (lm & 1) * 16;

    float acc[4][NSUB][4];
#pragma unroll
    for (int mi = 0; mi < 4; mi++)
#pragma unroll
        for (int ni = 0; ni < NSUB; ni++)
#pragma unroll
            for (int j = 0; j < 4; j++) acc[mi][ni][j] = 0.f;

    {
        const uint32_t st = smb;
#pragma unroll
        for (int i = 0; i < 4; i++) {
            int row = crow + i * 32;
            uint32_t d = st + row * 80 + cseg * 16;
            CPA(d,       Agh + (long)row * lda + cseg * 8);
            CPA(d + ABY, Agl + (long)row * lda + cseg * 8);
        }
#pragma unroll
        for (int i = 0; i < BN / 32; i++) {
            int row = crow + i * 32;
            uint32_t d = st + 2 * ABY + row * 80 + cseg * 16;
            CPA(d,       Bgh + (long)row * ldb + cseg * 8);
            CPA(d + BBY, Bgl + (long)row * ldb + cseg * 8);
        }
        CPC();
    }

    for (int ch = 0; ch < nch; ch++) {
        if (ch + 1 < nch) {
            const uint32_t st = smb + ((ch + 1) & 1) * STG;
            const bf16* ah = Agh + (ch + 1) * 32;
            const bf16* al = Agl + (ch + 1) * 32;
            const bf16* bh = Bgh + (ch + 1) * 32;
            const bf16* bl = Bgl + (ch + 1) * 32;
#pragma unroll
            for (int i = 0; i < 4; i++) {
                int row = crow + i * 32;
                uint32_t d = st + row * 80 + cseg * 16;
                CPA(d,       ah + (long)row * lda + cseg * 8);
                CPA(d + ABY, al + (long)row * lda + cseg * 8);
            }
#pragma unroll
            for (int i = 0; i < BN / 32; i++) {
                int row = crow + i * 32;
                uint32_t d = st + 2 * ABY + row * 80 + cseg * 16;
                CPA(d,       bh + (long)row * ldb + cseg * 8);
                CPA(d + BBY, bl + (long)row * ldb + cseg * 8);
            }
            CPC();
            CPW(1);
        } else {
            CPW(0);
        }
        __syncthreads();

        const uint32_t sbase = smb + (ch & 1) * STG;
#pragma unroll
        for (int ks = 0; ks < 2; ks++) {
            const int ko = ks * 32;
            uint32_t fa[16], fbh[2 * NSUB], fbl[2 * NSUB];
            const uint32_t abase = sbase + a_off0 + ko;
            const uint32_t bbase = sbase + 2 * ABY + b_off0 + ko;
#pragma unroll
            for (int mi = 0; mi < 4; mi++) ldsm4(&fa[mi * 4], abase + mi * 1280);
#pragma unroll
            for (int np = 0; np < NSUB / 2; np++) ldsm4(&fbh[np * 4], bbase + np * 1280);
#pragma unroll
            for (int mi = 0; mi < 4; mi++)
#pragma unroll
                for (int ni = 0; ni < NSUB; ni++)
                    mma_bf16(acc[mi][ni], &fa[mi * 4], &fbh[ni * 2]);
#pragma unroll
            for (int np = 0; np < NSUB / 2; np++) ldsm4(&fbl[np * 4], bbase + BBY + np * 1280);
#pragma unroll
            for (int mi = 0; mi < 4; mi++)
#pragma unroll
                for (int ni = 0; ni < NSUB; ni++)
                    mma_bf16(acc[mi][ni], &fa[mi * 4], &fbl[ni * 2]);
#pragma unroll
            for (int mi = 0; mi < 4; mi++) ldsm4(&fa[mi * 4], abase + ABY + mi * 1280);
#pragma unroll
            for (int mi = 0; mi < 4; mi++)
#pragma unroll
                for (int ni = 0; ni < NSUB; ni++)
                    mma_bf16(acc[mi][ni], &fa[mi * 4], &fbh[ni * 2]);
        }
        __syncthreads();
    }

    float* Cp = C ? (C + sk * sCk + z1 * sC1 + z2 * sC2) : (float*)0;
    const float* Ad = Add ? (Add + z1 * sAdd1) : (const float*)0;
#pragma unroll
    for (int mi = 0; mi < 4; mi++) {
        long r0 = m0 + wm * 64 + mi * 16 + g;
#pragma unroll
        for (int ni = 0; ni < NSUB; ni++) {
            long col = n0 + wn * WN + ni * 8 + tq * 2;
            float2 v0 = make_float2(acc[mi][ni][0], acc[mi][ni][1]);
            float2 v1 = make_float2(acc[mi][ni][2], acc[mi][ni][3]);
            if (Ad) {
                float2 a0 = *(const float2*)(Ad + (r0 / addDiv) * (long)ldadd + col);
                float2 a1 = *(const float2*)(Ad + ((r0 + 8) / addDiv) * (long)ldadd + col);
                v0.x += a0.x; v0.y += a0.y; v1.x += a1.x; v1.y += a1.y;
            }
            if (Cp) {
                *(float2*)(Cp + r0 * ldc + col) = v0;
                *(float2*)(Cp + (r0 + 8) * ldc + col) = v1;
            }
            if (CbH) {
                long base = z1 * sC1 + z2 * sC2;
                long i0 = base + r0 * ldc + col, i1 = base + (r0 + 8) * ldc + col;
                if (pairHalf) {
                    hsplit2(v0.x, v0.y, (fp16*)CbH, (fp16*)CbL, i0);
                    hsplit2(v1.x, v1.y, (fp16*)CbH, (fp16*)CbL, i1);
                } else {
                    bsplit2(v0.x, v0.y, (bf16*)CbH, (bf16*)CbL, i0);
                    bsplit2(v1.x, v1.y, (bf16*)CbH, (bf16*)CbL, i1);
                }
            }
        }
    }
}

// ============ fp16 2-pass NT GEMM (A hi/lo, B single), split-K ============
__global__ void __launch_bounds__(128, 2) gemm_hf(
    const fp16* __restrict__ Ah, const fp16* __restrict__ Al,
    const fp16* __restrict__ Bh,
    float* __restrict__ C,
    int lda, int ldb, int ldc, int Kc,
    long sA1, long sB1, long sC1,
    int nsplit, int nzTot, long sCk)
{
    constexpr int BN = 128, WN = 64, NSUB = 8;
    constexpr int ABY = 10240;
    constexpr int BBY = BN * 80;
    constexpr int STG = 2 * ABY + BBY;

    extern __shared__ __align__(16) char sm[];
    const int t = threadIdx.x, wid = t >> 5, lane = t & 31;
    const int g = lane >> 2, tq = lane & 3;
    const int wm = wid & 1, wn = wid >> 1;

    const int bz = blockIdx.z;
    const int sk = bz / nzTot;
    const int z1 = bz - sk * nzTot;
    const int nch = (Kc >> 5) / nsplit;
    const long kOff = (long)sk * nch * 32;

    const long m0 = (long)blockIdx.y * 128, n0 = (long)blockIdx.x * BN;
    const fp16* Agh = Ah + z1 * sA1 + m0 * lda + kOff;
    const fp16* Agl = Al + z1 * sA1 + m0 * lda + kOff;
    const fp16* Bgh = Bh + z1 * sB1 + n0 * ldb + kOff;

    const uint32_t smb = s2u(sm);
    const int crow = t >> 2, cseg = t & 3;
    const int lm = lane >> 3, lr = lane & 7;
    const int a_off0 = (wm * 64 + (lm & 1) * 8 + lr) * 80 + (lm >> 1) * 16;
    const int b_off0 = (wn * WN + (lm >> 1) * 8 + lr) * 80 + (lm & 1) * 16;

    float acc[4][NSUB][4];
#pragma unroll
    for (int mi = 0; mi < 4; mi++)
#pragma unroll
        for (int ni = 0; ni < NSUB; ni++)
#pragma unroll
            for (int j = 0; j < 4; j++) acc[mi][ni][j] = 0.f;

    {
        const uint32_t st = smb;
#pragma unroll
        for (int i = 0; i < 4; i++) {
            int row = crow + i * 32;
            uint32_t d = st + row * 80 + cseg * 16;
            CPA(d,       Agh + (long)row * lda + cseg * 8);
            CPA(d + ABY, Agl + (long)row * lda + cseg * 8);
        }
#pragma unroll
        for (int i = 0; i < 4; i++) {
            int row = crow + i * 32;
            CPA(st + 2 * ABY + row * 80 + cseg * 16, Bgh + (long)row * ldb + cseg * 8);
        }
        CPC();
    }

    for (int ch = 0; ch < nch; ch++) {
        if (ch + 1 < nch) {
            const uint32_t st = smb + ((ch + 1) & 1) * STG;
            const fp16* ah = Agh + (ch + 1) * 32;
            const fp16* al = Agl + (ch + 1) * 32;
            const fp16* bh = Bgh + (ch + 1) * 32;
#pragma unroll
            for (int i = 0; i < 4; i++) {
                int row = crow + i * 32;
                uint32_t d = st + row * 80 + cseg * 16;
                CPA(d,       ah + (long)row * lda + cseg * 8);
                CPA(d + ABY, al + (long)row * lda + cseg * 8);
            }
#pragma unroll
            for (int i = 0; i < 4; i++) {
                int row = crow + i * 32;
                CPA(st + 2 * ABY + row * 80 + cseg * 16, bh + (long)row * ldb + cseg * 8);
            }
            CPC();
            CPW(1);
        } else {
            CPW(0);
        }
        __syncthreads();

        const uint32_t sbase = smb + (ch & 1) * STG;
#pragma unroll
        for (int ks = 0; ks < 2; ks++) {
            const int ko = ks * 32;
            uint32_t fa[16], fb[2 * NSUB];
            const uint32_t abase = sbase + a_off0 + ko;
            const uint32_t bbase = sbase + 2 * ABY + b_off0 + ko;
#pragma unroll
            for (int mi = 0; mi < 4; mi++) ldsm4(&fa[mi * 4], abase + mi * 1280);
#pragma unroll
            for (int np = 0; np < NSUB / 2; np++) ldsm4(&fb[np * 4], bbase + np * 1280);
#pragma unroll
            for (int mi = 0; mi < 4; mi++)
#pragma unroll
                for (int ni = 0; ni < NSUB; ni++)
                    mma_f16(acc[mi][ni], &fa[mi * 4], &fb[ni * 2]);     // hi*B
#pragma unroll
            for (int mi = 0; mi < 4; mi++) ldsm4(&fa[mi * 4], abase + ABY + mi * 1280);
#pragma unroll
            for (int mi = 0; mi < 4; mi++)
#pragma unroll
                for (int ni = 0; ni < NSUB; ni++)
                    mma_f16(acc[mi][ni], &fa[mi * 4], &fb[ni * 2]);     // lo*B
        }
        __syncthreads();
    }

    float* Cp = C + sk * sCk + z1 * sC1;
#pragma unroll
    for (int mi = 0; mi < 4; mi++) {
        long r0 = m0 + wm * 64 + mi * 16 + g;
#pragma unroll
        for (int ni = 0; ni < NSUB; ni++) {
            long col = n0 + wn * WN + ni * 8 + tq * 2;
            *(float2*)(Cp + r0 * ldc + col) = make_float2(acc[mi][ni][0], acc[mi][ni][1]);
            *(float2*)(Cp + (r0 + 8) * ldc + col) = make_float2(acc[mi][ni][2], acc[mi][ni][3]);
        }
    }
}

// ---------------- input transpose + bf16 split ----------------
__global__ void k_split_in(const float* __restrict__ tgt, const float* __restrict__ mem)
{
    long stride = (long)gridDim.x * blockDim.x;
    long base   = (long)blockIdx.x * blockDim.x + threadIdx.x;
    for (long p = base; p < (long)C_N * C_D / 2; p += stride) {
        const float* s = tgt + 6 * p;
        float2 a = *(const float2*)s, b = *(const float2*)(s + 2), c = *(const float2*)(s + 4);
        bsplit2(a.x, b.y, &g_Tb_h[0][0][0], &g_Tb_l[0][0][0], 2 * p);
        bsplit2(a.y, c.x, &g_Tb_h[1][0][0], &g_Tb_l[1][0][0], 2 * p);
        bsplit2(b.x, c.y, &g_Tb_h[2][0][0], &g_Tb_l[2][0][0], 2 * p);
    }
    for (long p = base; p < (long)C_E * C_D / 2; p += stride) {
        const float* s = mem + 6 * p;
        float2 a = *(const float2*)s, b = *(const float2*)(s + 2), c = *(const float2*)(s + 4);
        bsplit2(a.x, b.y, &g_Mb_h[0][0][0], &g_Mb_l[0][0][0], 2 * p);
        bsplit2(a.y, c.x, &g_Mb_h[1][0][0], &g_Mb_l[1][0][0], 2 * p);
        bsplit2(b.x, c.y, &g_Mb_h[2][0][0], &g_Mb_l[2][0][0], 2 * p);
    }
}

// ---------------- all weight splits in one kernel ----------------
__global__ void k_split_all(
    const float* __restrict__ Wsrc, const float* __restrict__ Wdst,
    const float* __restrict__ Wv,   const float* __restrict__ Wp,
    const float* __restrict__ Wf1,  const float* __restrict__ Wfd,
    const float* __restrict__ Wf2,  const float* __restrict__ Wa)
{
    const long SQ = (long)C_D * C_D;
    const long O4 = 4 * SQ;
    const long O5 = O4 + (long)C_FF * C_D;
    const long O6 = O5 + (long)C_FF * C_FF;
    const long O7 = O6 + (long)C_D * C_FF;
    const long O8 = O7 + (long)C_MA * C_D;
    long stride = (long)gridDim.x * blockDim.x;
    for (long i = (long)blockIdx.x * blockDim.x + threadIdx.x; i < O8; i += stride) {
        if (i < SQ)            bsplit(Wsrc[i],      g_Wsrc_h, g_Wsrc_l, i);
        else if (i < 2 * SQ)   bsplit(Wdst[i - SQ], g_Wdst_h, g_Wdst_l, i - SQ);
        else if (i < 3 * SQ)   bsplit(Wv[i - 2*SQ], g_Wv_h,   g_Wv_l,   i - 2*SQ);
        else if (i < 4 * SQ)   bsplit(Wp[i - 3*SQ], g_Wp_h,   g_Wp_l,   i - 3*SQ);
        else if (i < O5)       bsplit(Wf1[i - O4],  g_Wf1_h,  g_Wf1_l,  i - O4);
        else if (i < O6)       g_Wfd_f[i - O5] = __float2half_rn(Wfd[i - O5]);
        else if (i < O7)       bsplit(Wf2[i - O6],  g_Wf2_h,  g_Wf2_l,  i - O6);
        else {
            long k = i - O7;
            long r = k >> 6, c = k & 63;
            bsplit(Wa[k], g_Wa_h, g_Wa_l, c * C_D + r);
        }
    }
}

// ---------------- fused edge MLP ----------------
__global__ void __launch_bounds__(256) k_mlp(
    const float* __restrict__ es, const float* __restrict__ w1, const float* __restrict__ b1,
    const float* __restrict__ w2, const float* __restrict__ b2,
    const float* __restrict__ w3, const float* __restrict__ b3)
{
    __shared__ float s_es[64][65];
    __shared__ float s_w1[64][32];
    __shared__ float s_w2[32][32];
    __shared__ float s_h1[64][33];
    __shared__ float s_h2[64][33];
    const int t = threadIdx.x;
    const long e0 = (long)blockIdx.x * 64;

    for (int i = t; i < 64 * 32; i += 256) s_w1[i >> 5][i & 31] = w1[i];
    for (int i = t; i < 32 * 32; i += 256) s_w2[i >> 5][i & 31] = w2[i];
    for (int i = t; i < 64 * 64; i += 256) s_es[i >> 6][i & 63] = es[e0 * 64 + i];
    __syncthreads();

    for (int i = t; i < 64 * 32; i += 256) {
        int e = i >> 5, j = i & 31;
        float acc = b1[j];
#pragma unroll 8
        for (int c = 0; c < 64; c++) acc = fmaf(s_es[e][c], s_w1[c][j], acc);
        s_h1[e][j] = acc / (1.f + expf(-acc));
    }
    __syncthreads();
    for (int i = t; i < 64 * 32; i += 256) {
        int e = i >> 5, j = i & 31;
        float acc = b2[j];
#pragma unroll 8
        for (int c = 0; c < 32; c++) acc = fmaf(s_h1[e][c], s_w2[c][j], acc);
        s_h2[e][j] = acc / (1.f + expf(-acc));
    }
    __syncthreads();
    for (int i = t; i < 64 * 1536; i += 256) {
        int e = i / 1536, o = i - e * 1536;
        float acc = b3[o];
#pragma unroll 8
        for (int c = 0; c < 32; c++) acc = fmaf(s_h2[e][c], w3[c * 1536 + o], acc);
        g_w[e0 + e][o] = acc;
    }
}

// ---------------- pointwise equivariant products ----------------
__global__ void k_pointwise(const float* __restrict__ esh)
{
    long stride = (long)gridDim.x * blockDim.x;
    for (long p = (long)blockIdx.x * blockDim.x + threadIdx.x; p < (long)C_E * C_D / 2; p += stride) {
        int  c = (int)(p & 255) * 2;
        long e = p >> 8;
        float s  = esh[e * 4 + 0];
        float v0 = esh[e * 4 + 1], v1 = esh[e * 4 + 2], v2 = esh[e * 4 + 3];
        float2 m0 = *(const float2*)&g_MSG[0][e][c];
        float2 m1 = *(const float2*)&g_MSG[1][e][c];
        float2 m2 = *(const float2*)&g_MSG[2][e][c];
        float2 w0 = *(const float2*)&g_w[e][c];
        float2 w1 = *(const float2*)&g_w[e][512 + c];
        float2 w2 = *(const float2*)&g_w[e][1024 + c];
        float p0 = w0.x * (m0.x * v0 + m1.x * v1 + m2.x * v2) * 0.5773502691896258f;
        float p1 = w0.y * (m0.y * v0 + m1.y * v1 + m2.y * v2) * 0.5773502691896258f;
        bsplit2(p0, p1, &g_pscb_h[0][0], &g_pscb_l[0][0], e * C_D + c);
        float k2x = w2.x * 0.7071067811865475f, k2y = w2.y * 0.7071067811865475f;
        float wsx = w1.x * s, wsy = w1.y * s;
        *(float2*)&g_PV[0][e][c] = make_float2(wsx * m0.x + k2x * (m1.x * v2 - m2.x * v1),
                                               wsy * m0.y + k2y * (m1.y * v2 - m2.y * v1));
        *(float2*)&g_PV[1][e][c] = make_float2(wsx * m1.x + k2x * (m2.x * v0 - m0.x * v2),
                                               wsy * m1.y + k2y * (m2.y * v0 - m0.y * v2));
        *(float2*)&g_PV[2][e][c] = make_float2(wsx * m2.x + k2x * (m0.x * v1 - m1.x * v0),
                                               wsy * m2.y + k2y * (m0.y * v1 - m1.y * v0));
    }
}

// ---------------- fused alpha post + softmax (reduces 2 split-K partials) ----------------
__global__ void __launch_bounds__(512) k_alpha(const float* __restrict__ gg, const float* __restrict__ bb,
                                               const float* __restrict__ adot)
{
    int n = blockIdx.x;
    int t = threadIdx.x, wid = t >> 5, lane = t & 31;
    __shared__ float s_l[16][8];
    int e = n * 16 + wid;
    float v0 = g_araw[0][e][lane * 2]     + g_araw[1][e][lane * 2];
    float v1 = g_araw[0][e][lane * 2 + 1] + g_araw[1][e][lane * 2 + 1];
    float s = v0 + v1, s2 = v0 * v0 + v1 * v1;
#pragma unroll
    for (int o = 16; o > 0; o >>= 1) {
        s  += __shfl_xor_sync(0xffffffffu, s, o);
        s2 += __shfl_xor_sync(0xffffffffu, s2, o);
    }
    float mu  = s * (1.f / 64.f);
    float var = s2 * (1.f / 64.f) - mu * mu;
    float inv = rsqrtf(var + C_EPS);
    float a0 = (v0 - mu) * inv * gg[lane * 2]     + bb[lane * 2];
    float a1 = (v1 - mu) * inv * gg[lane * 2 + 1] + bb[lane * 2 + 1];
    a0 = 0.6f * a0 + 0.4f * a0 * tanhf(0.5f * a0);
    a1 = 0.6f * a1 + 0.4f * a1 * tanhf(0.5f * a1);
    int h = lane >> 2;
    int m = (lane & 3) * 2;
    float p = a0 * adot[h * 8 + m] + a1 * adot[h * 8 + m + 1];
    p += __shfl_xor_sync(0xffffffffu, p, 1);
    p += __shfl_xor_sync(0xffffffffu, p, 2);
    if ((lane & 3) == 0) s_l[wid][h] = p;
    __syncthreads();
    if (t < 8) {
        float mx = -1e30f;
#pragma unroll
        for (int k = 0; k < 16; k++) mx = fmaxf(mx, s_l[k][t]);
        float sum = 0.f; float ex[16];
#pragma unroll
        for (int k = 0; k < 16; k++) { ex[k] = expf(s_l[k][t] - mx); sum += ex[k]; }
        float is = 1.f / sum;
#pragma unroll
        for (int k = 0; k < 16; k++) g_att[n * 16 + k][t] = ex[k] * is;
    }
}

// ---------------- z = sum_k att * pv ----------------
__global__ void __launch_bounds__(256) k_z()
{
    int n = blockIdx.x, x = blockIdx.y;
    __shared__ float s_a[16][8];
    if (threadIdx.x < 128)
        s_a[threadIdx.x >> 3][threadIdx.x & 7] = g_att[n * 16 + (threadIdx.x >> 3)][threadIdx.x & 7];
    __syncthreads();
    int c = threadIdx.x * 2;
    float2 acc[8];
#pragma unroll
    for (int h = 0; h < 8; h++) acc[h] = make_float2(0.f, 0.f);
#pragma unroll
    for (int k = 0; k < 16; k++) {
        float2 pv = *(const float2*)&g_PV[x][n * 16 + k][c];
#pragma unroll
        for (int h = 0; h < 8; h++) {
            acc[h].x = fmaf(s_a[k][h], pv.x, acc[h].x);
            acc[h].y = fmaf(s_a[k][h], pv.y, acc[h].y);
        }
    }
#pragma unroll
    for (int h = 0; h < 8; h++) {
        long idx = (((long)x * C_N + n) * C_H + h) * C_D + c;
        bsplit2(acc[h].x, acc[h].y, &g_Zb_h[0][0][0][0], &g_Zb_l[0][0][0][0], idx);
    }
}

// ---------------- vn_ln with fused split-K partial reduction ----------------
__global__ void __launch_bounds__(256) k_vnln(const float* __restrict__ Xin,
                                              const float* __restrict__ Parts, int nparts, long pstride,
                                              float* __restrict__ Xout,
                                              bf16* __restrict__ bH, bf16* __restrict__ bL,
                                              const float* __restrict__ gg, const float* __restrict__ bb,
                                              int inter)
{
    int n = blockIdx.x, t = threadIdx.x;
    const long P = (long)C_N * C_D;
    __shared__ float rs[8], rs2[8];
    __shared__ float smu, sinv;
    float xv[2][3], nc[2];
    float s = 0.f, s2 = 0.f;
#pragma unroll
    for (int i = 0; i < 2; i++) {
        int c = t * 2 + i;
#pragma unroll
        for (int xx = 0; xx < 3; xx++) {
            long idx = xx * P + (long)n * C_D + c;
            float v = Xin[idx];
            for (int pp = 0; pp < nparts; pp++) v += Parts[pp * pstride + idx];
            xv[i][xx] = v;
        }
        float v = sqrtf(xv[i][0] * xv[i][0] + xv[i][1] * xv[i][1] + xv[i][2] * xv[i][2] + C_EPS);
        nc[i] = v; s += v; s2 = fmaf(v, v, s2);
    }
#pragma unroll
    for (int o = 16; o > 0; o >>= 1) {
        s  += __shfl_xor_sync(0xffffffffu, s, o);
        s2 += __shfl_xor_sync(0xffffffffu, s2, o);
    }
    if ((t & 31) == 0) { rs[t >> 5] = s; rs2[t >> 5] = s2; }
    __syncthreads();
    if (t == 0) {
        float S = 0.f, S2 = 0.f;
        for (int i = 0; i < 8; i++) { S += rs[i]; S2 += rs2[i]; }
        float mu  = S * (1.f / 512.f);
        float var = S2 * (1.f / 512.f) - mu * mu;
        smu = mu; sinv = rsqrtf(var + C_EPS);
    }
    __syncthreads();
    float sc[2];
#pragma unroll
    for (int i = 0; i < 2; i++) {
        int c = t * 2 + i;
        float ln = (nc[i] - smu) * sinv * gg[c] + bb[c];
        sc[i] = ln / nc[i];
    }
    if (inter) {
#pragma unroll
        for (int i = 0; i < 2; i++) {
            int c = t * 2 + i;
#pragma unroll
            for (int xx = 0; xx < 3; xx++) Xout[(long)n * 1536 + c * 3 + xx] = xv[i][xx] * sc[i];
        }
    } else {
#pragma unroll
        for (int xx = 0; xx < 3; xx++) {
            long idx = xx * P + (long)n * C_D + t * 2;
            float o0 = xv[0][xx] * sc[0], o1 = xv[1][xx] * sc[1];
            *(float2*)(Xout + idx) = make_float2(o0, o1);
            if (bH) bsplit2(o0, o1, bH, bL, idx);
        }
    }
}

// ---------------- FF gating with fused DV partial reduction ----------------
__global__ void k_gate()
{
    const long P = (long)C_N * C_FF;
    const float* Y  = &g_Y[0][0][0];
    const float* D0 = &g_DVP[0][0][0][0];
    const float* D1 = &g_DVP[1][0][0][0];
    long stride = (long)gridDim.x * blockDim.x;
    for (long p = (long)blockIdx.x * blockDim.x + threadIdx.x; p < P / 2; p += stride) {
        long i = 2 * p;
        float2 y0 = *(const float2*)(Y + i), y1 = *(const float2*)(Y + P + i), y2 = *(const float2*)(Y + 2 * P + i);
        float2 a0 = *(const float2*)(D0 + i), a1 = *(const float2*)(D0 + P + i), a2 = *(const float2*)(D0 + 2 * P + i);
        float2 b0 = *(const float2*)(D1 + i), b1 = *(const float2*)(D1 + P + i), b2 = *(const float2*)(D1 + 2 * P + i);
        float2 d0 = make_float2(a0.x + b0.x, a0.y + b0.y);
        float2 d1 = make_float2(a1.x + b1.x, a1.y + b1.y);
        float2 d2 = make_float2(a2.x + b2.x, a2.y + b2.y);
        float dotx = y0.x * d0.x + y1.x * d1.x + y2.x * d2.x;
        float doty = y0.y * d0.y + y1.y * d1.y + y2.y * d2.y;
        float fx = (dotx >= 0.f) ? 0.f : 0.8f * dotx / (d0.x * d0.x + d1.x * d1.x + d2.x * d2.x + C_EPS);
        float fy = (doty >= 0.f) ? 0.f : 0.8f * doty / (d0.y * d0.y + d1.y * d1.y + d2.y * d2.y + C_EPS);
        bsplit2(y0.x - fx * d0.x, y0.y - fy * d0.y, &g_Y2b_h[0][0][0], &g_Y2b_l[0][0][0], i);
        bsplit2(y1.x - fx * d1.x, y1.y - fy * d1.y, &g_Y2b_h[0][0][0], &g_Y2b_l[0][0][0], P + i);
        bsplit2(y2.x - fx * d2.x, y2.y - fy * d2.y, &g_Y2b_h[0][0][0], &g_Y2b_l[0][0][0], 2 * P + i);
    }
}

// ---------------- host launch ----------------
extern "C" void kernel_launch(void* const* d_in, const int* in_sizes, int n_in,
                              void* d_out, int out_size)
{
    const float* tgt    = (const float*)d_in[0];
    const float* mem    = (const float*)d_in[1];
    const float* esh    = (const float*)d_in[2];
    const float* escal  = (const float*)d_in[3];
    const float* W_src  = (const float*)d_in[4];
    const float* W_dst  = (const float*)d_in[5];
    const float* fc_w1  = (const float*)d_in[6];
    const float* fc_b1  = (const float*)d_in[7];
    const float* fc_w2  = (const float*)d_in[8];
    const float* fc_b2  = (const float*)d_in[9];
    const float* fc_w3  = (const float*)d_in[10];
    const float* fc_b3  = (const float*)d_in[11];
    const float* W_alpha= (const float*)d_in[12];
    const float* ln_a_g = (const float*)d_in[13];
    const float* ln_a_b = (const float*)d_in[14];
    const float* adot   = (const float*)d_in[15];
    const float* W_value= (const float*)d_in[16];
    const float* W_proj = (const float*)d_in[17];
    const float* n1_g   = (const float*)d_in[18];
    const float* n1_b   = (const float*)d_in[19];
    const float* n2_g   = (const float*)d_in[20];
    const float* n2_b   = (const float*)d_in[21];
    const float* W_ff1  = (const float*)d_in[22];
    const float* W_ffd  = (const float*)d_in[23];
    const float* W_ff2  = (const float*)d_in[24];

#define SYM(p, s) cudaGetSymbolAddress((void**)&p, s)
    float *pTV, *pMSG, *paraw, *pX1, *pY, *pPRJ, *pFF2, *pDVP;
    SYM(pTV, g_TV); SYM(pMSG, g_MSG); SYM(paraw, g_araw);
    SYM(pX1, g_X1); SYM(pY, g_Y);
    SYM(pPRJ, g_PRJP); SYM(pFF2, g_FF2P); SYM(pDVP, g_DVP);
    bf16 *pTbh, *pTbl, *pMbh, *pMbl, *ppsh, *ppsl, *pZh, *pZl, *pOh, *pOl;
    bf16 *pX1h, *pX1l, *pY2h, *pY2l;
    SYM(pTbh, g_Tb_h); SYM(pTbl, g_Tb_l); SYM(pMbh, g_Mb_h); SYM(pMbl, g_Mb_l);
    SYM(ppsh, g_pscb_h); SYM(ppsl, g_pscb_l); SYM(pZh, g_Zb_h); SYM(pZl, g_Zb_l);
    SYM(pOh, g_OUTb_h); SYM(pOl, g_OUTb_l); SYM(pX1h, g_X1b_h); SYM(pX1l, g_X1b_l);
    SYM(pY2h, g_Y2b_h); SYM(pY2l, g_Y2b_l);
    fp16 *pYfh, *pYfl, *pWfdf;
    SYM(pYfh, g_Yf_h); SYM(pYfl, g_Yf_l); SYM(pWfdf, g_Wfd_f);
    bf16 *pWsh, *pWsl, *pWdh, *pWdl, *pWah, *pWal, *pWvh, *pWvl, *pWph, *pWpl;
    bf16 *pW1h, *pW1l, *pW2h, *pW2l;
    SYM(pWsh, g_Wsrc_h); SYM(pWsl, g_Wsrc_l); SYM(pWdh, g_Wdst_h); SYM(pWdl, g_Wdst_l);
    SYM(pWah, g_Wa_h); SYM(pWal, g_Wa_l); SYM(pWvh, g_Wv_h); SYM(pWvl, g_Wv_l);
    SYM(pWph, g_Wp_h); SYM(pWpl, g_Wp_l); SYM(pW1h, g_Wf1_h); SYM(pW1l, g_Wf1_l);
    SYM(pW2h, g_Wf2_h); SYM(pW2l, g_Wf2_l);
#undef SYM

    const long NP_D  = (long)C_N * C_D;
    const long EP_D  = (long)C_E * C_D;
    const long NP_FF = (long)C_N * C_FF;
    const long NHD   = (long)C_N * C_H * C_D;

    const int SM128 = 2 * (2 * 10240 + 2 * 128 * 80);   // 81920
    const int SM64  = 2 * (2 * 10240 + 2 * 64 * 80);    // 61440
    const int SMH   = 2 * (2 * 10240 + 128 * 80);       // 61440
    cudaFuncSetAttribute(gemm_bf<128>, cudaFuncAttributeMaxDynamicSharedMemorySize, SM128);
    cudaFuncSetAttribute(gemm_bf<64>,  cudaFuncAttributeMaxDynamicSharedMemorySize, SM64);
    cudaFuncSetAttribute(gemm_hf,      cudaFuncAttributeMaxDynamicSharedMemorySize, SMH);

    // 1) input + weight splits
    k_split_in<<<4096, 256>>>(tgt, mem);
    k_split_all<<<8192, 256>>>(W_src, W_dst, W_value, W_proj, W_ff1, W_ffd, W_ff2, W_alpha);

    // 2) tv = W_dst @ tgt
    gemm_bf<128><<<dim3(4, 8, 3), 128, SM128>>>(pTbh, pTbl, pWdh, pWdl, pTV, nullptr, nullptr, nullptr, 0,
        C_D, C_D, C_D, C_D, NP_D, 0, 0, 0, NP_D, 0, 1, 1, 0, 0, 1, 3, 0);

    // 3) msg = W_src @ memory + tv[e/K]
    gemm_bf<128><<<dim3(4, 128, 3), 128, SM128>>>(pMbh, pMbl, pWsh, pWsl, pMSG, pTV, nullptr, nullptr, 0,
        C_D, C_D, C_D, C_D, EP_D, 0, 0, 0, EP_D, 0, 1, C_K, C_D, NP_D, 1, 3, 0);

    // 4) edge MLP -> g_w
    k_mlp<<<C_E / 64, 256>>>(escal, fc_w1, fc_b1, fc_w2, fc_b2, fc_w3, fc_b3);

    // 5) p_sc / pv
    k_pointwise<<<2048, 256>>>(esh);

    // 6) a_raw = p_sc @ W_alpha (split-K=2 -> partials reduced in k_alpha)
    gemm_bf<64><<<dim3(1, 128, 2), 128, SM64>>>(ppsh, ppsl, pWah, pWal, paraw, nullptr, nullptr, nullptr, 0,
        C_D, C_D, C_MA, C_D, 0, 0, 0, 0, 0, 0, 1, 1, 0, 0, 2, 1, (long)C_E * C_MA);

    // 7) fused LN + lrelu + head dot + softmax
    k_alpha<<<C_N, 512>>>(ln_a_g, ln_a_b, adot);

    // 8) z = sum_k att * pv
    k_z<<<dim3(C_N, 3), 256>>>();

    // 9) out = W_value @ z (per head, bf16 out), then proj (split-K=2)
    gemm_bf<64><<<dim3(1, 8, 24), 128, SM64>>>(pZh, pZl, pWvh, pWvl, nullptr, nullptr, pOh, pOl, 0,
        C_H * C_D, C_D, C_D, C_D, NHD, C_D, 0, 64 * C_D, NP_D, 64, C_H, 1, 0, 0, 1, 24, 0);
    gemm_bf<128><<<dim3(4, 8, 6), 128, SM128>>>(pOh, pOl, pWph, pWpl, pPRJ, nullptr, nullptr, nullptr, 0,
        C_D, C_D, C_D, C_D, NP_D, 0, 0, 0, NP_D, 0, 1, 1, 0, 0, 2, 3, 3 * NP_D);

    // 10) vn_ln #1
    k_vnln<<<C_N, 256>>>(pTV, pPRJ, 2, 3 * NP_D, pX1, pX1h, pX1l, n1_g, n1_b, 0);

    // 11) FF block: ff1 (bf16 3-pass, fp16 pair out), ffd (fp16 2-pass, split-K=2)
    gemm_bf<128><<<dim3(16, 8, 3), 128, SM128>>>(pX1h, pX1l, pW1h, pW1l, pY, nullptr, pYfh, pYfl, 1,
        C_D, C_D, C_FF, C_D, NP_D, 0, 0, 0, NP_FF, 0, 1, 1, 0, 0, 1, 3, 0);
    gemm_hf<<<dim3(16, 8, 6), 128, SMH>>>(pYfh, pYfl, pWfdf, pDVP,
        C_FF, C_FF, C_FF, C_FF, NP_FF, 0, NP_FF, 2, 3, 3 * NP_FF);
    k_gate<<<2048, 256>>>();
    gemm_bf<128><<<dim3(4, 8, 12), 128, SM128>>>(pY2h, pY2l, pW2h, pW2l, pFF2, nullptr, nullptr, nullptr, 0,
        C_FF, C_FF, C_D, C_FF, NP_FF, 0, 0, 0, NP_D, 0, 1, 1, 0, 0, 4, 3, 3 * NP_D);

    // 12) vn_ln #2 -> interleaved output
    k_vnln<<<C_N, 256>>>(pX1, pFF2, 4, 3 * NP_D, (float*)d_out, nullptr, nullptr, n2_g, n2_b, 1);
}

// round 15
// speedup vs baseline: 1.2107x; 1.0373x over previous
#include <cuda_runtime.h>
#include <cuda_bf16.h>
#include <cuda_fp16.h>
#include <math.h>
#include <stdint.h>

// ---------------- problem constants ----------------
#define C_N   1024
#define C_K   16
#define C_D   512
#define C_H   8
#define C_FF  2048
#define C_MA  64
#define C_ES  64
#define C_E   (C_N * C_K)      // 16384
#define C_EPS 1e-6f

typedef __nv_bfloat16 bf16;
typedef __half fp16;

// ---------------- fp32 scratch ----------------
__device__ float g_TV  [3][C_N][C_D];
__device__ float g_MSG [3][C_E][C_D];
__device__ float g_w   [C_E][3*C_D];
__device__ float g_PV  [3][C_E][C_D];
__device__ float g_araw[2][C_E][C_MA];
__device__ float g_att [C_E][C_H];
__device__ float g_X1  [3][C_N][C_D];
__device__ float g_Y   [3][C_N][C_FF];
// split-K partial buffers
__device__ float g_PRJP[2][3][C_N][C_D];
__device__ float g_FF2P[4][3][C_N][C_D];
__device__ float g_DVP [2][3][C_N][C_FF];

// ---------------- bf16 hi/lo pairs (GEMM operands) ----------------
__device__ __align__(128) bf16 g_Tb_h [3][C_N][C_D],        g_Tb_l [3][C_N][C_D];
__device__ __align__(128) bf16 g_Mb_h [3][C_E][C_D],        g_Mb_l [3][C_E][C_D];
__device__ __align__(128) bf16 g_pscb_h[C_E][C_D],          g_pscb_l[C_E][C_D];
__device__ __align__(128) bf16 g_Zb_h [3][C_N][C_H][C_D],   g_Zb_l [3][C_N][C_H][C_D];
__device__ __align__(128) bf16 g_OUTb_h[3][C_N][C_D],       g_OUTb_l[3][C_N][C_D];
// fp16 pairs (FF block path)
__device__ __align__(128) fp16 g_X1f_h[3][C_N][C_D],        g_X1f_l[3][C_N][C_D];
__device__ __align__(128) fp16 g_Yf_h [3][C_N][C_FF],       g_Yf_l [3][C_N][C_FF];
__device__ __align__(128) fp16 g_Y2f_h[3][C_N][C_FF],       g_Y2f_l[3][C_N][C_FF];
// weights
__device__ __align__(128) bf16 g_Wsrc_h[C_D*C_D],  g_Wsrc_l[C_D*C_D];
__device__ __align__(128) bf16 g_Wdst_h[C_D*C_D],  g_Wdst_l[C_D*C_D];
__device__ __align__(128) bf16 g_Wa_h  [C_MA*C_D], g_Wa_l  [C_MA*C_D];
__device__ __align__(128) bf16 g_Wv_h  [C_D*C_D],  g_Wv_l  [C_D*C_D];
__device__ __align__(128) bf16 g_Wp_h  [C_D*C_D],  g_Wp_l  [C_D*C_D];
__device__ __align__(128) fp16 g_Wf1_f [C_FF*C_D];
__device__ __align__(128) fp16 g_Wfd_f [C_FF*C_FF];
__device__ __align__(128) fp16 g_Wf2_f [C_D*C_FF];

// ---------------- helpers ----------------
__device__ __forceinline__ void bsplit(float v, bf16* H, bf16* L, long i) {
    bf16 h = __float2bfloat16_rn(v);
    H[i] = h;
    L[i] = __float2bfloat16_rn(v - __bfloat162float(h));
}
__device__ __forceinline__ void bsplit2(float v0, float v1, bf16* H, bf16* L, long i) {
    bf16 h0 = __float2bfloat16_rn(v0), h1 = __float2bfloat16_rn(v1);
    *(__nv_bfloat162*)(H + i) = __nv_bfloat162(h0, h1);
    *(__nv_bfloat162*)(L + i) = __nv_bfloat162(
        __float2bfloat16_rn(v0 - __bfloat162float(h0)),
        __float2bfloat16_rn(v1 - __bfloat162float(h1)));
}
__device__ __forceinline__ void hsplit2(float v0, float v1, fp16* H, fp16* L, long i) {
    fp16 h0 = __float2half_rn(v0), h1 = __float2half_rn(v1);
    *(__half2*)(H + i) = __half2(h0, h1);
    *(__half2*)(L + i) = __half2(
        __float2half_rn(v0 - __half2float(h0)),
        __float2half_rn(v1 - __half2float(h1)));
}
__device__ __forceinline__ uint32_t s2u(const void* p) {
    uint32_t a;
    asm("{ .reg .u64 t; cvta.to.shared.u64 t, %1; cvt.u32.u64 %0, t; }" : "=r"(a) : "l"(p));
    return a;
}
__device__ __forceinline__ void mma_bf16(float* c, const uint32_t* a, const uint32_t* b) {
    asm volatile("mma.sync.aligned.m16n8k16.row.col.f32.bf16.bf16.f32 "
                 "{%0,%1,%2,%3},{%4,%5,%6,%7},{%8,%9},{%0,%1,%2,%3};"
                 : "+f"(c[0]), "+f"(c[1]), "+f"(c[2]), "+f"(c[3])
                 : "r"(a[0]), "r"(a[1]), "r"(a[2]), "r"(a[3]), "r"(b[0]), "r"(b[1]));
}
__device__ __forceinline__ void mma_f16(float* c, const uint32_t* a, const uint32_t* b) {
    asm volatile("mma.sync.aligned.m16n8k16.row.col.f32.f16.f16.f32 "
                 "{%0,%1,%2,%3},{%4,%5,%6,%7},{%8,%9},{%0,%1,%2,%3};"
                 : "+f"(c[0]), "+f"(c[1]), "+f"(c[2]), "+f"(c[3])
                 : "r"(a[0]), "r"(a[1]), "r"(a[2]), "r"(a[3]), "r"(b[0]), "r"(b[1]));
}
__device__ __forceinline__ void ldsm4(uint32_t* r, uint32_t addr) {
    asm volatile("ldmatrix.sync.aligned.m8n8.x4.shared.b16 {%0,%1,%2,%3}, [%4];"
        : "=r"(r[0]), "=r"(r[1]), "=r"(r[2]), "=r"(r[3]) : "r"(addr));
}
#define CPA(d, s) asm volatile("cp.async.cg.shared.global [%0], [%1], 16;" :: "r"(d), "l"(s) : "memory")
#define CPC()     asm volatile("cp.async.commit_group;" ::: "memory")
#define CPW(n)    asm volatile("cp.async.wait_group %0;" :: "n"(n) : "memory")

// ============ bf16-pair NT GEMM (3 HMMA passes), optional split-K ============
template<int BN>
__global__ void __launch_bounds__(128, 2) gemm_bf(
    const bf16* __restrict__ Ah, const bf16* __restrict__ Al,
    const bf16* __restrict__ Bh, const bf16* __restrict__ Bl,
    float* __restrict__ C, const float* __restrict__ Add,
    bf16* __restrict__ CbH, bf16* __restrict__ CbL,
    int lda, int ldb, int ldc, int Kc,
    long sA1, long sA2, long sB1, long sB2, long sC1, long sC2, int nz2,
    int addDiv, int ldadd, long sAdd1,
    int nsplit, int nzTot, long sCk)
{
    constexpr int WN   = BN / 2;
    constexpr int NSUB = WN / 8;
    constexpr int ABY  = 10240;
    constexpr int BBY  = BN * 80;
    constexpr int STG  = 2 * ABY + 2 * BBY;

    extern __shared__ __align__(16) char sm[];
    const int t = threadIdx.x, wid = t >> 5, lane = t & 31;
    const int g = lane >> 2, tq = lane & 3;
    const int wm = wid & 1, wn = wid >> 1;

    const int bz = blockIdx.z;
    const int sk = bz / nzTot;
    const int z  = bz - sk * nzTot;
    const int z1 = z / nz2, z2 = z - z1 * nz2;
    const int nch = (Kc >> 5) / nsplit;
    const long kOff = (long)sk * nch * 32;

    const long m0 = (long)blockIdx.y * 128, n0 = (long)blockIdx.x * BN;
    const bf16* Agh = Ah + z1 * sA1 + z2 * sA2 + m0 * lda + kOff;
    const bf16* Agl = Al + z1 * sA1 + z2 * sA2 + m0 * lda + kOff;
    const bf16* Bgh = Bh + z1 * sB1 + z2 * sB2 + n0 * ldb + kOff;
    const bf16* Bgl = Bl + z1 * sB1 + z2 * sB2 + n0 * ldb + kOff;

    const uint32_t smb = s2u(sm);
    const int crow = t >> 2, cseg = t & 3;

    const int lm = lane >> 3, lr = lane & 7;
    const int a_off0 = (wm * 64 + (lm & 1) * 8 + lr) * 80 + (lm >> 1) * 16;
    const int b_off0 = (wn * WN + (lm >> 1) * 8 + lr) * 80 + (lm & 1) * 16;

    float acc[4][NSUB][4];
#pragma unroll
    for (int mi = 0; mi < 4; mi++)
#pragma unroll
        for (int ni = 0; ni < NSUB; ni++)
#pragma unroll
            for (int j = 0; j < 4; j++) acc[mi][ni][j] = 0.f;

    {
        const uint32_t st = smb;
#pragma unroll
        for (int i = 0; i < 4; i++) {
            int row = crow + i * 32;
            uint32_t d = st + row * 80 + cseg * 16;
            CPA(d,       Agh + (long)row * lda + cseg * 8);
            CPA(d + ABY, Agl + (long)row * lda + cseg * 8);
        }
#pragma unroll
        for (int i = 0; i < BN / 32; i++) {
            int row = crow + i * 32;
            uint32_t d = st + 2 * ABY + row * 80 + cseg * 16;
            CPA(d,       Bgh + (long)row * ldb + cseg * 8);
            CPA(d + BBY, Bgl + (long)row * ldb + cseg * 8);
        }
        CPC();
    }

    for (int ch = 0; ch < nch; ch++) {
        if (ch + 1 < nch) {
            const uint32_t st = smb + ((ch + 1) & 1) * STG;
            const bf16* ah = Agh + (ch + 1) * 32;
            const bf16* al = Agl + (ch + 1) * 32;
            const bf16* bh = Bgh + (ch + 1) * 32;
            const bf16* bl = Bgl + (ch + 1) * 32;
#pragma unroll
            for (int i = 0; i < 4; i++) {
                int row = crow + i * 32;
                uint32_t d = st + row * 80 + cseg * 16;
                CPA(d,       ah + (long)row * lda + cseg * 8);
                CPA(d + ABY, al + (long)row * lda + cseg * 8);
            }
#pragma unroll
            for (int i = 0; i < BN / 32; i++) {
                int row = crow + i * 32;
                uint32_t d = st + 2 * ABY + row * 80 + cseg * 16;
                CPA(d,       bh + (long)row * ldb + cseg * 8);
                CPA(d + BBY, bl + (long)row * ldb + cseg * 8);
            }
            CPC();
            CPW(1);
        } else {
            CPW(0);
        }
        __syncthreads();

        const uint32_t sbase = smb + (ch & 1) * STG;
#pragma unroll
        for (int ks = 0; ks < 2; ks++) {
            const int ko = ks * 32;
            uint32_t fa[16], fbh[2 * NSUB], fbl[2 * NSUB];
            const uint32_t abase = sbase + a_off0 + ko;
            const uint32_t bbase = sbase + 2 * ABY + b_off0 + ko;
#pragma unroll
            for (int mi = 0; mi < 4; mi++) ldsm4(&fa[mi * 4], abase + mi * 1280);
#pragma unroll
            for (int np = 0; np < NSUB / 2; np++) ldsm4(&fbh[np * 4], bbase + np * 1280);
#pragma unroll
            for (int mi = 0; mi < 4; mi++)
#pragma unroll
                for (int ni = 0; ni < NSUB; ni++)
                    mma_bf16(acc[mi][ni], &fa[mi * 4], &fbh[ni * 2]);
#pragma unroll
            for (int np = 0; np < NSUB / 2; np++) ldsm4(&fbl[np * 4], bbase + BBY + np * 1280);
#pragma unroll
            for (int mi = 0; mi < 4; mi++)
#pragma unroll
                for (int ni = 0; ni < NSUB; ni++)
                    mma_bf16(acc[mi][ni], &fa[mi * 4], &fbl[ni * 2]);
#pragma unroll
            for (int mi = 0; mi < 4; mi++) ldsm4(&fa[mi * 4], abase + ABY + mi * 1280);
#pragma unroll
            for (int mi = 0; mi < 4; mi++)
#pragma unroll
                for (int ni = 0; ni < NSUB; ni++)
                    mma_bf16(acc[mi][ni], &fa[mi * 4], &fbh[ni * 2]);
        }
        __syncthreads();
    }

    float* Cp = C ? (C + sk * sCk + z1 * sC1 + z2 * sC2) : (float*)0;
    const float* Ad = Add ? (Add + z1 * sAdd1) : (const float*)0;
#pragma unroll
    for (int mi = 0; mi < 4; mi++) {
        long r0 = m0 + wm * 64 + mi * 16 + g;
#pragma unroll
        for (int ni = 0; ni < NSUB; ni++) {
            long col = n0 + wn * WN + ni * 8 + tq * 2;
            float2 v0 = make_float2(acc[mi][ni][0], acc[mi][ni][1]);
            float2 v1 = make_float2(acc[mi][ni][2], acc[mi][ni][3]);
            if (Ad) {
                float2 a0 = *(const float2*)(Ad + (r0 / addDiv) * (long)ldadd + col);
                float2 a1 = *(const float2*)(Ad + ((r0 + 8) / addDiv) * (long)ldadd + col);
                v0.x += a0.x; v0.y += a0.y; v1.x += a1.x; v1.y += a1.y;
            }
            if (Cp) {
                *(float2*)(Cp + r0 * ldc + col) = v0;
                *(float2*)(Cp + (r0 + 8) * ldc + col) = v1;
            }
            if (CbH) {
                long base = z1 * sC1 + z2 * sC2;
                long i0 = base + r0 * ldc + col, i1 = base + (r0 + 8) * ldc + col;
                bsplit2(v0.x, v0.y, CbH, CbL, i0);
                bsplit2(v1.x, v1.y, CbH, CbL, i1);
            }
        }
    }
}

// ============ fp16 2-pass NT GEMM (A hi/lo, B single), split-K, optional fp16-pair out ============
__global__ void __launch_bounds__(128, 2) gemm_hf(
    const fp16* __restrict__ Ah, const fp16* __restrict__ Al,
    const fp16* __restrict__ Bh,
    float* __restrict__ C,
    fp16* __restrict__ CbH, fp16* __restrict__ CbL,
    int lda, int ldb, int ldc, int Kc,
    long sA1, long sB1, long sC1,
    int nsplit, int nzTot, long sCk)
{
    constexpr int BN = 128, WN = 64, NSUB = 8;
    constexpr int ABY = 10240;
    constexpr int BBY = BN * 80;
    constexpr int STG = 2 * ABY + BBY;

    extern __shared__ __align__(16) char sm[];
    const int t = threadIdx.x, wid = t >> 5, lane = t & 31;
    const int g = lane >> 2, tq = lane & 3;
    const int wm = wid & 1, wn = wid >> 1;

    const int bz = blockIdx.z;
    const int sk = bz / nzTot;
    const int z1 = bz - sk * nzTot;
    const int nch = (Kc >> 5) / nsplit;
    const long kOff = (long)sk * nch * 32;

    const long m0 = (long)blockIdx.y * 128, n0 = (long)blockIdx.x * BN;
    const fp16* Agh = Ah + z1 * sA1 + m0 * lda + kOff;
    const fp16* Agl = Al + z1 * sA1 + m0 * lda + kOff;
    const fp16* Bgh = Bh + z1 * sB1 + n0 * ldb + kOff;

    const uint32_t smb = s2u(sm);
    const int crow = t >> 2, cseg = t & 3;
    const int lm = lane >> 3, lr = lane & 7;
    const int a_off0 = (wm * 64 + (lm & 1) * 8 + lr) * 80 + (lm >> 1) * 16;
    const int b_off0 = (wn * WN + (lm >> 1) * 8 + lr) * 80 + (lm & 1) * 16;

    float acc[4][NSUB][4];
#pragma unroll
    for (int mi = 0; mi < 4; mi++)
#pragma unroll
        for (int ni = 0; ni < NSUB; ni++)
#pragma unroll
            for (int j = 0; j < 4; j++) acc[mi][ni][j] = 0.f;

    {
        const uint32_t st = smb;
#pragma unroll
        for (int i = 0; i < 4; i++) {
            int row = crow + i * 32;
            uint32_t d = st + row * 80 + cseg * 16;
            CPA(d,       Agh + (long)row * lda + cseg * 8);
            CPA(d + ABY, Agl + (long)row * lda + cseg * 8);
        }
#pragma unroll
        for (int i = 0; i < 4; i++) {
            int row = crow + i * 32;
            CPA(st + 2 * ABY + row * 80 + cseg * 16, Bgh + (long)row * ldb + cseg * 8);
        }
        CPC();
    }

    for (int ch = 0; ch < nch; ch++) {
        if (ch + 1 < nch) {
            const uint32_t st = smb + ((ch + 1) & 1) * STG;
            const fp16* ah = Agh + (ch + 1) * 32;
            const fp16* al = Agl + (ch + 1) * 32;
            const fp16* bh = Bgh + (ch + 1) * 32;
#pragma unroll
            for (int i = 0; i < 4; i++) {
                int row = crow + i * 32;
                uint32_t d = st + row * 80 + cseg * 16;
                CPA(d,       ah + (long)row * lda + cseg * 8);
                CPA(d + ABY, al + (long)row * lda + cseg * 8);
            }
#pragma unroll
            for (int i = 0; i < 4; i++) {
                int row = crow + i * 32;
                CPA(st + 2 * ABY + row * 80 + cseg * 16, bh + (long)row * ldb + cseg * 8);
            }
            CPC();
            CPW(1);
        } else {
            CPW(0);
        }
        __syncthreads();

        const uint32_t sbase = smb + (ch & 1) * STG;
#pragma unroll
        for (int ks = 0; ks < 2; ks++) {
            const int ko = ks * 32;
            uint32_t fa[16], fb[2 * NSUB];
            const uint32_t abase = sbase + a_off0 + ko;
            const uint32_t bbase = sbase + 2 * ABY + b_off0 + ko;
#pragma unroll
            for (int mi = 0; mi < 4; mi++) ldsm4(&fa[mi * 4], abase + mi * 1280);
#pragma unroll
            for (int np = 0; np < NSUB / 2; np++) ldsm4(&fb[np * 4], bbase + np * 1280);
#pragma unroll
            for (int mi = 0; mi < 4; mi++)
#pragma unroll
                for (int ni = 0; ni < NSUB; ni++)
                    mma_f16(acc[mi][ni], &fa[mi * 4], &fb[ni * 2]);     // hi*B
#pragma unroll
            for (int mi = 0; mi < 4; mi++) ldsm4(&fa[mi * 4], abase + ABY + mi * 1280);
#pragma unroll
            for (int mi = 0; mi < 4; mi++)
#pragma unroll
                for (int ni = 0; ni < NSUB; ni++)
                    mma_f16(acc[mi][ni], &fa[mi * 4], &fb[ni * 2]);     // lo*B
        }
        __syncthreads();
    }

    float* Cp = C ? (C + sk * sCk + z1 * sC1) : (float*)0;
#pragma unroll
    for (int mi = 0; mi < 4; mi++) {
        long r0 = m0 + wm * 64 + mi * 16 + g;
#pragma unroll
        for (int ni = 0; ni < NSUB; ni++) {
            long col = n0 + wn * WN + ni * 8 + tq * 2;
            float2 v0 = make_float2(acc[mi][ni][0], acc[mi][ni][1]);
            float2 v1 = make_float2(acc[mi][ni][2], acc[mi][ni][3]);
            if (Cp) {
                *(float2*)(Cp + r0 * ldc + col) = v0;
                *(float2*)(Cp + (r0 + 8) * ldc + col) = v1;
            }
            if (CbH) {
                long base = z1 * sC1;
                long i0 = base + r0 * ldc + col, i1 = base + (r0 + 8) * ldc + col;
                hsplit2(v0.x, v0.y, CbH, CbL, i0);
                hsplit2(v1.x, v1.y, CbH, CbL, i1);
            }
        }
    }
}

// ---------------- input transpose + bf16 split ----------------
__global__ void k_split_in(const float* __restrict__ tgt, const float* __restrict__ mem)
{
    long stride = (long)gridDim.x * blockDim.x;
    long base   = (long)blockIdx.x * blockDim.x + threadIdx.x;
    for (long p = base; p < (long)C_N * C_D / 2; p += stride) {
        const float* s = tgt + 6 * p;
        float2 a = *(const float2*)s, b = *(const float2*)(s + 2), c = *(const float2*)(s + 4);
        bsplit2(a.x, b.y, &g_Tb_h[0][0][0], &g_Tb_l[0][0][0], 2 * p);
        bsplit2(a.y, c.x, &g_Tb_h[1][0][0], &g_Tb_l[1][0][0], 2 * p);
        bsplit2(b.x, c.y, &g_Tb_h[2][0][0], &g_Tb_l[2][0][0], 2 * p);
    }
    for (long p = base; p < (long)C_E * C_D / 2; p += stride) {
        const float* s = mem + 6 * p;
        float2 a = *(const float2*)s, b = *(const float2*)(s + 2), c = *(const float2*)(s + 4);
        bsplit2(a.x, b.y, &g_Mb_h[0][0][0], &g_Mb_l[0][0][0], 2 * p);
        bsplit2(a.y, c.x, &g_Mb_h[1][0][0], &g_Mb_l[1][0][0], 2 * p);
        bsplit2(b.x, c.y, &g_Mb_h[2][0][0], &g_Mb_l[2][0][0], 2 * p);
    }
}

// ---------------- all weight splits in one kernel ----------------
__global__ void k_split_all(
    const float* __restrict__ Wsrc, const float* __restrict__ Wdst,
    const float* __restrict__ Wv,   const float* __restrict__ Wp,
    const float* __restrict__ Wf1,  const float* __restrict__ Wfd,
    const float* __restrict__ Wf2,  const float* __restrict__ Wa)
{
    const long SQ = (long)C_D * C_D;
    const long O4 = 4 * SQ;
    const long O5 = O4 + (long)C_FF * C_D;
    const long O6 = O5 + (long)C_FF * C_FF;
    const long O7 = O6 + (long)C_D * C_FF;
    const long O8 = O7 + (long)C_MA * C_D;
    long stride = (long)gridDim.x * blockDim.x;
    for (long i = (long)blockIdx.x * blockDim.x + threadIdx.x; i < O8; i += stride) {
        if (i < SQ)            bsplit(Wsrc[i],      g_Wsrc_h, g_Wsrc_l, i);
        else if (i < 2 * SQ)   bsplit(Wdst[i - SQ], g_Wdst_h, g_Wdst_l, i - SQ);
        else if (i < 3 * SQ)   bsplit(Wv[i - 2*SQ], g_Wv_h,   g_Wv_l,   i - 2*SQ);
        else if (i < 4 * SQ)   bsplit(Wp[i - 3*SQ], g_Wp_h,   g_Wp_l,   i - 3*SQ);
        else if (i < O5)       g_Wf1_f[i - O4] = __float2half_rn(Wf1[i - O4]);
        else if (i < O6)       g_Wfd_f[i - O5] = __float2half_rn(Wfd[i - O5]);
        else if (i < O7)       g_Wf2_f[i - O6] = __float2half_rn(Wf2[i - O6]);
        else {
            long k = i - O7;
            long r = k >> 6, c = k & 63;
            bsplit(Wa[k], g_Wa_h, g_Wa_l, c * C_D + r);
        }
    }
}

// ---------------- fused edge MLP ----------------
__global__ void __launch_bounds__(256) k_mlp(
    const float* __restrict__ es, const float* __restrict__ w1, const float* __restrict__ b1,
    const float* __restrict__ w2, const float* __restrict__ b2,
    const float* __restrict__ w3, const float* __restrict__ b3)
{
    __shared__ float s_es[64][65];
    __shared__ float s_w1[64][32];
    __shared__ float s_w2[32][32];
    __shared__ float s_h1[64][33];
    __shared__ float s_h2[64][33];
    const int t = threadIdx.x;
    const long e0 = (long)blockIdx.x * 64;

    for (int i = t; i < 64 * 32; i += 256) s_w1[i >> 5][i & 31] = w1[i];
    for (int i = t; i < 32 * 32; i += 256) s_w2[i >> 5][i & 31] = w2[i];
    for (int i = t; i < 64 * 64; i += 256) s_es[i >> 6][i & 63] = es[e0 * 64 + i];
    __syncthreads();

    for (int i = t; i < 64 * 32; i += 256) {
        int e = i >> 5, j = i & 31;
        float acc = b1[j];
#pragma unroll 8
        for (int c = 0; c < 64; c++) acc = fmaf(s_es[e][c], s_w1[c][j], acc);
        s_h1[e][j] = acc / (1.f + expf(-acc));
    }
    __syncthreads();
    for (int i = t; i < 64 * 32; i += 256) {
        int e = i >> 5, j = i & 31;
        float acc = b2[j];
#pragma unroll 8
        for (int c = 0; c < 32; c++) acc = fmaf(s_h1[e][c], s_w2[c][j], acc);
        s_h2[e][j] = acc / (1.f + expf(-acc));
    }
    __syncthreads();
    for (int i = t; i < 64 * 1536; i += 256) {
        int e = i / 1536, o = i - e * 1536;
        float acc = b3[o];
#pragma unroll 8
        for (int c = 0; c < 32; c++) acc = fmaf(s_h2[e][c], w3[c * 1536 + o], acc);
        g_w[e0 + e][o] = acc;
    }
}

// ---------------- pointwise equivariant products ----------------
__global__ void k_pointwise(const float* __restrict__ esh)
{
    long stride = (long)gridDim.x * blockDim.x;
    for (long p = (long)blockIdx.x * blockDim.x + threadIdx.x; p < (long)C_E * C_D / 2; p += stride) {
        int  c = (int)(p & 255) * 2;
        long e = p >> 8;
        float s  = esh[e * 4 + 0];
        float v0 = esh[e * 4 + 1], v1 = esh[e * 4 + 2], v2 = esh[e * 4 + 3];
        float2 m0 = *(const float2*)&g_MSG[0][e][c];
        float2 m1 = *(const float2*)&g_MSG[1][e][c];
        float2 m2 = *(const float2*)&g_MSG[2][e][c];
        float2 w0 = *(const float2*)&g_w[e][c];
        float2 w1 = *(const float2*)&g_w[e][512 + c];
        float2 w2 = *(const float2*)&g_w[e][1024 + c];
        float p0 = w0.x * (m0.x * v0 + m1.x * v1 + m2.x * v2) * 0.5773502691896258f;
        float p1 = w0.y * (m0.y * v0 + m1.y * v1 + m2.y * v2) * 0.5773502691896258f;
        bsplit2(p0, p1, &g_pscb_h[0][0], &g_pscb_l[0][0], e * C_D + c);
        float k2x = w2.x * 0.7071067811865475f, k2y = w2.y * 0.7071067811865475f;
        float wsx = w1.x * s, wsy = w1.y * s;
        *(float2*)&g_PV[0][e][c] = make_float2(wsx * m0.x + k2x * (m1.x * v2 - m2.x * v1),
                                               wsy * m0.y + k2y * (m1.y * v2 - m2.y * v1));
        *(float2*)&g_PV[1][e][c] = make_float2(wsx * m1.x + k2x * (m2.x * v0 - m0.x * v2),
                                               wsy * m1.y + k2y * (m2.y * v0 - m0.y * v2));
        *(float2*)&g_PV[2][e][c] = make_float2(wsx * m2.x + k2x * (m0.x * v1 - m1.x * v0),
                                               wsy * m2.y + k2y * (m0.y * v1 - m1.y * v0));
    }
}

// ---------------- fused alpha post + softmax (reduces 2 split-K partials) ----------------
__global__ void __launch_bounds__(512) k_alpha(const float* __restrict__ gg, const float* __restrict__ bb,
                                               const float* __restrict__ adot)
{
    int n = blockIdx.x;
    int t = threadIdx.x, wid = t >> 5, lane = t & 31;
    __shared__ float s_l[16][8];
    int e = n * 16 + wid;
    float v0 = g_araw[0][e][lane * 2]     + g_araw[1][e][lane * 2];
    float v1 = g_araw[0][e][lane * 2 + 1] + g_araw[1][e][lane * 2 + 1];
    float s = v0 + v1, s2 = v0 * v0 + v1 * v1;
#pragma unroll
    for (int o = 16; o > 0; o >>= 1) {
        s  += __shfl_xor_sync(0xffffffffu, s, o);
        s2 += __shfl_xor_sync(0xffffffffu, s2, o);
    }
    float mu  = s * (1.f / 64.f);
    float var = s2 * (1.f / 64.f) - mu * mu;
    float inv = rsqrtf(var + C_EPS);
    float a0 = (v0 - mu) * inv * gg[lane * 2]     + bb[lane * 2];
    float a1 = (v1 - mu) * inv * gg[lane * 2 + 1] + bb[lane * 2 + 1];
    a0 = 0.6f * a0 + 0.4f * a0 * tanhf(0.5f * a0);
    a1 = 0.6f * a1 + 0.4f * a1 * tanhf(0.5f * a1);
    int h = lane >> 2;
    int m = (lane & 3) * 2;
    float p = a0 * adot[h * 8 + m] + a1 * adot[h * 8 + m + 1];
    p += __shfl_xor_sync(0xffffffffu, p, 1);
    p += __shfl_xor_sync(0xffffffffu, p, 2);
    if ((lane & 3) == 0) s_l[wid][h] = p;
    __syncthreads();
    if (t < 8) {
        float mx = -1e30f;
#pragma unroll
        for (int k = 0; k < 16; k++) mx = fmaxf(mx, s_l[k][t]);
        float sum = 0.f; float ex[16];
#pragma unroll
        for (int k = 0; k < 16; k++) { ex[k] = expf(s_l[k][t] - mx); sum += ex[k]; }
        float is = 1.f / sum;
#pragma unroll
        for (int k = 0; k < 16; k++) g_att[n * 16 + k][t] = ex[k] * is;
    }
}

// ---------------- z = sum_k att * pv ----------------
__global__ void __launch_bounds__(256) k_z()
{
    int n = blockIdx.x, x = blockIdx.y;
    __shared__ float s_a[16][8];
    if (threadIdx.x < 128)
        s_a[threadIdx.x >> 3][threadIdx.x & 7] = g_att[n * 16 + (threadIdx.x >> 3)][threadIdx.x & 7];
    __syncthreads();
    int c = threadIdx.x * 2;
    float2 acc[8];
#pragma unroll
    for (int h = 0; h < 8; h++) acc[h] = make_float2(0.f, 0.f);
#pragma unroll
    for (int k = 0; k < 16; k++) {
        float2 pv = *(const float2*)&g_PV[x][n * 16 + k][c];
#pragma unroll
        for (int h = 0; h < 8; h++) {
            acc[h].x = fmaf(s_a[k][h], pv.x, acc[h].x);
            acc[h].y = fmaf(s_a[k][h], pv.y, acc[h].y);
        }
    }
#pragma unroll
    for (int h = 0; h < 8; h++) {
        long idx = (((long)x * C_N + n) * C_H + h) * C_D + c;
        bsplit2(acc[h].x, acc[h].y, &g_Zb_h[0][0][0][0], &g_Zb_l[0][0][0][0], idx);
    }
}

// ---------------- vn_ln with fused split-K partial reduction ----------------
// pair output: bf16 (bH/bL) or fp16 (fH/fL) — at most one set non-null.
__global__ void __launch_bounds__(256) k_vnln(const float* __restrict__ Xin,
                                              const float* __restrict__ Parts, int nparts, long pstride,
                                              float* __restrict__ Xout,
                                              fp16* __restrict__ fH, fp16* __restrict__ fL,
                                              const float* __restrict__ gg, const float* __restrict__ bb,
                                              int inter)
{
    int n = blockIdx.x, t = threadIdx.x;
    const long P = (long)C_N * C_D;
    __shared__ float rs[8], rs2[8];
    __shared__ float smu, sinv;
    float xv[2][3], nc[2];
    float s = 0.f, s2 = 0.f;
#pragma unroll
    for (int i = 0; i < 2; i++) {
        int c = t * 2 + i;
#pragma unroll
        for (int xx = 0; xx < 3; xx++) {
            long idx = xx * P + (long)n * C_D + c;
            float v = Xin[idx];
            for (int pp = 0; pp < nparts; pp++) v += Parts[pp * pstride + idx];
            xv[i][xx] = v;
        }
        float v = sqrtf(xv[i][0] * xv[i][0] + xv[i][1] * xv[i][1] + xv[i][2] * xv[i][2] + C_EPS);
        nc[i] = v; s += v; s2 = fmaf(v, v, s2);
    }
#pragma unroll
    for (int o = 16; o > 0; o >>= 1) {
        s  += __shfl_xor_sync(0xffffffffu, s, o);
        s2 += __shfl_xor_sync(0xffffffffu, s2, o);
    }
    if ((t & 31) == 0) { rs[t >> 5] = s; rs2[t >> 5] = s2; }
    __syncthreads();
    if (t == 0) {
        float S = 0.f, S2 = 0.f;
        for (int i = 0; i < 8; i++) { S += rs[i]; S2 += rs2[i]; }
        float mu  = S * (1.f / 512.f);
        float var = S2 * (1.f / 512.f) - mu * mu;
        smu = mu; sinv = rsqrtf(var + C_EPS);
    }
    __syncthreads();
    float sc[2];
#pragma unroll
    for (int i = 0; i < 2; i++) {
        int c = t * 2 + i;
        float ln = (nc[i] - smu) * sinv * gg[c] + bb[c];
        sc[i] = ln / nc[i];
    }
    if (inter) {
#pragma unroll
        for (int i = 0; i < 2; i++) {
            int c = t * 2 + i;
#pragma unroll
            for (int xx = 0; xx < 3; xx++) Xout[(long)n * 1536 + c * 3 + xx] = xv[i][xx] * sc[i];
        }
    } else {
#pragma unroll
        for (int xx = 0; xx < 3; xx++) {
            long idx = xx * P + (long)n * C_D + t * 2;
            float o0 = xv[0][xx] * sc[0], o1 = xv[1][xx] * sc[1];
            *(float2*)(Xout + idx) = make_float2(o0, o1);
            if (fH) hsplit2(o0, o1, fH, fL, idx);
        }
    }
}

// ---------------- FF gating with fused DV partial reduction (fp16 pair out) ----------------
__global__ void k_gate()
{
    const long P = (long)C_N * C_FF;
    const float* Y  = &g_Y[0][0][0];
    const float* D0 = &g_DVP[0][0][0][0];
    const float* D1 = &g_DVP[1][0][0][0];
    long stride = (long)gridDim.x * blockDim.x;
    for (long p = (long)blockIdx.x * blockDim.x + threadIdx.x; p < P / 2; p += stride) {
        long i = 2 * p;
        float2 y0 = *(const float2*)(Y + i), y1 = *(const float2*)(Y + P + i), y2 = *(const float2*)(Y + 2 * P + i);
        float2 a0 = *(const float2*)(D0 + i), a1 = *(const float2*)(D0 + P + i), a2 = *(const float2*)(D0 + 2 * P + i);
        float2 b0 = *(const float2*)(D1 + i), b1 = *(const float2*)(D1 + P + i), b2 = *(const float2*)(D1 + 2 * P + i);
        float2 d0 = make_float2(a0.x + b0.x, a0.y + b0.y);
        float2 d1 = make_float2(a1.x + b1.x, a1.y + b1.y);
        float2 d2 = make_float2(a2.x + b2.x, a2.y + b2.y);
        float dotx = y0.x * d0.x + y1.x * d1.x + y2.x * d2.x;
        float doty = y0.y * d0.y + y1.y * d1.y + y2.y * d2.y;
        float fx = (dotx >= 0.f) ? 0.f : 0.8f * dotx / (d0.x * d0.x + d1.x * d1.x + d2.x * d2.x + C_EPS);
        float fy = (doty >= 0.f) ? 0.f : 0.8f * doty / (d0.y * d0.y + d1.y * d1.y + d2.y * d2.y + C_EPS);
        hsplit2(y0.x - fx * d0.x, y0.y - fy * d0.y, &g_Y2f_h[0][0][0], &g_Y2f_l[0][0][0], i);
        hsplit2(y1.x - fx * d1.x, y1.y - fy * d1.y, &g_Y2f_h[0][0][0], &g_Y2f_l[0][0][0], P + i);
        hsplit2(y2.x - fx * d2.x, y2.y - fy * d2.y, &g_Y2f_h[0][0][0], &g_Y2f_l[0][0][0], 2 * P + i);
    }
}

// ---------------- host launch ----------------
extern "C" void kernel_launch(void* const* d_in, const int* in_sizes, int n_in,
                              void* d_out, int out_size)
{
    const float* tgt    = (const float*)d_in[0];
    const float* mem    = (const float*)d_in[1];
    const float* esh    = (const float*)d_in[2];
    const float* escal  = (const float*)d_in[3];
    const float* W_src  = (const float*)d_in[4];
    const float* W_dst  = (const float*)d_in[5];
    const float* fc_w1  = (const float*)d_in[6];
    const float* fc_b1  = (const float*)d_in[7];
    const float* fc_w2  = (const float*)d_in[8];
    const float* fc_b2  = (const float*)d_in[9];
    const float* fc_w3  = (const float*)d_in[10];
    const float* fc_b3  = (const float*)d_in[11];
    const float* W_alpha= (const float*)d_in[12];
    const float* ln_a_g = (const float*)d_in[13];
    const float* ln_a_b = (const float*)d_in[14];
    const float* adot   = (const float*)d_in[15];
    const float* W_value= (const float*)d_in[16];
    const float* W_proj = (const float*)d_in[17];
    const float* n1_g   = (const float*)d_in[18];
    const float* n1_b   = (const float*)d_in[19];
    const float* n2_g   = (const float*)d_in[20];
    const float* n2_b   = (const float*)d_in[21];
    const float* W_ff1  = (const float*)d_in[22];
    const float* W_ffd  = (const float*)d_in[23];
    const float* W_ff2  = (const float*)d_in[24];

#define SYM(p, s) cudaGetSymbolAddress((void**)&p, s)
    float *pTV, *pMSG, *paraw, *pX1, *pY, *pPRJ, *pFF2, *pDVP;
    SYM(pTV, g_TV); SYM(pMSG, g_MSG); SYM(paraw, g_araw);
    SYM(pX1, g_X1); SYM(pY, g_Y);
    SYM(pPRJ, g_PRJP); SYM(pFF2, g_FF2P); SYM(pDVP, g_DVP);
    bf16 *pTbh, *pTbl, *pMbh, *pMbl, *ppsh, *ppsl, *pZh, *pZl, *pOh, *pOl;
    SYM(pTbh, g_Tb_h); SYM(pTbl, g_Tb_l); SYM(pMbh, g_Mb_h); SYM(pMbl, g_Mb_l);
    SYM(ppsh, g_pscb_h); SYM(ppsl, g_pscb_l); SYM(pZh, g_Zb_h); SYM(pZl, g_Zb_l);
    SYM(pOh, g_OUTb_h); SYM(pOl, g_OUTb_l);
    fp16 *pX1fh, *pX1fl, *pYfh, *pYfl, *pY2fh, *pY2fl, *pWf1f, *pWfdf, *pWf2f;
    SYM(pX1fh, g_X1f_h); SYM(pX1fl, g_X1f_l); SYM(pYfh, g_Yf_h); SYM(pYfl, g_Yf_l);
    SYM(pY2fh, g_Y2f_h); SYM(pY2fl, g_Y2f_l);
    SYM(pWf1f, g_Wf1_f); SYM(pWfdf, g_Wfd_f); SYM(pWf2f, g_Wf2_f);
    bf16 *pWsh, *pWsl, *pWdh, *pWdl, *pWah, *pWal, *pWvh, *pWvl, *pWph, *pWpl;
    SYM(pWsh, g_Wsrc_h); SYM(pWsl, g_Wsrc_l); SYM(pWdh, g_Wdst_h); SYM(pWdl, g_Wdst_l);
    SYM(pWah, g_Wa_h); SYM(pWal, g_Wa_l); SYM(pWvh, g_Wv_h); SYM(pWvl, g_Wv_l);
    SYM(pWph, g_Wp_h); SYM(pWpl, g_Wp_l);
#undef SYM

    const long NP_D  = (long)C_N * C_D;
    const long EP_D  = (long)C_E * C_D;
    const long NP_FF = (long)C_N * C_FF;
    const long NHD   = (long)C_N * C_H * C_D;

    const int SM128 = 2 * (2 * 10240 + 2 * 128 * 80);   // 81920
    const int SM64  = 2 * (2 * 10240 + 2 * 64 * 80);    // 61440
    const int SMH   = 2 * (2 * 10240 + 128 * 80);       // 61440
    cudaFuncSetAttribute(gemm_bf<128>, cudaFuncAttributeMaxDynamicSharedMemorySize, SM128);
    cudaFuncSetAttribute(gemm_bf<64>,  cudaFuncAttributeMaxDynamicSharedMemorySize, SM64);
    cudaFuncSetAttribute(gemm_hf,      cudaFuncAttributeMaxDynamicSharedMemorySize, SMH);

    // 1) input + weight splits
    k_split_in<<<4096, 256>>>(tgt, mem);
    k_split_all<<<8192, 256>>>(W_src, W_dst, W_value, W_proj, W_ff1, W_ffd, W_ff2, W_alpha);

    // 2) tv = W_dst @ tgt
    gemm_bf<128><<<dim3(4, 8, 3), 128, SM128>>>(pTbh, pTbl, pWdh, pWdl, pTV, nullptr, nullptr, nullptr,
        C_D, C_D, C_D, C_D, NP_D, 0, 0, 0, NP_D, 0, 1, 1, 0, 0, 1, 3, 0);

    // 3) msg = W_src @ memory + tv[e/K]
    gemm_bf<128><<<dim3(4, 128, 3), 128, SM128>>>(pMbh, pMbl, pWsh, pWsl, pMSG, pTV, nullptr, nullptr,
        C_D, C_D, C_D, C_D, EP_D, 0, 0, 0, EP_D, 0, 1, C_K, C_D, NP_D, 1, 3, 0);

    // 4) edge MLP -> g_w
    k_mlp<<<C_E / 64, 256>>>(escal, fc_w1, fc_b1, fc_w2, fc_b2, fc_w3, fc_b3);

    // 5) p_sc / pv
    k_pointwise<<<2048, 256>>>(esh);

    // 6) a_raw = p_sc @ W_alpha (split-K=2 -> reduced in k_alpha)
    gemm_bf<64><<<dim3(1, 128, 2), 128, SM64>>>(ppsh, ppsl, pWah, pWal, paraw, nullptr, nullptr, nullptr,
        C_D, C_D, C_MA, C_D, 0, 0, 0, 0, 0, 0, 1, 1, 0, 0, 2, 1, (long)C_E * C_MA);

    // 7) fused LN + lrelu + head dot + softmax
    k_alpha<<<C_N, 512>>>(ln_a_g, ln_a_b, adot);

    // 8) z = sum_k att * pv
    k_z<<<dim3(C_N, 3), 256>>>();

    // 9) out = W_value @ z (per head, bf16 out), then proj (split-K=2)
    gemm_bf<64><<<dim3(1, 8, 24), 128, SM64>>>(pZh, pZl, pWvh, pWvl, nullptr, nullptr, pOh, pOl,
        C_H * C_D, C_D, C_D, C_D, NHD, C_D, 0, 64 * C_D, NP_D, 64, C_H, 1, 0, 0, 1, 24, 0);
    gemm_bf<128><<<dim3(4, 8, 6), 128, SM128>>>(pOh, pOl, pWph, pWpl, pPRJ, nullptr, nullptr, nullptr,
        C_D, C_D, C_D, C_D, NP_D, 0, 0, 0, NP_D, 0, 1, 1, 0, 0, 2, 3, 3 * NP_D);

    // 10) vn_ln #1 (fp32 + fp16 pairs for ff1)
    k_vnln<<<C_N, 256>>>(pTV, pPRJ, 2, 3 * NP_D, pX1, pX1fh, pX1fl, n1_g, n1_b, 0);

    // 11) FF block: ff1 (fp16 2-pass), ffd (fp16 2-pass, split-K=2), ff2 (fp16 2-pass, split-K=4)
    gemm_hf<<<dim3(16, 8, 3), 128, SMH>>>(pX1fh, pX1fl, pWf1f, pY, pYfh, pYfl,
        C_D, C_D, C_FF, C_D, NP_D, 0, NP_FF, 1, 3, 0);
    gemm_hf<<<dim3(16, 8, 6), 128, SMH>>>(pYfh, pYfl, pWfdf, pDVP, nullptr, nullptr,
        C_FF, C_FF, C_FF, C_FF, NP_FF, 0, NP_FF, 2, 3, 3 * NP_FF);
    k_gate<<<2048, 256>>>();
    gemm_hf<<<dim3(4, 8, 12), 128, SMH>>>(pY2fh, pY2fl, pWf2f, pFF2, nullptr, nullptr,
        C_FF, C_FF, C_D, C_FF, NP_FF, 0, NP_D, 4, 3, 3 * NP_D);

    // 12) vn_ln #2 -> interleaved output
    k_vnln<<<C_N, 256>>>(pX1, pFF2, 4, 3 * NP_D, (float*)d_out, nullptr, nullptr, n2_g, n2_b, 1);
}

// round 16
// speedup vs baseline: 1.3986x; 1.1552x over previous
#include <cuda_runtime.h>
#include <cuda_bf16.h>
#include <cuda_fp16.h>
#include <math.h>
#include <stdint.h>

// ---------------- problem constants ----------------
#define C_N   1024
#define C_K   16
#define C_D   512
#define C_H   8
#define C_FF  2048
#define C_MA  64
#define C_ES  64
#define C_E   (C_N * C_K)      // 16384
#define C_EPS 1e-6f

typedef __nv_bfloat16 bf16;
typedef __half fp16;

// ---------------- fp32 scratch ----------------
__device__ float g_TV  [3][C_N][C_D];
__device__ float g_MSG [3][C_E][C_D];
__device__ float g_w   [C_E][3*C_D];
__device__ float g_PV  [3][C_E][C_D];
__device__ float g_araw[2][C_E][C_MA];
__device__ float g_att [C_E][C_H];
__device__ float g_X1  [3][C_N][C_D];
__device__ float g_Y   [3][C_N][C_FF];
// split-K partial buffers
__device__ float g_PRJP[2][3][C_N][C_D];
__device__ float g_FF2P[4][3][C_N][C_D];
__device__ float g_DVP [2][3][C_N][C_FF];

// ---------------- bf16 hi/lo pairs (GEMM operands) ----------------
__device__ __align__(128) bf16 g_Tb_h [3][C_N][C_D],        g_Tb_l [3][C_N][C_D];
__device__ __align__(128) bf16 g_Mb_h [3][C_E][C_D],        g_Mb_l [3][C_E][C_D];
__device__ __align__(128) bf16 g_pscb_h[C_E][C_D],          g_pscb_l[C_E][C_D];
__device__ __align__(128) bf16 g_Zb_h [3][C_N][C_H][C_D],   g_Zb_l [3][C_N][C_H][C_D];
__device__ __align__(128) bf16 g_OUTb_h[3][C_N][C_D],       g_OUTb_l[3][C_N][C_D];
// fp16 pairs (FF block path)
__device__ __align__(128) fp16 g_X1f_h[3][C_N][C_D],        g_X1f_l[3][C_N][C_D];
__device__ __align__(128) fp16 g_Yf_h [3][C_N][C_FF],       g_Yf_l [3][C_N][C_FF];
__device__ __align__(128) fp16 g_Y2f_h[3][C_N][C_FF],       g_Y2f_l[3][C_N][C_FF];
// weights
__device__ __align__(128) bf16 g_Wsrc_h[C_D*C_D],  g_Wsrc_l[C_D*C_D];
__device__ __align__(128) bf16 g_Wdst_h[C_D*C_D],  g_Wdst_l[C_D*C_D];
__device__ __align__(128) bf16 g_Wa_h  [C_MA*C_D], g_Wa_l  [C_MA*C_D];
__device__ __align__(128) bf16 g_Wv_h  [C_D*C_D],  g_Wv_l  [C_D*C_D];
__device__ __align__(128) bf16 g_Wp_h  [C_D*C_D],  g_Wp_l  [C_D*C_D];
__device__ __align__(128) fp16 g_Wf1_f [C_FF*C_D];
__device__ __align__(128) fp16 g_Wfd_f [C_FF*C_FF];
__device__ __align__(128) fp16 g_Wf2_f [C_D*C_FF];

// ---------------- helpers ----------------
__device__ __forceinline__ void bsplit(float v, bf16* H, bf16* L, long i) {
    bf16 h = __float2bfloat16_rn(v);
    H[i] = h;
    L[i] = __float2bfloat16_rn(v - __bfloat162float(h));
}
__device__ __forceinline__ void bsplit2(float v0, float v1, bf16* H, bf16* L, long i) {
    bf16 h0 = __float2bfloat16_rn(v0), h1 = __float2bfloat16_rn(v1);
    *(__nv_bfloat162*)(H + i) = __nv_bfloat162(h0, h1);
    *(__nv_bfloat162*)(L + i) = __nv_bfloat162(
        __float2bfloat16_rn(v0 - __bfloat162float(h0)),
        __float2bfloat16_rn(v1 - __bfloat162float(h1)));
}
__device__ __forceinline__ void hsplit2(float v0, float v1, fp16* H, fp16* L, long i) {
    fp16 h0 = __float2half_rn(v0), h1 = __float2half_rn(v1);
    *(__half2*)(H + i) = __half2(h0, h1);
    *(__half2*)(L + i) = __half2(
        __float2half_rn(v0 - __half2float(h0)),
        __float2half_rn(v1 - __half2float(h1)));
}
__device__ __forceinline__ uint32_t s2u(const void* p) {
    uint32_t a;
    asm("{ .reg .u64 t; cvta.to.shared.u64 t, %1; cvt.u32.u64 %0, t; }" : "=r"(a) : "l"(p));
    return a;
}
__device__ __forceinline__ void mma_bf16(float* c, const uint32_t* a, const uint32_t* b) {
    asm volatile("mma.sync.aligned.m16n8k16.row.col.f32.bf16.bf16.f32 "
                 "{%0,%1,%2,%3},{%4,%5,%6,%7},{%8,%9},{%0,%1,%2,%3};"
                 : "+f"(c[0]), "+f"(c[1]), "+f"(c[2]), "+f"(c[3])
                 : "r"(a[0]), "r"(a[1]), "r"(a[2]), "r"(a[3]), "r"(b[0]), "r"(b[1]));
}
__device__ __forceinline__ void mma_f16(float* c, const uint32_t* a, const uint32_t* b) {
    asm volatile("mma.sync.aligned.m16n8k16.row.col.f32.f16.f16.f32 "
                 "{%0,%1,%2,%3},{%4,%5,%6,%7},{%8,%9},{%0,%1,%2,%3};"
                 : "+f"(c[0]), "+f"(c[1]), "+f"(c[2]), "+f"(c[3])
                 : "r"(a[0]), "r"(a[1]), "r"(a[2]), "r"(a[3]), "r"(b[0]), "r"(b[1]));
}
__device__ __forceinline__ void ldsm4(uint32_t* r, uint32_t addr) {
    asm volatile("ldmatrix.sync.aligned.m8n8.x4.shared.b16 {%0,%1,%2,%3}, [%4];"
        : "=r"(r[0]), "=r"(r[1]), "=r"(r[2]), "=r"(r[3]) : "r"(addr));
}
#define CPA(d, s) asm volatile("cp.async.cg.shared.global [%0], [%1], 16;" :: "r"(d), "l"(s) : "memory")
#define CPC()     asm volatile("cp.async.commit_group;" ::: "memory")
#define CPW(n)    asm volatile("cp.async.wait_group %0;" :: "n"(n) : "memory")

// ============ bf16-pair NT GEMM (3 HMMA passes), optional split-K ============
template<int BN>
__global__ void __launch_bounds__(128, 2) gemm_bf(
    const bf16* __restrict__ Ah, const bf16* __restrict__ Al,
    const bf16* __restrict__ Bh, const bf16* __restrict__ Bl,
    float* __restrict__ C, const float* __restrict__ Add,
    bf16* __restrict__ CbH, bf16* __restrict__ CbL,
    int lda, int ldb, int ldc, int Kc,
    long sA1, long sA2, long sB1, long sB2, long sC1, long sC2, int nz2,
    int addDiv, int ldadd, long sAdd1,
    int nsplit, int nzTot, long sCk)
{
    constexpr int WN   = BN / 2;
    constexpr int NSUB = WN / 8;
    constexpr int ABY  = 10240;
    constexpr int BBY  = BN * 80;
    constexpr int STG  = 2 * ABY + 2 * BBY;

    extern __shared__ __align__(16) char sm[];
    const int t = threadIdx.x, wid = t >> 5, lane = t & 31;
    const int g = lane >> 2, tq = lane & 3;
    const int wm = wid & 1, wn = wid >> 1;

    const int bz = blockIdx.z;
    const int sk = bz / nzTot;
    const int z  = bz - sk * nzTot;
    const int z1 = z / nz2, z2 = z - z1 * nz2;
    const int nch = (Kc >> 5) / nsplit;
    const long kOff = (long)sk * nch * 32;

    const long m0 = (long)blockIdx.y * 128, n0 = (long)blockIdx.x * BN;
    const bf16* Agh = Ah + z1 * sA1 + z2 * sA2 + m0 * lda + kOff;
    const bf16* Agl = Al + z1 * sA1 + z2 * sA2 + m0 * lda + kOff;
    const bf16* Bgh = Bh + z1 * sB1 + z2 * sB2 + n0 * ldb + kOff;
    const bf16* Bgl = Bl + z1 * sB1 + z2 * sB2 + n0 * ldb + kOff;

    const uint32_t smb = s2u(sm);
    const int crow = t >> 2, cseg = t & 3;

    const int lm = lane >> 3, lr = lane & 7;
    const int a_off0 = (wm * 64 + (lm & 1) * 8 + lr) * 80 + (lm >> 1) * 16;
    const int b_off0 = (wn * WN + (lm >> 1) * 8 + lr) * 80 + (lm & 1) * 16;

    float acc[4][NSUB][4];
#pragma unroll
    for (int mi = 0; mi < 4; mi++)
#pragma unroll
        for (int ni = 0; ni < NSUB; ni++)
#pragma unroll
            for (int j = 0; j < 4; j++) acc[mi][ni][j] = 0.f;

    {
        const uint32_t st = smb;
#pragma unroll
        for (int i = 0; i < 4; i++) {
            int row = crow + i * 32;
            uint32_t d = st + row * 80 + cseg * 16;
            CPA(d,       Agh + (long)row * lda + cseg * 8);
            CPA(d + ABY, Agl + (long)row * lda + cseg * 8);
        }
#pragma unroll
        for (int i = 0; i < BN / 32; i++) {
            int row = crow + i * 32;
            uint32_t d = st + 2 * ABY + row * 80 + cseg * 16;
            CPA(d,       Bgh + (long)row * ldb + cseg * 8);
            CPA(d + BBY, Bgl + (long)row * ldb + cseg * 8);
        }
        CPC();
    }

    for (int ch = 0; ch < nch; ch++) {
        if (ch + 1 < nch) {
            const uint32_t st = smb + ((ch + 1) & 1) * STG;
            const bf16* ah = Agh + (ch + 1) * 32;
            const bf16* al = Agl + (ch + 1) * 32;
            const bf16* bh = Bgh + (ch + 1) * 32;
            const bf16* bl = Bgl + (ch + 1) * 32;
#pragma unroll
            for (int i = 0; i < 4; i++) {
                int row = crow + i * 32;
                uint32_t d = st + row * 80 + cseg * 16;
                CPA(d,       ah + (long)row * lda + cseg * 8);
                CPA(d + ABY, al + (long)row * lda + cseg * 8);
            }
#pragma unroll
            for (int i = 0; i < BN / 32; i++) {
                int row = crow + i * 32;
                uint32_t d = st + 2 * ABY + row * 80 + cseg * 16;
                CPA(d,       bh + (long)row * ldb + cseg * 8);
                CPA(d + BBY, bl + (long)row * ldb + cseg * 8);
            }
            CPC();
            CPW(1);
        } else {
            CPW(0);
        }
        __syncthreads();

        const uint32_t sbase = smb + (ch & 1) * STG;
#pragma unroll
        for (int ks = 0; ks < 2; ks++) {
            const int ko = ks * 32;
            uint32_t fa[16], fbh[2 * NSUB], fbl[2 * NSUB];
            const uint32_t abase = sbase + a_off0 + ko;
            const uint32_t bbase = sbase + 2 * ABY + b_off0 + ko;
#pragma unroll
            for (int mi = 0; mi < 4; mi++) ldsm4(&fa[mi * 4], abase + mi * 1280);
#pragma unroll
            for (int np = 0; np < NSUB / 2; np++) ldsm4(&fbh[np * 4], bbase + np * 1280);
#pragma unroll
            for (int mi = 0; mi < 4; mi++)
#pragma unroll
                for (int ni = 0; ni < NSUB; ni++)
                    mma_bf16(acc[mi][ni], &fa[mi * 4], &fbh[ni * 2]);
#pragma unroll
            for (int np = 0; np < NSUB / 2; np++) ldsm4(&fbl[np * 4], bbase + BBY + np * 1280);
#pragma unroll
            for (int mi = 0; mi < 4; mi++)
#pragma unroll
                for (int ni = 0; ni < NSUB; ni++)
                    mma_bf16(acc[mi][ni], &fa[mi * 4], &fbl[ni * 2]);
#pragma unroll
            for (int mi = 0; mi < 4; mi++) ldsm4(&fa[mi * 4], abase + ABY + mi * 1280);
#pragma unroll
            for (int mi = 0; mi < 4; mi++)
#pragma unroll
                for (int ni = 0; ni < NSUB; ni++)
                    mma_bf16(acc[mi][ni], &fa[mi * 4], &fbh[ni * 2]);
        }
        __syncthreads();
    }

    float* Cp = C ? (C + sk * sCk + z1 * sC1 + z2 * sC2) : (float*)0;
    const float* Ad = Add ? (Add + z1 * sAdd1) : (const float*)0;
#pragma unroll
    for (int mi = 0; mi < 4; mi++) {
        long r0 = m0 + wm * 64 + mi * 16 + g;
#pragma unroll
        for (int ni = 0; ni < NSUB; ni++) {
            long col = n0 + wn * WN + ni * 8 + tq * 2;
            float2 v0 = make_float2(acc[mi][ni][0], acc[mi][ni][1]);
            float2 v1 = make_float2(acc[mi][ni][2], acc[mi][ni][3]);
            if (Ad) {
                float2 a0 = *(const float2*)(Ad + (r0 / addDiv) * (long)ldadd + col);
                float2 a1 = *(const float2*)(Ad + ((r0 + 8) / addDiv) * (long)ldadd + col);
                v0.x += a0.x; v0.y += a0.y; v1.x += a1.x; v1.y += a1.y;
            }
            if (Cp) {
                *(float2*)(Cp + r0 * ldc + col) = v0;
                *(float2*)(Cp + (r0 + 8) * ldc + col) = v1;
            }
            if (CbH) {
                long base = z1 * sC1 + z2 * sC2;
                long i0 = base + r0 * ldc + col, i1 = base + (r0 + 8) * ldc + col;
                bsplit2(v0.x, v0.y, CbH, CbL, i0);
                bsplit2(v1.x, v1.y, CbH, CbL, i1);
            }
        }
    }
}

// ============ fp16 2-pass NT GEMM (A hi/lo, B single), split-K, optional fp16-pair out ============
__global__ void __launch_bounds__(128, 2) gemm_hf(
    const fp16* __restrict__ Ah, const fp16* __restrict__ Al,
    const fp16* __restrict__ Bh,
    float* __restrict__ C,
    fp16* __restrict__ CbH, fp16* __restrict__ CbL,
    int lda, int ldb, int ldc, int Kc,
    long sA1, long sB1, long sC1,
    int nsplit, int nzTot, long sCk)
{
    constexpr int BN = 128, WN = 64, NSUB = 8;
    constexpr int ABY = 10240;
    constexpr int BBY = BN * 80;
    constexpr int STG = 2 * ABY + BBY;

    extern __shared__ __align__(16) char sm[];
    const int t = threadIdx.x, wid = t >> 5, lane = t & 31;
    const int g = lane >> 2, tq = lane & 3;
    const int wm = wid & 1, wn = wid >> 1;

    const int bz = blockIdx.z;
    const int sk = bz / nzTot;
    const int z1 = bz - sk * nzTot;
    const int nch = (Kc >> 5) / nsplit;
    const long kOff = (long)sk * nch * 32;

    const long m0 = (long)blockIdx.y * 128, n0 = (long)blockIdx.x * BN;
    const fp16* Agh = Ah + z1 * sA1 + m0 * lda + kOff;
    const fp16* Agl = Al + z1 * sA1 + m0 * lda + kOff;
    const fp16* Bgh = Bh + z1 * sB1 + n0 * ldb + kOff;

    const uint32_t smb = s2u(sm);
    const int crow = t >> 2, cseg = t & 3;
    const int lm = lane >> 3, lr = lane & 7;
    const int a_off0 = (wm * 64 + (lm & 1) * 8 + lr) * 80 + (lm >> 1) * 16;
    const int b_off0 = (wn * WN + (lm >> 1) * 8 + lr) * 80 + (lm & 1) * 16;

    float acc[4][NSUB][4];
#pragma unroll
    for (int mi = 0; mi < 4; mi++)
#pragma unroll
        for (int ni = 0; ni < NSUB; ni++)
#pragma unroll
            for (int j = 0; j < 4; j++) acc[mi][ni][j] = 0.f;

    {
        const uint32_t st = smb;
#pragma unroll
        for (int i = 0; i < 4; i++) {
            int row = crow + i * 32;
            uint32_t d = st + row * 80 + cseg * 16;
            CPA(d,       Agh + (long)row * lda + cseg * 8);
            CPA(d + ABY, Agl + (long)row * lda + cseg * 8);
        }
#pragma unroll
        for (int i = 0; i < 4; i++) {
            int row = crow + i * 32;
            CPA(st + 2 * ABY + row * 80 + cseg * 16, Bgh + (long)row * ldb + cseg * 8);
        }
        CPC();
    }

    for (int ch = 0; ch < nch; ch++) {
        if (ch + 1 < nch) {
            const uint32_t st = smb + ((ch + 1) & 1) * STG;
            const fp16* ah = Agh + (ch + 1) * 32;
            const fp16* al = Agl + (ch + 1) * 32;
            const fp16* bh = Bgh + (ch + 1) * 32;
#pragma unroll
            for (int i = 0; i < 4; i++) {
                int row = crow + i * 32;
                uint32_t d = st + row * 80 + cseg * 16;
                CPA(d,       ah + (long)row * lda + cseg * 8);
                CPA(d + ABY, al + (long)row * lda + cseg * 8);
            }
#pragma unroll
            for (int i = 0; i < 4; i++) {
                int row = crow + i * 32;
                CPA(st + 2 * ABY + row * 80 + cseg * 16, bh + (long)row * ldb + cseg * 8);
            }
            CPC();
            CPW(1);
        } else {
            CPW(0);
        }
        __syncthreads();

        const uint32_t sbase = smb + (ch & 1) * STG;
#pragma unroll
        for (int ks = 0; ks < 2; ks++) {
            const int ko = ks * 32;
            uint32_t fa[16], fb[2 * NSUB];
            const uint32_t abase = sbase + a_off0 + ko;
            const uint32_t bbase = sbase + 2 * ABY + b_off0 + ko;
#pragma unroll
            for (int mi = 0; mi < 4; mi++) ldsm4(&fa[mi * 4], abase + mi * 1280);
#pragma unroll
            for (int np = 0; np < NSUB / 2; np++) ldsm4(&fb[np * 4], bbase + np * 1280);
#pragma unroll
            for (int mi = 0; mi < 4; mi++)
#pragma unroll
                for (int ni = 0; ni < NSUB; ni++)
                    mma_f16(acc[mi][ni], &fa[mi * 4], &fb[ni * 2]);     // hi*B
#pragma unroll
            for (int mi = 0; mi < 4; mi++) ldsm4(&fa[mi * 4], abase + ABY + mi * 1280);
#pragma unroll
            for (int mi = 0; mi < 4; mi++)
#pragma unroll
                for (int ni = 0; ni < NSUB; ni++)
                    mma_f16(acc[mi][ni], &fa[mi * 4], &fb[ni * 2]);     // lo*B
        }
        __syncthreads();
    }

    float* Cp = C ? (C + sk * sCk + z1 * sC1) : (float*)0;
#pragma unroll
    for (int mi = 0; mi < 4; mi++) {
        long r0 = m0 + wm * 64 + mi * 16 + g;
#pragma unroll
        for (int ni = 0; ni < NSUB; ni++) {
            long col = n0 + wn * WN + ni * 8 + tq * 2;
            float2 v0 = make_float2(acc[mi][ni][0], acc[mi][ni][1]);
            float2 v1 = make_float2(acc[mi][ni][2], acc[mi][ni][3]);
            if (Cp) {
                *(float2*)(Cp + r0 * ldc + col) = v0;
                *(float2*)(Cp + (r0 + 8) * ldc + col) = v1;
            }
            if (CbH) {
                long base = z1 * sC1;
                long i0 = base + r0 * ldc + col, i1 = base + (r0 + 8) * ldc + col;
                hsplit2(v0.x, v0.y, CbH, CbL, i0);
                hsplit2(v1.x, v1.y, CbH, CbL, i1);
            }
        }
    }
}

// ---------------- input transpose + bf16 split ----------------
__global__ void k_split_in(const float* __restrict__ tgt, const float* __restrict__ mem)
{
    long stride = (long)gridDim.x * blockDim.x;
    long base   = (long)blockIdx.x * blockDim.x + threadIdx.x;
    for (long p = base; p < (long)C_N * C_D / 2; p += stride) {
        const float* s = tgt + 6 * p;
        float2 a = *(const float2*)s, b = *(const float2*)(s + 2), c = *(const float2*)(s + 4);
        bsplit2(a.x, b.y, &g_Tb_h[0][0][0], &g_Tb_l[0][0][0], 2 * p);
        bsplit2(a.y, c.x, &g_Tb_h[1][0][0], &g_Tb_l[1][0][0], 2 * p);
        bsplit2(b.x, c.y, &g_Tb_h[2][0][0], &g_Tb_l[2][0][0], 2 * p);
    }
    for (long p = base; p < (long)C_E * C_D / 2; p += stride) {
        const float* s = mem + 6 * p;
        float2 a = *(const float2*)s, b = *(const float2*)(s + 2), c = *(const float2*)(s + 4);
        bsplit2(a.x, b.y, &g_Mb_h[0][0][0], &g_Mb_l[0][0][0], 2 * p);
        bsplit2(a.y, c.x, &g_Mb_h[1][0][0], &g_Mb_l[1][0][0], 2 * p);
        bsplit2(b.x, c.y, &g_Mb_h[2][0][0], &g_Mb_l[2][0][0], 2 * p);
    }
}

// ---------------- all weight splits in one kernel ----------------
__global__ void k_split_all(
    const float* __restrict__ Wsrc, const float* __restrict__ Wdst,
    const float* __restrict__ Wv,   const float* __restrict__ Wp,
    const float* __restrict__ Wf1,  const float* __restrict__ Wfd,
    const float* __restrict__ Wf2,  const float* __restrict__ Wa)
{
    const long SQ = (long)C_D * C_D;
    const long O4 = 4 * SQ;
    const long O5 = O4 + (long)C_FF * C_D;
    const long O6 = O5 + (long)C_FF * C_FF;
    const long O7 = O6 + (long)C_D * C_FF;
    const long O8 = O7 + (long)C_MA * C_D;
    long stride = (long)gridDim.x * blockDim.x;
    for (long i = (long)blockIdx.x * blockDim.x + threadIdx.x; i < O8; i += stride) {
        if (i < SQ)            bsplit(Wsrc[i],      g_Wsrc_h, g_Wsrc_l, i);
        else if (i < 2 * SQ)   bsplit(Wdst[i - SQ], g_Wdst_h, g_Wdst_l, i - SQ);
        else if (i < 3 * SQ)   bsplit(Wv[i - 2*SQ], g_Wv_h,   g_Wv_l,   i - 2*SQ);
        else if (i < 4 * SQ)   bsplit(Wp[i - 3*SQ], g_Wp_h,   g_Wp_l,   i - 3*SQ);
        else if (i < O5)       g_Wf1_f[i - O4] = __float2half_rn(Wf1[i - O4]);
        else if (i < O6)       g_Wfd_f[i - O5] = __float2half_rn(Wfd[i - O5]);
        else if (i < O7)       g_Wf2_f[i - O6] = __float2half_rn(Wf2[i - O6]);
        else {
            long k = i - O7;
            long r = k >> 6, c = k & 63;
            bsplit(Wa[k], g_Wa_h, g_Wa_l, c * C_D + r);
        }
    }
}

// ---------------- fused edge MLP ----------------
__global__ void __launch_bounds__(256) k_mlp(
    const float* __restrict__ es, const float* __restrict__ w1, const float* __restrict__ b1,
    const float* __restrict__ w2, const float* __restrict__ b2,
    const float* __restrict__ w3, const float* __restrict__ b3)
{
    __shared__ float s_es[64][65];
    __shared__ float s_w1[64][32];
    __shared__ float s_w2[32][32];
    __shared__ float s_h1[64][33];
    __shared__ float s_h2[64][33];
    const int t = threadIdx.x;
    const long e0 = (long)blockIdx.x * 64;

    for (int i = t; i < 64 * 32; i += 256) s_w1[i >> 5][i & 31] = w1[i];
    for (int i = t; i < 32 * 32; i += 256) s_w2[i >> 5][i & 31] = w2[i];
    for (int i = t; i < 64 * 64; i += 256) s_es[i >> 6][i & 63] = es[e0 * 64 + i];
    __syncthreads();

    for (int i = t; i < 64 * 32; i += 256) {
        int e = i >> 5, j = i & 31;
        float acc = b1[j];
#pragma unroll 8
        for (int c = 0; c < 64; c++) acc = fmaf(s_es[e][c], s_w1[c][j], acc);
        s_h1[e][j] = acc / (1.f + expf(-acc));
    }
    __syncthreads();
    for (int i = t; i < 64 * 32; i += 256) {
        int e = i >> 5, j = i & 31;
        float acc = b2[j];
#pragma unroll 8
        for (int c = 0; c < 32; c++) acc = fmaf(s_h1[e][c], s_w2[c][j], acc);
        s_h2[e][j] = acc / (1.f + expf(-acc));
    }
    __syncthreads();
    for (int i = t; i < 64 * 1536; i += 256) {
        int e = i / 1536, o = i - e * 1536;
        float acc = b3[o];
#pragma unroll 8
        for (int c = 0; c < 32; c++) acc = fmaf(s_h2[e][c], w3[c * 1536 + o], acc);
        g_w[e0 + e][o] = acc;
    }
}

// ---------------- pointwise equivariant products ----------------
__global__ void k_pointwise(const float* __restrict__ esh)
{
    long stride = (long)gridDim.x * blockDim.x;
    for (long p = (long)blockIdx.x * blockDim.x + threadIdx.x; p < (long)C_E * C_D / 2; p += stride) {
        int  c = (int)(p & 255) * 2;
        long e = p >> 8;
        float s  = esh[e * 4 + 0];
        float v0 = esh[e * 4 + 1], v1 = esh[e * 4 + 2], v2 = esh[e * 4 + 3];
        float2 m0 = *(const float2*)&g_MSG[0][e][c];
        float2 m1 = *(const float2*)&g_MSG[1][e][c];
        float2 m2 = *(const float2*)&g_MSG[2][e][c];
        float2 w0 = *(const float2*)&g_w[e][c];
        float2 w1 = *(const float2*)&g_w[e][512 + c];
        float2 w2 = *(const float2*)&g_w[e][1024 + c];
        float p0 = w0.x * (m0.x * v0 + m1.x * v1 + m2.x * v2) * 0.5773502691896258f;
        float p1 = w0.y * (m0.y * v0 + m1.y * v1 + m2.y * v2) * 0.5773502691896258f;
        bsplit2(p0, p1, &g_pscb_h[0][0], &g_pscb_l[0][0], e * C_D + c);
        float k2x = w2.x * 0.7071067811865475f, k2y = w2.y * 0.7071067811865475f;
        float wsx = w1.x * s, wsy = w1.y * s;
        *(float2*)&g_PV[0][e][c] = make_float2(wsx * m0.x + k2x * (m1.x * v2 - m2.x * v1),
                                               wsy * m0.y + k2y * (m1.y * v2 - m2.y * v1));
        *(float2*)&g_PV[1][e][c] = make_float2(wsx * m1.x + k2x * (m2.x * v0 - m0.x * v2),
                                               wsy * m1.y + k2y * (m2.y * v0 - m0.y * v2));
        *(float2*)&g_PV[2][e][c] = make_float2(wsx * m2.x + k2x * (m0.x * v1 - m1.x * v0),
                                               wsy * m2.y + k2y * (m0.y * v1 - m1.y * v0));
    }
}

// ---------------- fused alpha post + softmax (reduces 2 split-K partials) ----------------
__global__ void __launch_bounds__(512) k_alpha(const float* __restrict__ gg, const float* __restrict__ bb,
                                               const float* __restrict__ adot)
{
    int n = blockIdx.x;
    int t = threadIdx.x, wid = t >> 5, lane = t & 31;
    __shared__ float s_l[16][8];
    int e = n * 16 + wid;
    float v0 = g_araw[0][e][lane * 2]     + g_araw[1][e][lane * 2];
    float v1 = g_araw[0][e][lane * 2 + 1] + g_araw[1][e][lane * 2 + 1];
    float s = v0 + v1, s2 = v0 * v0 + v1 * v1;
#pragma unroll
    for (int o = 16; o > 0; o >>= 1) {
        s  += __shfl_xor_sync(0xffffffffu, s, o);
        s2 += __shfl_xor_sync(0xffffffffu, s2, o);
    }
    float mu  = s * (1.f / 64.f);
    float var = s2 * (1.f / 64.f) - mu * mu;
    float inv = rsqrtf(var + C_EPS);
    float a0 = (v0 - mu) * inv * gg[lane * 2]     + bb[lane * 2];
    float a1 = (v1 - mu) * inv * gg[lane * 2 + 1] + bb[lane * 2 + 1];
    a0 = 0.6f * a0 + 0.4f * a0 * tanhf(0.5f * a0);
    a1 = 0.6f * a1 + 0.4f * a1 * tanhf(0.5f * a1);
    int h = lane >> 2;
    int m = (lane & 3) * 2;
    float p = a0 * adot[h * 8 + m] + a1 * adot[h * 8 + m + 1];
    p += __shfl_xor_sync(0xffffffffu, p, 1);
    p += __shfl_xor_sync(0xffffffffu, p, 2);
    if ((lane & 3) == 0) s_l[wid][h] = p;
    __syncthreads();
    if (t < 8) {
        float mx = -1e30f;
#pragma unroll
        for (int k = 0; k < 16; k++) mx = fmaxf(mx, s_l[k][t]);
        float sum = 0.f; float ex[16];
#pragma unroll
        for (int k = 0; k < 16; k++) { ex[k] = expf(s_l[k][t] - mx); sum += ex[k]; }
        float is = 1.f / sum;
#pragma unroll
        for (int k = 0; k < 16; k++) g_att[n * 16 + k][t] = ex[k] * is;
    }
}

// ---------------- z = sum_k att * pv ----------------
__global__ void __launch_bounds__(256) k_z()
{
    int n = blockIdx.x, x = blockIdx.y;
    __shared__ float s_a[16][8];
    if (threadIdx.x < 128)
        s_a[threadIdx.x >> 3][threadIdx.x & 7] = g_att[n * 16 + (threadIdx.x >> 3)][threadIdx.x & 7];
    __syncthreads();
    int c = threadIdx.x * 2;
    float2 acc[8];
#pragma unroll
    for (int h = 0; h < 8; h++) acc[h] = make_float2(0.f, 0.f);
#pragma unroll
    for (int k = 0; k < 16; k++) {
        float2 pv = *(const float2*)&g_PV[x][n * 16 + k][c];
#pragma unroll
        for (int h = 0; h < 8; h++) {
            acc[h].x = fmaf(s_a[k][h], pv.x, acc[h].x);
            acc[h].y = fmaf(s_a[k][h], pv.y, acc[h].y);
        }
    }
#pragma unroll
    for (int h = 0; h < 8; h++) {
        long idx = (((long)x * C_N + n) * C_H + h) * C_D + c;
        bsplit2(acc[h].x, acc[h].y, &g_Zb_h[0][0][0][0], &g_Zb_l[0][0][0][0], idx);
    }
}

// ---------------- vn_ln with fused split-K partial reduction ----------------
__global__ void __launch_bounds__(256) k_vnln(const float* __restrict__ Xin,
                                              const float* __restrict__ Parts, int nparts, long pstride,
                                              float* __restrict__ Xout,
                                              fp16* __restrict__ fH, fp16* __restrict__ fL,
                                              const float* __restrict__ gg, const float* __restrict__ bb,
                                              int inter)
{
    int n = blockIdx.x, t = threadIdx.x;
    const long P = (long)C_N * C_D;
    __shared__ float rs[8], rs2[8];
    __shared__ float smu, sinv;
    float xv[2][3], nc[2];
    float s = 0.f, s2 = 0.f;
#pragma unroll
    for (int i = 0; i < 2; i++) {
        int c = t * 2 + i;
#pragma unroll
        for (int xx = 0; xx < 3; xx++) {
            long idx = xx * P + (long)n * C_D + c;
            float v = Xin[idx];
            for (int pp = 0; pp < nparts; pp++) v += Parts[pp * pstride + idx];
            xv[i][xx] = v;
        }
        float v = sqrtf(xv[i][0] * xv[i][0] + xv[i][1] * xv[i][1] + xv[i][2] * xv[i][2] + C_EPS);
        nc[i] = v; s += v; s2 = fmaf(v, v, s2);
    }
#pragma unroll
    for (int o = 16; o > 0; o >>= 1) {
        s  += __shfl_xor_sync(0xffffffffu, s, o);
        s2 += __shfl_xor_sync(0xffffffffu, s2, o);
    }
    if ((t & 31) == 0) { rs[t >> 5] = s; rs2[t >> 5] = s2; }
    __syncthreads();
    if (t == 0) {
        float S = 0.f, S2 = 0.f;
        for (int i = 0; i < 8; i++) { S += rs[i]; S2 += rs2[i]; }
        float mu  = S * (1.f / 512.f);
        float var = S2 * (1.f / 512.f) - mu * mu;
        smu = mu; sinv = rsqrtf(var + C_EPS);
    }
    __syncthreads();
    float sc[2];
#pragma unroll
    for (int i = 0; i < 2; i++) {
        int c = t * 2 + i;
        float ln = (nc[i] - smu) * sinv * gg[c] + bb[c];
        sc[i] = ln / nc[i];
    }
    if (inter) {
#pragma unroll
        for (int i = 0; i < 2; i++) {
            int c = t * 2 + i;
#pragma unroll
            for (int xx = 0; xx < 3; xx++) Xout[(long)n * 1536 + c * 3 + xx] = xv[i][xx] * sc[i];
        }
    } else {
#pragma unroll
        for (int xx = 0; xx < 3; xx++) {
            long idx = xx * P + (long)n * C_D + t * 2;
            float o0 = xv[0][xx] * sc[0], o1 = xv[1][xx] * sc[1];
            *(float2*)(Xout + idx) = make_float2(o0, o1);
            if (fH) hsplit2(o0, o1, fH, fL, idx);
        }
    }
}

// ---------------- FF gating with fused DV partial reduction (fp16 pair out) ----------------
__global__ void k_gate()
{
    const long P = (long)C_N * C_FF;
    const float* Y  = &g_Y[0][0][0];
    const float* D0 = &g_DVP[0][0][0][0];
    const float* D1 = &g_DVP[1][0][0][0];
    long stride = (long)gridDim.x * blockDim.x;
    for (long p = (long)blockIdx.x * blockDim.x + threadIdx.x; p < P / 2; p += stride) {
        long i = 2 * p;
        float2 y0 = *(const float2*)(Y + i), y1 = *(const float2*)(Y + P + i), y2 = *(const float2*)(Y + 2 * P + i);
        float2 a0 = *(const float2*)(D0 + i), a1 = *(const float2*)(D0 + P + i), a2 = *(const float2*)(D0 + 2 * P + i);
        float2 b0 = *(const float2*)(D1 + i), b1 = *(const float2*)(D1 + P + i), b2 = *(const float2*)(D1 + 2 * P + i);
        float2 d0 = make_float2(a0.x + b0.x, a0.y + b0.y);
        float2 d1 = make_float2(a1.x + b1.x, a1.y + b1.y);
        float2 d2 = make_float2(a2.x + b2.x, a2.y + b2.y);
        float dotx = y0.x * d0.x + y1.x * d1.x + y2.x * d2.x;
        float doty = y0.y * d0.y + y1.y * d1.y + y2.y * d2.y;
        float fx = (dotx >= 0.f) ? 0.f : 0.8f * dotx / (d0.x * d0.x + d1.x * d1.x + d2.x * d2.x + C_EPS);
        float fy = (doty >= 0.f) ? 0.f : 0.8f * doty / (d0.y * d0.y + d1.y * d1.y + d2.y * d2.y + C_EPS);
        hsplit2(y0.x - fx * d0.x, y0.y - fy * d0.y, &g_Y2f_h[0][0][0], &g_Y2f_l[0][0][0], i);
        hsplit2(y1.x - fx * d1.x, y1.y - fy * d1.y, &g_Y2f_h[0][0][0], &g_Y2f_l[0][0][0], P + i);
        hsplit2(y2.x - fx * d2.x, y2.y - fy * d2.y, &g_Y2f_h[0][0][0], &g_Y2f_l[0][0][0], 2 * P + i);
    }
}

// ---------------- host launch ----------------
extern "C" void kernel_launch(void* const* d_in, const int* in_sizes, int n_in,
                              void* d_out, int out_size)
{
    const float* tgt    = (const float*)d_in[0];
    const float* mem    = (const float*)d_in[1];
    const float* esh    = (const float*)d_in[2];
    const float* escal  = (const float*)d_in[3];
    const float* W_src  = (const float*)d_in[4];
    const float* W_dst  = (const float*)d_in[5];
    const float* fc_w1  = (const float*)d_in[6];
    const float* fc_b1  = (const float*)d_in[7];
    const float* fc_w2  = (const float*)d_in[8];
    const float* fc_b2  = (const float*)d_in[9];
    const float* fc_w3  = (const float*)d_in[10];
    const float* fc_b3  = (const float*)d_in[11];
    const float* W_alpha= (const float*)d_in[12];
    const float* ln_a_g = (const float*)d_in[13];
    const float* ln_a_b = (const float*)d_in[14];
    const float* adot   = (const float*)d_in[15];
    const float* W_value= (const float*)d_in[16];
    const float* W_proj = (const float*)d_in[17];
    const float* n1_g   = (const float*)d_in[18];
    const float* n1_b   = (const float*)d_in[19];
    const float* n2_g   = (const float*)d_in[20];
    const float* n2_b   = (const float*)d_in[21];
    const float* W_ff1  = (const float*)d_in[22];
    const float* W_ffd  = (const float*)d_in[23];
    const float* W_ff2  = (const float*)d_in[24];

#define SYM(p, s) cudaGetSymbolAddress((void**)&p, s)
    float *pTV, *pMSG, *paraw, *pX1, *pY, *pPRJ, *pFF2, *pDVP;
    SYM(pTV, g_TV); SYM(pMSG, g_MSG); SYM(paraw, g_araw);
    SYM(pX1, g_X1); SYM(pY, g_Y);
    SYM(pPRJ, g_PRJP); SYM(pFF2, g_FF2P); SYM(pDVP, g_DVP);
    bf16 *pTbh, *pTbl, *pMbh, *pMbl, *ppsh, *ppsl, *pZh, *pZl, *pOh, *pOl;
    SYM(pTbh, g_Tb_h); SYM(pTbl, g_Tb_l); SYM(pMbh, g_Mb_h); SYM(pMbl, g_Mb_l);
    SYM(ppsh, g_pscb_h); SYM(ppsl, g_pscb_l); SYM(pZh, g_Zb_h); SYM(pZl, g_Zb_l);
    SYM(pOh, g_OUTb_h); SYM(pOl, g_OUTb_l);
    fp16 *pX1fh, *pX1fl, *pYfh, *pYfl, *pY2fh, *pY2fl, *pWf1f, *pWfdf, *pWf2f;
    SYM(pX1fh, g_X1f_h); SYM(pX1fl, g_X1f_l); SYM(pYfh, g_Yf_h); SYM(pYfl, g_Yf_l);
    SYM(pY2fh, g_Y2f_h); SYM(pY2fl, g_Y2f_l);
    SYM(pWf1f, g_Wf1_f); SYM(pWfdf, g_Wfd_f); SYM(pWf2f, g_Wf2_f);
    bf16 *pWsh, *pWsl, *pWdh, *pWdl, *pWah, *pWal, *pWvh, *pWvl, *pWph, *pWpl;
    SYM(pWsh, g_Wsrc_h); SYM(pWsl, g_Wsrc_l); SYM(pWdh, g_Wdst_h); SYM(pWdl, g_Wdst_l);
    SYM(pWah, g_Wa_h); SYM(pWal, g_Wa_l); SYM(pWvh, g_Wv_h); SYM(pWvl, g_Wv_l);
    SYM(pWph, g_Wp_h); SYM(pWpl, g_Wp_l);
#undef SYM

    const long NP_D  = (long)C_N * C_D;
    const long EP_D  = (long)C_E * C_D;
    const long NP_FF = (long)C_N * C_FF;
    const long NHD   = (long)C_N * C_H * C_D;

    const int SM128 = 2 * (2 * 10240 + 2 * 128 * 80);   // 81920
    const int SM64  = 2 * (2 * 10240 + 2 * 64 * 80);    // 61440
    const int SMH   = 2 * (2 * 10240 + 128 * 80);       // 61440
    cudaFuncSetAttribute(gemm_bf<128>, cudaFuncAttributeMaxDynamicSharedMemorySize, SM128);
    cudaFuncSetAttribute(gemm_bf<64>,  cudaFuncAttributeMaxDynamicSharedMemorySize, SM64);
    cudaFuncSetAttribute(gemm_hf,      cudaFuncAttributeMaxDynamicSharedMemorySize, SMH);

    // one-time stream/event setup (no device memory involved)
    static cudaStream_t s1 = nullptr, s2 = nullptr;
    static cudaEvent_t evRoot = nullptr, evMlp = nullptr, evIn = nullptr;
    if (!s1) {
        cudaStreamCreateWithFlags(&s1, cudaStreamNonBlocking);
        cudaStreamCreateWithFlags(&s2, cudaStreamNonBlocking);
        cudaEventCreateWithFlags(&evRoot, cudaEventDisableTiming);
        cudaEventCreateWithFlags(&evMlp,  cudaEventDisableTiming);
        cudaEventCreateWithFlags(&evIn,   cudaEventDisableTiming);
    }

    // fork helper streams off the main (capture) stream
    cudaEventRecord(evRoot, 0);
    cudaStreamWaitEvent(s1, evRoot, 0);
    cudaStreamWaitEvent(s2, evRoot, 0);

    // s1: edge MLP (independent of everything up to pointwise)
    k_mlp<<<C_E / 64, 256, 0, s1>>>(escal, fc_w1, fc_b1, fc_w2, fc_b2, fc_w3, fc_b3);
    cudaEventRecord(evMlp, s1);

    // s2: input transpose + split
    k_split_in<<<4096, 256, 0, s2>>>(tgt, mem);
    cudaEventRecord(evIn, s2);

    // main stream: weight splits, then tv (needs Tb from s2)
    k_split_all<<<8192, 256>>>(W_src, W_dst, W_value, W_proj, W_ff1, W_ffd, W_ff2, W_alpha);
    cudaStreamWaitEvent(0, evIn, 0);

    // 2) tv = W_dst @ tgt
    gemm_bf<128><<<dim3(4, 8, 3), 128, SM128>>>(pTbh, pTbl, pWdh, pWdl, pTV, nullptr, nullptr, nullptr,
        C_D, C_D, C_D, C_D, NP_D, 0, 0, 0, NP_D, 0, 1, 1, 0, 0, 1, 3, 0);

    // 3) msg = W_src @ memory + tv[e/K]
    gemm_bf<128><<<dim3(4, 128, 3), 128, SM128>>>(pMbh, pMbl, pWsh, pWsl, pMSG, pTV, nullptr, nullptr,
        C_D, C_D, C_D, C_D, EP_D, 0, 0, 0, EP_D, 0, 1, C_K, C_D, NP_D, 1, 3, 0);

    // join mlp before pointwise (reads g_w)
    cudaStreamWaitEvent(0, evMlp, 0);

    // 5) p_sc / pv
    k_pointwise<<<2048, 256>>>(esh);

    // 6) a_raw = p_sc @ W_alpha (split-K=2 -> reduced in k_alpha)
    gemm_bf<64><<<dim3(1, 128, 2), 128, SM64>>>(ppsh, ppsl, pWah, pWal, paraw, nullptr, nullptr, nullptr,
        C_D, C_D, C_MA, C_D, 0, 0, 0, 0, 0, 0, 1, 1, 0, 0, 2, 1, (long)C_E * C_MA);

    // 7) fused LN + lrelu + head dot + softmax
    k_alpha<<<C_N, 512>>>(ln_a_g, ln_a_b, adot);

    // 8) z = sum_k att * pv
    k_z<<<dim3(C_N, 3), 256>>>();

    // 9) out = W_value @ z (per head, bf16 out), then proj (split-K=2)
    gemm_bf<64><<<dim3(1, 8, 24), 128, SM64>>>(pZh, pZl, pWvh, pWvl, nullptr, nullptr, pOh, pOl,
        C_H * C_D, C_D, C_D, C_D, NHD, C_D, 0, 64 * C_D, NP_D, 64, C_H, 1, 0, 0, 1, 24, 0);
    gemm_bf<128><<<dim3(4, 8, 6), 128, SM128>>>(pOh, pOl, pWph, pWpl, pPRJ, nullptr, nullptr, nullptr,
        C_D, C_D, C_D, C_D, NP_D, 0, 0, 0, NP_D, 0, 1, 1, 0, 0, 2, 3, 3 * NP_D);

    // 10) vn_ln #1 (fp32 + fp16 pairs for ff1)
    k_vnln<<<C_N, 256>>>(pTV, pPRJ, 2, 3 * NP_D, pX1, pX1fh, pX1fl, n1_g, n1_b, 0);

    // 11) FF block: ff1 (fp16 2-pass), ffd (fp16 2-pass, split-K=2), ff2 (fp16 2-pass, split-K=4)
    gemm_hf<<<dim3(16, 8, 3), 128, SMH>>>(pX1fh, pX1fl, pWf1f, pY, pYfh, pYfl,
        C_D, C_D, C_FF, C_D, NP_D, 0, NP_FF, 1, 3, 0);
    gemm_hf<<<dim3(16, 8, 6), 128, SMH>>>(pYfh, pYfl, pWfdf, pDVP, nullptr, nullptr,
        C_FF, C_FF, C_FF, C_FF, NP_FF, 0, NP_FF, 2, 3, 3 * NP_FF);
    k_gate<<<2048, 256>>>();
    gemm_hf<<<dim3(4, 8, 12), 128, SMH>>>(pY2fh, pY2fl, pWf2f, pFF2, nullptr, nullptr,
        C_FF, C_FF, C_D, C_FF, NP_FF, 0, NP_D, 4, 3, 3 * NP_D);

    // 12) vn_ln #2 -> interleaved output
    k_vnln<<<C_N, 256>>>(pX1, pFF2, 4, 3 * NP_D, (float*)d_out, nullptr, nullptr, n2_g, n2_b, 1);
}

// round 17
// speedup vs baseline: 1.4080x; 1.0067x over previous
#include <cuda_runtime.h>
#include <cuda_bf16.h>
#include <cuda_fp16.h>
#include <math.h>
#include <stdint.h>

// ---------------- problem constants ----------------
#define C_N   1024
#define C_K   16
#define C_D   512
#define C_H   8
#define C_FF  2048
#define C_MA  64
#define C_ES  64
#define C_E   (C_N * C_K)      // 16384
#define C_EPS 1e-6f

typedef __nv_bfloat16 bf16;
typedef __half fp16;

// ---------------- fp32 scratch ----------------
__device__ float g_TV  [3][C_N][C_D];
__device__ float g_MSG [3][C_E][C_D];
__device__ float g_w   [C_E][3*C_D];
__device__ float g_PV  [3][C_E][C_D];
__device__ float g_araw[2][C_E][C_MA];
__device__ float g_att [C_E][C_H];
__device__ float g_X1  [3][C_N][C_D];
__device__ float g_Y   [3][C_N][C_FF];
// split-K partial buffers
__device__ float g_PRJP[2][3][C_N][C_D];
__device__ float g_FF2P[4][3][C_N][C_D];
__device__ float g_DVP [2][3][C_N][C_FF];

// ---------------- bf16 hi/lo pairs (GEMM operands) ----------------
__device__ __align__(128) bf16 g_Tb_h [3][C_N][C_D],        g_Tb_l [3][C_N][C_D];
__device__ __align__(128) bf16 g_Mb_h [3][C_E][C_D],        g_Mb_l [3][C_E][C_D];
__device__ __align__(128) bf16 g_pscb_h[C_E][C_D],          g_pscb_l[C_E][C_D];
__device__ __align__(128) bf16 g_Zb_h [3][C_N][C_H][C_D],   g_Zb_l [3][C_N][C_H][C_D];
__device__ __align__(128) bf16 g_OUTb_h[3][C_N][C_D],       g_OUTb_l[3][C_N][C_D];
// fp16 pairs (FF block path)
__device__ __align__(128) fp16 g_X1f_h[3][C_N][C_D],        g_X1f_l[3][C_N][C_D];
__device__ __align__(128) fp16 g_Yf_h [3][C_N][C_FF],       g_Yf_l [3][C_N][C_FF];
__device__ __align__(128) fp16 g_Y2f_h[3][C_N][C_FF],       g_Y2f_l[3][C_N][C_FF];
// weights
__device__ __align__(128) bf16 g_Wsrc_h[C_D*C_D],  g_Wsrc_l[C_D*C_D];
__device__ __align__(128) bf16 g_Wdst_h[C_D*C_D],  g_Wdst_l[C_D*C_D];
__device__ __align__(128) bf16 g_Wa_h  [C_MA*C_D], g_Wa_l  [C_MA*C_D];
__device__ __align__(128) bf16 g_Wv_h  [C_D*C_D],  g_Wv_l  [C_D*C_D];
__device__ __align__(128) bf16 g_Wp_h  [C_D*C_D],  g_Wp_l  [C_D*C_D];
__device__ __align__(128) fp16 g_Wf1_f [C_FF*C_D];
__device__ __align__(128) fp16 g_Wfd_f [C_FF*C_FF];
__device__ __align__(128) fp16 g_Wf2_f [C_D*C_FF];

// ---------------- helpers ----------------
__device__ __forceinline__ void bsplit(float v, bf16* H, bf16* L, long i) {
    bf16 h = __float2bfloat16_rn(v);
    H[i] = h;
    L[i] = __float2bfloat16_rn(v - __bfloat162float(h));
}
__device__ __forceinline__ void bsplit2(float v0, float v1, bf16* H, bf16* L, long i) {
    bf16 h0 = __float2bfloat16_rn(v0), h1 = __float2bfloat16_rn(v1);
    *(__nv_bfloat162*)(H + i) = __nv_bfloat162(h0, h1);
    *(__nv_bfloat162*)(L + i) = __nv_bfloat162(
        __float2bfloat16_rn(v0 - __bfloat162float(h0)),
        __float2bfloat16_rn(v1 - __bfloat162float(h1)));
}
__device__ __forceinline__ void hsplit2(float v0, float v1, fp16* H, fp16* L, long i) {
    fp16 h0 = __float2half_rn(v0), h1 = __float2half_rn(v1);
    *(__half2*)(H + i) = __half2(h0, h1);
    *(__half2*)(L + i) = __half2(
        __float2half_rn(v0 - __half2float(h0)),
        __float2half_rn(v1 - __half2float(h1)));
}
__device__ __forceinline__ uint32_t s2u(const void* p) {
    uint32_t a;
    asm("{ .reg .u64 t; cvta.to.shared.u64 t, %1; cvt.u32.u64 %0, t; }" : "=r"(a) : "l"(p));
    return a;
}
__device__ __forceinline__ void mma_bf16(float* c, const uint32_t* a, const uint32_t* b) {
    asm volatile("mma.sync.aligned.m16n8k16.row.col.f32.bf16.bf16.f32 "
                 "{%0,%1,%2,%3},{%4,%5,%6,%7},{%8,%9},{%0,%1,%2,%3};"
                 : "+f"(c[0]), "+f"(c[1]), "+f"(c[2]), "+f"(c[3])
                 : "r"(a[0]), "r"(a[1]), "r"(a[2]), "r"(a[3]), "r"(b[0]), "r"(b[1]));
}
__device__ __forceinline__ void mma_f16(float* c, const uint32_t* a, const uint32_t* b) {
    asm volatile("mma.sync.aligned.m16n8k16.row.col.f32.f16.f16.f32 "
                 "{%0,%1,%2,%3},{%4,%5,%6,%7},{%8,%9},{%0,%1,%2,%3};"
                 : "+f"(c[0]), "+f"(c[1]), "+f"(c[2]), "+f"(c[3])
                 : "r"(a[0]), "r"(a[1]), "r"(a[2]), "r"(a[3]), "r"(b[0]), "r"(b[1]));
}
__device__ __forceinline__ void ldsm4(uint32_t* r, uint32_t addr) {
    asm volatile("ldmatrix.sync.aligned.m8n8.x4.shared.b16 {%0,%1,%2,%3}, [%4];"
        : "=r"(r[0]), "=r"(r[1]), "=r"(r[2]), "=r"(r[3]) : "r"(addr));
}
#define CPA(d, s) asm volatile("cp.async.cg.shared.global [%0], [%1], 16;" :: "r"(d), "l"(s) : "memory")
#define CPC()     asm volatile("cp.async.commit_group;" ::: "memory")
#define CPW(n)    asm volatile("cp.async.wait_group %0;" :: "n"(n) : "memory")

// ============ bf16-pair NT GEMM (3 HMMA passes), optional split-K ============
template<int BN>
__global__ void __launch_bounds__(128, 2) gemm_bf(
    const bf16* __restrict__ Ah, const bf16* __restrict__ Al,
    const bf16* __restrict__ Bh, const bf16* __restrict__ Bl,
    float* __restrict__ C, const float* __restrict__ Add,
    bf16* __restrict__ CbH, bf16* __restrict__ CbL,
    int lda, int ldb, int ldc, int Kc,
    long sA1, long sA2, long sB1, long sB2, long sC1, long sC2, int nz2,
    int addDiv, int ldadd, long sAdd1,
    int nsplit, int nzTot, long sCk)
{
    constexpr int WN   = BN / 2;
    constexpr int NSUB = WN / 8;
    constexpr int ABY  = 10240;
    constexpr int BBY  = BN * 80;
    constexpr int STG  = 2 * ABY + 2 * BBY;

    extern __shared__ __align__(16) char sm[];
    const int t = threadIdx.x, wid = t >> 5, lane = t & 31;
    const int g = lane >> 2, tq = lane & 3;
    const int wm = wid & 1, wn = wid >> 1;

    const int bz = blockIdx.z;
    const int sk = bz / nzTot;
    const int z  = bz - sk * nzTot;
    const int z1 = z / nz2, z2 = z - z1 * nz2;
    const int nch = (Kc >> 5) / nsplit;
    const long kOff = (long)sk * nch * 32;

    const long m0 = (long)blockIdx.y * 128, n0 = (long)blockIdx.x * BN;
    const bf16* Agh = Ah + z1 * sA1 + z2 * sA2 + m0 * lda + kOff;
    const bf16* Agl = Al + z1 * sA1 + z2 * sA2 + m0 * lda + kOff;
    const bf16* Bgh = Bh + z1 * sB1 + z2 * sB2 + n0 * ldb + kOff;
    const bf16* Bgl = Bl + z1 * sB1 + z2 * sB2 + n0 * ldb + kOff;

    const uint32_t smb = s2u(sm);
    const int crow = t >> 2, cseg = t & 3;

    const int lm = lane >> 3, lr = lane & 7;
    const int a_off0 = (wm * 64 + (lm & 1) * 8 + lr) * 80 + (lm >> 1) * 16;
    const int b_off0 = (wn * WN + (lm >> 1) * 8 + lr) * 80 + (lm & 1) * 16;

    float acc[4][NSUB][4];
#pragma unroll
    for (int mi = 0; mi < 4; mi++)
#pragma unroll
        for (int ni = 0; ni < NSUB; ni++)
#pragma unroll
            for (int j = 0; j < 4; j++) acc[mi][ni][j] = 0.f;

    {
        const uint32_t st = smb;
#pragma unroll
        for (int i = 0; i < 4; i++) {
            int row = crow + i * 32;
            uint32_t d = st + row * 80 + cseg * 16;
            CPA(d,       Agh + (long)row * lda + cseg * 8);
            CPA(d + ABY, Agl + (long)row * lda + cseg * 8);
        }
#pragma unroll
        for (int i = 0; i < BN / 32; i++) {
            int row = crow + i * 32;
            uint32_t d = st + 2 * ABY + row * 80 + cseg * 16;
            CPA(d,       Bgh + (long)row * ldb + cseg * 8);
            CPA(d + BBY, Bgl + (long)row * ldb + cseg * 8);
        }
        CPC();
    }

    for (int ch = 0; ch < nch; ch++) {
        if (ch + 1 < nch) {
            const uint32_t st = smb + ((ch + 1) & 1) * STG;
            const bf16* ah = Agh + (ch + 1) * 32;
            const bf16* al = Agl + (ch + 1) * 32;
            const bf16* bh = Bgh + (ch + 1) * 32;
            const bf16* bl = Bgl + (ch + 1) * 32;
#pragma unroll
            for (int i = 0; i < 4; i++) {
                int row = crow + i * 32;
                uint32_t d = st + row * 80 + cseg * 16;
                CPA(d,       ah + (long)row * lda + cseg * 8);
                CPA(d + ABY, al + (long)row * lda + cseg * 8);
            }
#pragma unroll
            for (int i = 0; i < BN / 32; i++) {
                int row = crow + i * 32;
                uint32_t d = st + 2 * ABY + row * 80 + cseg * 16;
                CPA(d,       bh + (long)row * ldb + cseg * 8);
                CPA(d + BBY, bl + (long)row * ldb + cseg * 8);
            }
            CPC();
            CPW(1);
        } else {
            CPW(0);
        }
        __syncthreads();

        const uint32_t sbase = smb + (ch & 1) * STG;
#pragma unroll
        for (int ks = 0; ks < 2; ks++) {
            const int ko = ks * 32;
            uint32_t fa[16], fbh[2 * NSUB], fbl[2 * NSUB];
            const uint32_t abase = sbase + a_off0 + ko;
            const uint32_t bbase = sbase + 2 * ABY + b_off0 + ko;
#pragma unroll
            for (int mi = 0; mi < 4; mi++) ldsm4(&fa[mi * 4], abase + mi * 1280);
#pragma unroll
            for (int np = 0; np < NSUB / 2; np++) ldsm4(&fbh[np * 4], bbase + np * 1280);
#pragma unroll
            for (int mi = 0; mi < 4; mi++)
#pragma unroll
                for (int ni = 0; ni < NSUB; ni++)
                    mma_bf16(acc[mi][ni], &fa[mi * 4], &fbh[ni * 2]);
#pragma unroll
            for (int np = 0; np < NSUB / 2; np++) ldsm4(&fbl[np * 4], bbase + BBY + np * 1280);
#pragma unroll
            for (int mi = 0; mi < 4; mi++)
#pragma unroll
                for (int ni = 0; ni < NSUB; ni++)
                    mma_bf16(acc[mi][ni], &fa[mi * 4], &fbl[ni * 2]);
#pragma unroll
            for (int mi = 0; mi < 4; mi++) ldsm4(&fa[mi * 4], abase + ABY + mi * 1280);
#pragma unroll
            for (int mi = 0; mi < 4; mi++)
#pragma unroll
                for (int ni = 0; ni < NSUB; ni++)
                    mma_bf16(acc[mi][ni], &fa[mi * 4], &fbh[ni * 2]);
        }
        __syncthreads();
    }

    float* Cp = C ? (C + sk * sCk + z1 * sC1 + z2 * sC2) : (float*)0;
    const float* Ad = Add ? (Add + z1 * sAdd1) : (const float*)0;
#pragma unroll
    for (int mi = 0; mi < 4; mi++) {
        long r0 = m0 + wm * 64 + mi * 16 + g;
#pragma unroll
        for (int ni = 0; ni < NSUB; ni++) {
            long col = n0 + wn * WN + ni * 8 + tq * 2;
            float2 v0 = make_float2(acc[mi][ni][0], acc[mi][ni][1]);
            float2 v1 = make_float2(acc[mi][ni][2], acc[mi][ni][3]);
            if (Ad) {
                float2 a0 = *(const float2*)(Ad + (r0 / addDiv) * (long)ldadd + col);
                float2 a1 = *(const float2*)(Ad + ((r0 + 8) / addDiv) * (long)ldadd + col);
                v0.x += a0.x; v0.y += a0.y; v1.x += a1.x; v1.y += a1.y;
            }
            if (Cp) {
                *(float2*)(Cp + r0 * ldc + col) = v0;
                *(float2*)(Cp + (r0 + 8) * ldc + col) = v1;
            }
            if (CbH) {
                long base = z1 * sC1 + z2 * sC2;
                long i0 = base + r0 * ldc + col, i1 = base + (r0 + 8) * ldc + col;
                bsplit2(v0.x, v0.y, CbH, CbL, i0);
                bsplit2(v1.x, v1.y, CbH, CbL, i1);
            }
        }
    }
}

// ============ fp16 2-pass NT GEMM (A hi/lo, B single), split-K, optional fp16-pair out ============
__global__ void __launch_bounds__(128, 2) gemm_hf(
    const fp16* __restrict__ Ah, const fp16* __restrict__ Al,
    const fp16* __restrict__ Bh,
    float* __restrict__ C,
    fp16* __restrict__ CbH, fp16* __restrict__ CbL,
    int lda, int ldb, int ldc, int Kc,
    long sA1, long sB1, long sC1,
    int nsplit, int nzTot, long sCk)
{
    constexpr int BN = 128, WN = 64, NSUB = 8;
    constexpr int ABY = 10240;
    constexpr int BBY = BN * 80;
    constexpr int STG = 2 * ABY + BBY;

    extern __shared__ __align__(16) char sm[];
    const int t = threadIdx.x, wid = t >> 5, lane = t & 31;
    const int g = lane >> 2, tq = lane & 3;
    const int wm = wid & 1, wn = wid >> 1;

    const int bz = blockIdx.z;
    const int sk = bz / nzTot;
    const int z1 = bz - sk * nzTot;
    const int nch = (Kc >> 5) / nsplit;
    const long kOff = (long)sk * nch * 32;

    const long m0 = (long)blockIdx.y * 128, n0 = (long)blockIdx.x * BN;
    const fp16* Agh = Ah + z1 * sA1 + m0 * lda + kOff;
    const fp16* Agl = Al + z1 * sA1 + m0 * lda + kOff;
    const fp16* Bgh = Bh + z1 * sB1 + n0 * ldb + kOff;

    const uint32_t smb = s2u(sm);
    const int crow = t >> 2, cseg = t & 3;
    const int lm = lane >> 3, lr = lane & 7;
    const int a_off0 = (wm * 64 + (lm & 1) * 8 + lr) * 80 + (lm >> 1) * 16;
    const int b_off0 = (wn * WN + (lm >> 1) * 8 + lr) * 80 + (lm & 1) * 16;

    float acc[4][NSUB][4];
#pragma unroll
    for (int mi = 0; mi < 4; mi++)
#pragma unroll
        for (int ni = 0; ni < NSUB; ni++)
#pragma unroll
            for (int j = 0; j < 4; j++) acc[mi][ni][j] = 0.f;

    {
        const uint32_t st = smb;
#pragma unroll
        for (int i = 0; i < 4; i++) {
            int row = crow + i * 32;
            uint32_t d = st + row * 80 + cseg * 16;
            CPA(d,       Agh + (long)row * lda + cseg * 8);
            CPA(d + ABY, Agl + (long)row * lda + cseg * 8);
        }
#pragma unroll
        for (int i = 0; i < 4; i++) {
            int row = crow + i * 32;
            CPA(st + 2 * ABY + row * 80 + cseg * 16, Bgh + (long)row * ldb + cseg * 8);
        }
        CPC();
    }

    for (int ch = 0; ch < nch; ch++) {
        if (ch + 1 < nch) {
            const uint32_t st = smb + ((ch + 1) & 1) * STG;
            const fp16* ah = Agh + (ch + 1) * 32;
            const fp16* al = Agl + (ch + 1) * 32;
            const fp16* bh = Bgh + (ch + 1) * 32;
#pragma unroll
            for (int i = 0; i < 4; i++) {
                int row = crow + i * 32;
                uint32_t d = st + row * 80 + cseg * 16;
                CPA(d,       ah + (long)row * lda + cseg * 8);
                CPA(d + ABY, al + (long)row * lda + cseg * 8);
            }
#pragma unroll
            for (int i = 0; i < 4; i++) {
                int row = crow + i * 32;
                CPA(st + 2 * ABY + row * 80 + cseg * 16, bh + (long)row * ldb + cseg * 8);
            }
            CPC();
            CPW(1);
        } else {
            CPW(0);
        }
        __syncthreads();

        const uint32_t sbase = smb + (ch & 1) * STG;
#pragma unroll
        for (int ks = 0; ks < 2; ks++) {
            const int ko = ks * 32;
            uint32_t fa[16], fb[2 * NSUB];
            const uint32_t abase = sbase + a_off0 + ko;
            const uint32_t bbase = sbase + 2 * ABY + b_off0 + ko;
#pragma unroll
            for (int mi = 0; mi < 4; mi++) ldsm4(&fa[mi * 4], abase + mi * 1280);
#pragma unroll
            for (int np = 0; np < NSUB / 2; np++) ldsm4(&fb[np * 4], bbase + np * 1280);
#pragma unroll
            for (int mi = 0; mi < 4; mi++)
#pragma unroll
                for (int ni = 0; ni < NSUB; ni++)
                    mma_f16(acc[mi][ni], &fa[mi * 4], &fb[ni * 2]);     // hi*B
#pragma unroll
            for (int mi = 0; mi < 4; mi++) ldsm4(&fa[mi * 4], abase + ABY + mi * 1280);
#pragma unroll
            for (int mi = 0; mi < 4; mi++)
#pragma unroll
                for (int ni = 0; ni < NSUB; ni++)
                    mma_f16(acc[mi][ni], &fa[mi * 4], &fb[ni * 2]);     // lo*B
        }
        __syncthreads();
    }

    float* Cp = C ? (C + sk * sCk + z1 * sC1) : (float*)0;
#pragma unroll
    for (int mi = 0; mi < 4; mi++) {
        long r0 = m0 + wm * 64 + mi * 16 + g;
#pragma unroll
        for (int ni = 0; ni < NSUB; ni++) {
            long col = n0 + wn * WN + ni * 8 + tq * 2;
            float2 v0 = make_float2(acc[mi][ni][0], acc[mi][ni][1]);
            float2 v1 = make_float2(acc[mi][ni][2], acc[mi][ni][3]);
            if (Cp) {
                *(float2*)(Cp + r0 * ldc + col) = v0;
                *(float2*)(Cp + (r0 + 8) * ldc + col) = v1;
            }
            if (CbH) {
                long base = z1 * sC1;
                long i0 = base + r0 * ldc + col, i1 = base + (r0 + 8) * ldc + col;
                hsplit2(v0.x, v0.y, CbH, CbL, i0);
                hsplit2(v1.x, v1.y, CbH, CbL, i1);
            }
        }
    }
}

// ---------------- input transpose + bf16 split ----------------
__global__ void k_split_in(const float* __restrict__ tgt, const float* __restrict__ mem)
{
    long stride = (long)gridDim.x * blockDim.x;
    long base   = (long)blockIdx.x * blockDim.x + threadIdx.x;
    for (long p = base; p < (long)C_N * C_D / 2; p += stride) {
        const float* s = tgt + 6 * p;
        float2 a = *(const float2*)s, b = *(const float2*)(s + 2), c = *(const float2*)(s + 4);
        bsplit2(a.x, b.y, &g_Tb_h[0][0][0], &g_Tb_l[0][0][0], 2 * p);
        bsplit2(a.y, c.x, &g_Tb_h[1][0][0], &g_Tb_l[1][0][0], 2 * p);
        bsplit2(b.x, c.y, &g_Tb_h[2][0][0], &g_Tb_l[2][0][0], 2 * p);
    }
    for (long p = base; p < (long)C_E * C_D / 2; p += stride) {
        const float* s = mem + 6 * p;
        float2 a = *(const float2*)s, b = *(const float2*)(s + 2), c = *(const float2*)(s + 4);
        bsplit2(a.x, b.y, &g_Mb_h[0][0][0], &g_Mb_l[0][0][0], 2 * p);
        bsplit2(a.y, c.x, &g_Mb_h[1][0][0], &g_Mb_l[1][0][0], 2 * p);
        bsplit2(b.x, c.y, &g_Mb_h[2][0][0], &g_Mb_l[2][0][0], 2 * p);
    }
}

// ---------------- early weight splits (needed for tv/msg) ----------------
__global__ void k_split_early(const float* __restrict__ Wsrc, const float* __restrict__ Wdst)
{
    const long SQ = (long)C_D * C_D;
    long stride = (long)gridDim.x * blockDim.x;
    for (long i = (long)blockIdx.x * blockDim.x + threadIdx.x; i < 2 * SQ; i += stride) {
        if (i < SQ) bsplit(Wsrc[i], g_Wsrc_h, g_Wsrc_l, i);
        else        bsplit(Wdst[i - SQ], g_Wdst_h, g_Wdst_l, i - SQ);
    }
}

// ---------------- late weight splits (needed after pointwise) ----------------
__global__ void k_split_late(
    const float* __restrict__ Wv,   const float* __restrict__ Wp,
    const float* __restrict__ Wf1,  const float* __restrict__ Wfd,
    const float* __restrict__ Wf2,  const float* __restrict__ Wa)
{
    const long SQ = (long)C_D * C_D;
    const long O2 = 2 * SQ;
    const long O3 = O2 + (long)C_FF * C_D;
    const long O4 = O3 + (long)C_FF * C_FF;
    const long O5 = O4 + (long)C_D * C_FF;
    const long O6 = O5 + (long)C_MA * C_D;
    long stride = (long)gridDim.x * blockDim.x;
    for (long i = (long)blockIdx.x * blockDim.x + threadIdx.x; i < O6; i += stride) {
        if (i < SQ)          bsplit(Wv[i], g_Wv_h, g_Wv_l, i);
        else if (i < O2)     bsplit(Wp[i - SQ], g_Wp_h, g_Wp_l, i - SQ);
        else if (i < O3)     g_Wf1_f[i - O2] = __float2half_rn(Wf1[i - O2]);
        else if (i < O4)     g_Wfd_f[i - O3] = __float2half_rn(Wfd[i - O3]);
        else if (i < O5)     g_Wf2_f[i - O4] = __float2half_rn(Wf2[i - O4]);
        else {
            long k = i - O5;
            long r = k >> 6, c = k & 63;
            bsplit(Wa[k], g_Wa_h, g_Wa_l, c * C_D + r);
        }
    }
}

// ---------------- fused edge MLP ----------------
__global__ void __launch_bounds__(256) k_mlp(
    const float* __restrict__ es, const float* __restrict__ w1, const float* __restrict__ b1,
    const float* __restrict__ w2, const float* __restrict__ b2,
    const float* __restrict__ w3, const float* __restrict__ b3)
{
    __shared__ float s_es[64][65];
    __shared__ float s_w1[64][32];
    __shared__ float s_w2[32][32];
    __shared__ float s_h1[64][33];
    __shared__ float s_h2[64][33];
    const int t = threadIdx.x;
    const long e0 = (long)blockIdx.x * 64;

    for (int i = t; i < 64 * 32; i += 256) s_w1[i >> 5][i & 31] = w1[i];
    for (int i = t; i < 32 * 32; i += 256) s_w2[i >> 5][i & 31] = w2[i];
    for (int i = t; i < 64 * 64; i += 256) s_es[i >> 6][i & 63] = es[e0 * 64 + i];
    __syncthreads();

    for (int i = t; i < 64 * 32; i += 256) {
        int e = i >> 5, j = i & 31;
        float acc = b1[j];
#pragma unroll 8
        for (int c = 0; c < 64; c++) acc = fmaf(s_es[e][c], s_w1[c][j], acc);
        s_h1[e][j] = acc / (1.f + expf(-acc));
    }
    __syncthreads();
    for (int i = t; i < 64 * 32; i += 256) {
        int e = i >> 5, j = i & 31;
        float acc = b2[j];
#pragma unroll 8
        for (int c = 0; c < 32; c++) acc = fmaf(s_h1[e][c], s_w2[c][j], acc);
        s_h2[e][j] = acc / (1.f + expf(-acc));
    }
    __syncthreads();
    for (int i = t; i < 64 * 1536; i += 256) {
        int e = i / 1536, o = i - e * 1536;
        float acc = b3[o];
#pragma unroll 8
        for (int c = 0; c < 32; c++) acc = fmaf(s_h2[e][c], w3[c * 1536 + o], acc);
        g_w[e0 + e][o] = acc;
    }
}

// ---------------- pointwise equivariant products (adds tv[e/K] to msg) ----------------
__global__ void k_pointwise(const float* __restrict__ esh)
{
    const long P = (long)C_N * C_D;
    long stride = (long)gridDim.x * blockDim.x;
    for (long p = (long)blockIdx.x * blockDim.x + threadIdx.x; p < (long)C_E * C_D / 2; p += stride) {
        int  c = (int)(p & 255) * 2;
        long e = p >> 8;
        long n = e >> 4;
        float s  = esh[e * 4 + 0];
        float v0 = esh[e * 4 + 1], v1 = esh[e * 4 + 2], v2 = esh[e * 4 + 3];
        float2 t0 = *(const float2*)&g_TV[0][n][c];
        float2 t1 = *(const float2*)&g_TV[1][n][c];
        float2 t2 = *(const float2*)&g_TV[2][n][c];
        float2 m0 = *(const float2*)&g_MSG[0][e][c];
        float2 m1 = *(const float2*)&g_MSG[1][e][c];
        float2 m2 = *(const float2*)&g_MSG[2][e][c];
        m0.x += t0.x; m0.y += t0.y;
        m1.x += t1.x; m1.y += t1.y;
        m2.x += t2.x; m2.y += t2.y;
        float2 w0 = *(const float2*)&g_w[e][c];
        float2 w1 = *(const float2*)&g_w[e][512 + c];
        float2 w2 = *(const float2*)&g_w[e][1024 + c];
        float p0 = w0.x * (m0.x * v0 + m1.x * v1 + m2.x * v2) * 0.5773502691896258f;
        float p1 = w0.y * (m0.y * v0 + m1.y * v1 + m2.y * v2) * 0.5773502691896258f;
        bsplit2(p0, p1, &g_pscb_h[0][0], &g_pscb_l[0][0], e * C_D + c);
        float k2x = w2.x * 0.7071067811865475f, k2y = w2.y * 0.7071067811865475f;
        float wsx = w1.x * s, wsy = w1.y * s;
        *(float2*)&g_PV[0][e][c] = make_float2(wsx * m0.x + k2x * (m1.x * v2 - m2.x * v1),
                                               wsy * m0.y + k2y * (m1.y * v2 - m2.y * v1));
        *(float2*)&g_PV[1][e][c] = make_float2(wsx * m1.x + k2x * (m2.x * v0 - m0.x * v2),
                                               wsy * m1.y + k2y * (m2.y * v0 - m0.y * v2));
        *(float2*)&g_PV[2][e][c] = make_float2(wsx * m2.x + k2x * (m0.x * v1 - m1.x * v0),
                                               wsy * m2.y + k2y * (m0.y * v1 - m1.y * v0));
    }
}

// ---------------- fused alpha post + softmax (reduces 2 split-K partials) ----------------
__global__ void __launch_bounds__(512) k_alpha(const float* __restrict__ gg, const float* __restrict__ bb,
                                               const float* __restrict__ adot)
{
    int n = blockIdx.x;
    int t = threadIdx.x, wid = t >> 5, lane = t & 31;
    __shared__ float s_l[16][8];
    int e = n * 16 + wid;
    float v0 = g_araw[0][e][lane * 2]     + g_araw[1][e][lane * 2];
    float v1 = g_araw[0][e][lane * 2 + 1] + g_araw[1][e][lane * 2 + 1];
    float s = v0 + v1, s2 = v0 * v0 + v1 * v1;
#pragma unroll
    for (int o = 16; o > 0; o >>= 1) {
        s  += __shfl_xor_sync(0xffffffffu, s, o);
        s2 += __shfl_xor_sync(0xffffffffu, s2, o);
    }
    float mu  = s * (1.f / 64.f);
    float var = s2 * (1.f / 64.f) - mu * mu;
    float inv = rsqrtf(var + C_EPS);
    float a0 = (v0 - mu) * inv * gg[lane * 2]     + bb[lane * 2];
    float a1 = (v1 - mu) * inv * gg[lane * 2 + 1] + bb[lane * 2 + 1];
    a0 = 0.6f * a0 + 0.4f * a0 * tanhf(0.5f * a0);
    a1 = 0.6f * a1 + 0.4f * a1 * tanhf(0.5f * a1);
    int h = lane >> 2;
    int m = (lane & 3) * 2;
    float p = a0 * adot[h * 8 + m] + a1 * adot[h * 8 + m + 1];
    p += __shfl_xor_sync(0xffffffffu, p, 1);
    p += __shfl_xor_sync(0xffffffffu, p, 2);
    if ((lane & 3) == 0) s_l[wid][h] = p;
    __syncthreads();
    if (t < 8) {
        float mx = -1e30f;
#pragma unroll
        for (int k = 0; k < 16; k++) mx = fmaxf(mx, s_l[k][t]);
        float sum = 0.f; float ex[16];
#pragma unroll
        for (int k = 0; k < 16; k++) { ex[k] = expf(s_l[k][t] - mx); sum += ex[k]; }
        float is = 1.f / sum;
#pragma unroll
        for (int k = 0; k < 16; k++) g_att[n * 16 + k][t] = ex[k] * is;
    }
}

// ---------------- z = sum_k att * pv ----------------
__global__ void __launch_bounds__(256) k_z()
{
    int n = blockIdx.x, x = blockIdx.y;
    __shared__ float s_a[16][8];
    if (threadIdx.x < 128)
        s_a[threadIdx.x >> 3][threadIdx.x & 7] = g_att[n * 16 + (threadIdx.x >> 3)][threadIdx.x & 7];
    __syncthreads();
    int c = threadIdx.x * 2;
    float2 acc[8];
#pragma unroll
    for (int h = 0; h < 8; h++) acc[h] = make_float2(0.f, 0.f);
#pragma unroll
    for (int k = 0; k < 16; k++) {
        float2 pv = *(const float2*)&g_PV[x][n * 16 + k][c];
#pragma unroll
        for (int h = 0; h < 8; h++) {
            acc[h].x = fmaf(s_a[k][h], pv.x, acc[h].x);
            acc[h].y = fmaf(s_a[k][h], pv.y, acc[h].y);
        }
    }
#pragma unroll
    for (int h = 0; h < 8; h++) {
        long idx = (((long)x * C_N + n) * C_H + h) * C_D + c;
        bsplit2(acc[h].x, acc[h].y, &g_Zb_h[0][0][0][0], &g_Zb_l[0][0][0][0], idx);
    }
}

// ---------------- vn_ln with fused split-K partial reduction ----------------
__global__ void __launch_bounds__(256) k_vnln(const float* __restrict__ Xin,
                                              const float* __restrict__ Parts, int nparts, long pstride,
                                              float* __restrict__ Xout,
                                              fp16* __restrict__ fH, fp16* __restrict__ fL,
                                              const float* __restrict__ gg, const float* __restrict__ bb,
                                              int inter)
{
    int n = blockIdx.x, t = threadIdx.x;
    const long P = (long)C_N * C_D;
    __shared__ float rs[8], rs2[8];
    __shared__ float smu, sinv;
    float xv[2][3], nc[2];
    float s = 0.f, s2 = 0.f;
#pragma unroll
    for (int i = 0; i < 2; i++) {
        int c = t * 2 + i;
#pragma unroll
        for (int xx = 0; xx < 3; xx++) {
            long idx = xx * P + (long)n * C_D + c;
            float v = Xin[idx];
            for (int pp = 0; pp < nparts; pp++) v += Parts[pp * pstride + idx];
            xv[i][xx] = v;
        }
        float v = sqrtf(xv[i][0] * xv[i][0] + xv[i][1] * xv[i][1] + xv[i][2] * xv[i][2] + C_EPS);
        nc[i] = v; s += v; s2 = fmaf(v, v, s2);
    }
#pragma unroll
    for (int o = 16; o > 0; o >>= 1) {
        s  += __shfl_xor_sync(0xffffffffu, s, o);
        s2 += __shfl_xor_sync(0xffffffffu, s2, o);
    }
    if ((t & 31) == 0) { rs[t >> 5] = s; rs2[t >> 5] = s2; }
    __syncthreads();
    if (t == 0) {
        float S = 0.f, S2 = 0.f;
        for (int i = 0; i < 8; i++) { S += rs[i]; S2 += rs2[i]; }
        float mu  = S * (1.f / 512.f);
        float var = S2 * (1.f / 512.f) - mu * mu;
        smu = mu; sinv = rsqrtf(var + C_EPS);
    }
    __syncthreads();
    float sc[2];
#pragma unroll
    for (int i = 0; i < 2; i++) {
        int c = t * 2 + i;
        float ln = (nc[i] - smu) * sinv * gg[c] + bb[c];
        sc[i] = ln / nc[i];
    }
    if (inter) {
#pragma unroll
        for (int i = 0; i < 2; i++) {
            int c = t * 2 + i;
#pragma unroll
            for (int xx = 0; xx < 3; xx++) Xout[(long)n * 1536 + c * 3 + xx] = xv[i][xx] * sc[i];
        }
    } else {
#pragma unroll
        for (int xx = 0; xx < 3; xx++) {
            long idx = xx * P + (long)n * C_D + t * 2;
            float o0 = xv[0][xx] * sc[0], o1 = xv[1][xx] * sc[1];
            *(float2*)(Xout + idx) = make_float2(o0, o1);
            if (fH) hsplit2(o0, o1, fH, fL, idx);
        }
    }
}

// ---------------- FF gating with fused DV partial reduction (fp16 pair out) ----------------
__global__ void k_gate()
{
    const long P = (long)C_N * C_FF;
    const float* Y  = &g_Y[0][0][0];
    const float* D0 = &g_DVP[0][0][0][0];
    const float* D1 = &g_DVP[1][0][0][0];
    long stride = (long)gridDim.x * blockDim.x;
    for (long p = (long)blockIdx.x * blockDim.x + threadIdx.x; p < P / 2; p += stride) {
        long i = 2 * p;
        float2 y0 = *(const float2*)(Y + i), y1 = *(const float2*)(Y + P + i), y2 = *(const float2*)(Y + 2 * P + i);
        float2 a0 = *(const float2*)(D0 + i), a1 = *(const float2*)(D0 + P + i), a2 = *(const float2*)(D0 + 2 * P + i);
        float2 b0 = *(const float2*)(D1 + i), b1 = *(const float2*)(D1 + P + i), b2 = *(const float2*)(D1 + 2 * P + i);
        float2 d0 = make_float2(a0.x + b0.x, a0.y + b0.y);
        float2 d1 = make_float2(a1.x + b1.x, a1.y + b1.y);
        float2 d2 = make_float2(a2.x + b2.x, a2.y + b2.y);
        float dotx = y0.x * d0.x + y1.x * d1.x + y2.x * d2.x;
        float doty = y0.y * d0.y + y1.y * d1.y + y2.y * d2.y;
        float fx = (dotx >= 0.f) ? 0.f : 0.8f * dotx / (d0.x * d0.x + d1.x * d1.x + d2.x * d2.x + C_EPS);
        float fy = (doty >= 0.f) ? 0.f : 0.8f * doty / (d0.y * d0.y + d1.y * d1.y + d2.y * d2.y + C_EPS);
        hsplit2(y0.x - fx * d0.x, y0.y - fy * d0.y, &g_Y2f_h[0][0][0], &g_Y2f_l[0][0][0], i);
        hsplit2(y1.x - fx * d1.x, y1.y - fy * d1.y, &g_Y2f_h[0][0][0], &g_Y2f_l[0][0][0], P + i);
        hsplit2(y2.x - fx * d2.x, y2.y - fy * d2.y, &g_Y2f_h[0][0][0], &g_Y2f_l[0][0][0], 2 * P + i);
    }
}

// ---------------- host launch ----------------
extern "C" void kernel_launch(void* const* d_in, const int* in_sizes, int n_in,
                              void* d_out, int out_size)
{
    const float* tgt    = (const float*)d_in[0];
    const float* mem    = (const float*)d_in[1];
    const float* esh    = (const float*)d_in[2];
    const float* escal  = (const float*)d_in[3];
    const float* W_src  = (const float*)d_in[4];
    const float* W_dst  = (const float*)d_in[5];
    const float* fc_w1  = (const float*)d_in[6];
    const float* fc_b1  = (const float*)d_in[7];
    const float* fc_w2  = (const float*)d_in[8];
    const float* fc_b2  = (const float*)d_in[9];
    const float* fc_w3  = (const float*)d_in[10];
    const float* fc_b3  = (const float*)d_in[11];
    const float* W_alpha= (const float*)d_in[12];
    const float* ln_a_g = (const float*)d_in[13];
    const float* ln_a_b = (const float*)d_in[14];
    const float* adot   = (const float*)d_in[15];
    const float* W_value= (const float*)d_in[16];
    const float* W_proj = (const float*)d_in[17];
    const float* n1_g   = (const float*)d_in[18];
    const float* n1_b   = (const float*)d_in[19];
    const float* n2_g   = (const float*)d_in[20];
    const float* n2_b   = (const float*)d_in[21];
    const float* W_ff1  = (const float*)d_in[22];
    const float* W_ffd  = (const float*)d_in[23];
    const float* W_ff2  = (const float*)d_in[24];

#define SYM(p, s) cudaGetSymbolAddress((void**)&p, s)
    float *pTV, *pMSG, *paraw, *pX1, *pY, *pPRJ, *pFF2, *pDVP;
    SYM(pTV, g_TV); SYM(pMSG, g_MSG); SYM(paraw, g_araw);
    SYM(pX1, g_X1); SYM(pY, g_Y);
    SYM(pPRJ, g_PRJP); SYM(pFF2, g_FF2P); SYM(pDVP, g_DVP);
    bf16 *pTbh, *pTbl, *pMbh, *pMbl, *ppsh, *ppsl, *pZh, *pZl, *pOh, *pOl;
    SYM(pTbh, g_Tb_h); SYM(pTbl, g_Tb_l); SYM(pMbh, g_Mb_h); SYM(pMbl, g_Mb_l);
    SYM(ppsh, g_pscb_h); SYM(ppsl, g_pscb_l); SYM(pZh, g_Zb_h); SYM(pZl, g_Zb_l);
    SYM(pOh, g_OUTb_h); SYM(pOl, g_OUTb_l);
    fp16 *pX1fh, *pX1fl, *pYfh, *pYfl, *pY2fh, *pY2fl, *pWf1f, *pWfdf, *pWf2f;
    SYM(pX1fh, g_X1f_h); SYM(pX1fl, g_X1f_l); SYM(pYfh, g_Yf_h); SYM(pYfl, g_Yf_l);
    SYM(pY2fh, g_Y2f_h); SYM(pY2fl, g_Y2f_l);
    SYM(pWf1f, g_Wf1_f); SYM(pWfdf, g_Wfd_f); SYM(pWf2f, g_Wf2_f);
    bf16 *pWsh, *pWsl, *pWdh, *pWdl, *pWah, *pWal, *pWvh, *pWvl, *pWph, *pWpl;
    SYM(pWsh, g_Wsrc_h); SYM(pWsl, g_Wsrc_l); SYM(pWdh, g_Wdst_h); SYM(pWdl, g_Wdst_l);
    SYM(pWah, g_Wa_h); SYM(pWal, g_Wa_l); SYM(pWvh, g_Wv_h); SYM(pWvl, g_Wv_l);
    SYM(pWph, g_Wp_h); SYM(pWpl, g_Wp_l);
#undef SYM

    const long NP_D  = (long)C_N * C_D;
    const long EP_D  = (long)C_E * C_D;
    const long NP_FF = (long)C_N * C_FF;
    const long NHD   = (long)C_N * C_H * C_D;

    const int SM128 = 2 * (2 * 10240 + 2 * 128 * 80);   // 81920
    const int SM64  = 2 * (2 * 10240 + 2 * 64 * 80);    // 61440
    const int SMH   = 2 * (2 * 10240 + 128 * 80);       // 61440
    cudaFuncSetAttribute(gemm_bf<128>, cudaFuncAttributeMaxDynamicSharedMemorySize, SM128);
    cudaFuncSetAttribute(gemm_bf<64>,  cudaFuncAttributeMaxDynamicSharedMemorySize, SM64);
    cudaFuncSetAttribute(gemm_hf,      cudaFuncAttributeMaxDynamicSharedMemorySize, SMH);

    // one-time stream/event setup (no device memory involved)
    static cudaStream_t s1 = nullptr, s2 = nullptr;
    static cudaEvent_t evRoot = nullptr, evMlp = nullptr, evIn = nullptr;
    static cudaEvent_t evEarly = nullptr, evTV = nullptr, evLate = nullptr;
    if (!s1) {
        cudaStreamCreateWithFlags(&s1, cudaStreamNonBlocking);
        cudaStreamCreateWithFlags(&s2, cudaStreamNonBlocking);
        cudaEventCreateWithFlags(&evRoot,  cudaEventDisableTiming);
        cudaEventCreateWithFlags(&evMlp,   cudaEventDisableTiming);
        cudaEventCreateWithFlags(&evIn,    cudaEventDisableTiming);
        cudaEventCreateWithFlags(&evEarly, cudaEventDisableTiming);
        cudaEventCreateWithFlags(&evTV,    cudaEventDisableTiming);
        cudaEventCreateWithFlags(&evLate,  cudaEventDisableTiming);
    }

    // fork helper streams off the main (capture) stream
    cudaEventRecord(evRoot, 0);
    cudaStreamWaitEvent(s1, evRoot, 0);
    cudaStreamWaitEvent(s2, evRoot, 0);

    // s1: edge MLP (needed by pointwise), then late weight splits (needed from alpha on)
    k_mlp<<<C_E / 64, 256, 0, s1>>>(escal, fc_w1, fc_b1, fc_w2, fc_b2, fc_w3, fc_b3);
    cudaEventRecord(evMlp, s1);
    k_split_late<<<8192, 256, 0, s1>>>(W_value, W_proj, W_ff1, W_ffd, W_ff2, W_alpha);
    cudaEventRecord(evLate, s1);

    // s2: input transpose + split, then tv GEMM (needs Wdst from main's early split)
    k_split_in<<<4096, 256, 0, s2>>>(tgt, mem);
    cudaEventRecord(evIn, s2);

    // main: early weight splits (Wsrc, Wdst)
    k_split_early<<<2048, 256>>>(W_src, W_dst);
    cudaEventRecord(evEarly, 0);

    // s2: tv = W_dst @ tgt (concurrent with msg on main)
    cudaStreamWaitEvent(s2, evEarly, 0);
    gemm_bf<128><<<dim3(4, 8, 3), 128, SM128, s2>>>(pTbh, pTbl, pWdh, pWdl, pTV, nullptr, nullptr, nullptr,
        C_D, C_D, C_D, C_D, NP_D, 0, 0, 0, NP_D, 0, 1, 1, 0, 0, 1, 3, 0);
    cudaEventRecord(evTV, s2);

    // main: msg = W_src @ memory (tv added later in pointwise)
    cudaStreamWaitEvent(0, evIn, 0);
    gemm_bf<128><<<dim3(4, 128, 3), 128, SM128>>>(pMbh, pMbl, pWsh, pWsl, pMSG, nullptr, nullptr, nullptr,
        C_D, C_D, C_D, C_D, EP_D, 0, 0, 0, EP_D, 0, 1, 1, 0, 0, 1, 3, 0);

    // join mlp + tv before pointwise (reads g_w, g_TV, g_MSG)
    cudaStreamWaitEvent(0, evMlp, 0);
    cudaStreamWaitEvent(0, evTV, 0);

    // 5) p_sc / pv (adds tv)
    k_pointwise<<<2048, 256>>>(esh);

    // join late weight splits before alpha GEMM (needs Wa; Wv/Wp/FF weights follow)
    cudaStreamWaitEvent(0, evLate, 0);

    // 6) a_raw = p_sc @ W_alpha (split-K=2 -> reduced in k_alpha)
    gemm_bf<64><<<dim3(1, 128, 2), 128, SM64>>>(ppsh, ppsl, pWah, pWal, paraw, nullptr, nullptr, nullptr,
        C_D, C_D, C_MA, C_D, 0, 0, 0, 0, 0, 0, 1, 1, 0, 0, 2, 1, (long)C_E * C_MA);

    // 7) fused LN + lrelu + head dot + softmax
    k_alpha<<<C_N, 512>>>(ln_a_g, ln_a_b, adot);

    // 8) z = sum_k att * pv
    k_z<<<dim3(C_N, 3), 256>>>();

    // 9) out = W_value @ z (per head, bf16 out), then proj (split-K=2)
    gemm_bf<64><<<dim3(1, 8, 24), 128, SM64>>>(pZh, pZl, pWvh, pWvl, nullptr, nullptr, pOh, pOl,
        C_H * C_D, C_D, C_D, C_D, NHD, C_D, 0, 64 * C_D, NP_D, 64, C_H, 1, 0, 0, 1, 24, 0);
    gemm_bf<128><<<dim3(4, 8, 6), 128, SM128>>>(pOh, pOl, pWph, pWpl, pPRJ, nullptr, nullptr, nullptr,
        C_D, C_D, C_D, C_D, NP_D, 0, 0, 0, NP_D, 0, 1, 1, 0, 0, 2, 3, 3 * NP_D);

    // 10) vn_ln #1 (tv + proj partials; fp16 pairs for ff1)
    k_vnln<<<C_N, 256>>>(pTV, pPRJ, 2, 3 * NP_D, pX1, pX1fh, pX1fl, n1_g, n1_b, 0);

    // 11) FF block: ff1 (fp16 2-pass), ffd (fp16 2-pass, split-K=2), ff2 (fp16 2-pass, split-K=4)
    gemm_hf<<<dim3(16, 8, 3), 128, SMH>>>(pX1fh, pX1fl, pWf1f, pY, pYfh, pYfl,
        C_D, C_D, C_FF, C_D, NP_D, 0, NP_FF, 1, 3, 0);
    gemm_hf<<<dim3(16, 8, 6), 128, SMH>>>(pYfh, pYfl, pWfdf, pDVP, nullptr, nullptr,
        C_FF, C_FF, C_FF, C_FF, NP_FF, 0, NP_FF, 2, 3, 3 * NP_FF);
    k_gate<<<2048, 256>>>();
    gemm_hf<<<dim3(4, 8, 12), 128, SMH>>>(pY2fh, pY2fl, pWf2f, pFF2, nullptr, nullptr,
        C_FF, C_FF, C_D, C_FF, NP_FF, 0, NP_D, 4, 3, 3 * NP_D);

    // 12) vn_ln #2 -> interleaved output
    k_vnln<<<C_N, 256>>>(pX1, pFF2, 4, 3 * NP_D, (float*)d_out, nullptr, nullptr, n2_g, n2_b, 1);
}